// round 3
// baseline (speedup 1.0000x reference)
#include <cuda_runtime.h>

#define B_ 4
#define C_ 64
#define H_ 56
#define W_ 56
#define HW_ (H_*W_)

// Scratch (device globals; no allocation allowed)
__device__ __align__(16) float g_xT  [B_*HW_*C_];   // x transposed to NHWC
__device__ __align__(16) float g_off1[B_*HW_*50];   // offsets conv1, NHWC
__device__ __align__(16) float g_attn1[B_*HW_*C_];  // deform-dw 1 output, NHWC
__device__ __align__(16) float g_off2[B_*HW_*98];   // offsets conv2, NHWC
__device__ __align__(16) float g_attn2[B_*HW_*C_];  // deform-dw 2 output, NHWC

// ---------------------------------------------------------------------------
// NCHW -> NHWC transpose of x
// ---------------------------------------------------------------------------
__global__ void __launch_bounds__(224) transpose_kernel(
    const float* __restrict__ x, float* __restrict__ xT)
{
    int h = blockIdx.x, b = blockIdx.y;
    __shared__ float s[C_*W_];
    int t = threadIdx.x;
    for (int i = t; i < C_*W_; i += 224) {
        int c = i / W_, w = i - c*W_;
        s[i] = x[((b*C_ + c)*H_ + h)*W_ + w];
    }
    __syncthreads();
    float* orow = xT + (size_t)(b*H_ + h)*W_*C_;
    for (int j = t; j < C_*W_; j += 224) {
        int w = j >> 6, c = j & 63;
        orow[j] = s[c*W_ + w];
    }
}

// ---------------------------------------------------------------------------
// Offset convolution: full conv, NHWC in [B,H,W,64] -> NHWC out [B,H,W,CO]
// Tiled: block = (spatial 28x28 tile, 16 output channels, batch)
// 196 threads, each owns 4 pixels x 16 co accumulators.
// ---------------------------------------------------------------------------
template<int K, int DIL, int PAD, int CO>
__global__ void __launch_bounds__(196) conv_off_kernel(
    const float* __restrict__ in,    // [B,H,W,64]
    const float* __restrict__ wgt,   // [CO,64,K,K] (OIHW)
    const float* __restrict__ bias,  // [CO]
    float* __restrict__ out)         // [B,H,W,CO]
{
    constexpr int TILE = 28;
    constexpr int TWH  = TILE + 2*PAD;   // halo'd tile edge ((K-1)*DIL == 2*PAD here)
    constexpr int COB  = 16;
    __shared__ float4 s_in[TWH*TWH];     // 4 input channels per float4
    __shared__ float4 s_w [K*K*COB];     // per tap: 16 co x 4 ci weights

    const int t       = threadIdx.x;
    const int tIdx    = blockIdx.x;            // 0..3 (2x2 tiles)
    const int co_base = blockIdx.y * COB;
    const int b       = blockIdx.z;
    const int oy0 = (tIdx >> 1) * TILE, ox0 = (tIdx & 1) * TILE;
    const int gy0 = oy0 - PAD,          gx0 = ox0 - PAD;
    const int lx  = t % TILE;
    const int ly0 = t / TILE;                  // 0..6; pixels at rows ly0 + 7*i

    float acc[4][COB];
    #pragma unroll
    for (int i = 0; i < 4; ++i)
        #pragma unroll
        for (int co = 0; co < COB; ++co)
            acc[i][co] = (co_base + co < CO) ? bias[co_base + co] : 0.f;

    for (int cc = 0; cc < 16; ++cc) {          // 64 input channels / 4
        const int ci0 = cc * 4;
        __syncthreads();
        // stage haloed input tile (float4 = 4 ci)
        for (int i = t; i < TWH*TWH; i += 196) {
            int sy = i / TWH, sx = i - sy*TWH;
            int gy = gy0 + sy, gx = gx0 + sx;
            float4 v = make_float4(0.f, 0.f, 0.f, 0.f);
            if ((unsigned)gy < (unsigned)H_ && (unsigned)gx < (unsigned)W_)
                v = *(const float4*)(in + ((size_t)(b*H_ + gy)*W_ + gx)*64 + ci0);
            s_in[i] = v;
        }
        // stage weights for this (ci chunk, co block)
        for (int i = t; i < K*K*COB; i += 196) {
            int tap = i / COB, co = i - tap*COB;
            int cog = co_base + co;
            float4 wv = make_float4(0.f, 0.f, 0.f, 0.f);
            if (cog < CO) {
                const float* wp = wgt + (size_t)(cog*64 + ci0)*(K*K) + tap;
                wv.x = wp[0]; wv.y = wp[K*K]; wv.z = wp[2*K*K]; wv.w = wp[3*K*K];
            }
            s_w[i] = wv;
        }
        __syncthreads();

        for (int ky = 0; ky < K; ++ky) {
            for (int kx = 0; kx < K; ++kx) {
                int base = (ly0 + ky*DIL)*TWH + lx + kx*DIL;
                float4 v0 = s_in[base];
                float4 v1 = s_in[base +  7*TWH];
                float4 v2 = s_in[base + 14*TWH];
                float4 v3 = s_in[base + 21*TWH];
                const float4* wrow = s_w + (ky*K + kx)*COB;
                #pragma unroll
                for (int co = 0; co < COB; ++co) {
                    float4 wv = wrow[co];
                    acc[0][co] += v0.x*wv.x + v0.y*wv.y + v0.z*wv.z + v0.w*wv.w;
                    acc[1][co] += v1.x*wv.x + v1.y*wv.y + v1.z*wv.z + v1.w*wv.w;
                    acc[2][co] += v2.x*wv.x + v2.y*wv.y + v2.z*wv.z + v2.w*wv.w;
                    acc[3][co] += v3.x*wv.x + v3.y*wv.y + v3.z*wv.z + v3.w*wv.w;
                }
            }
        }
    }

    #pragma unroll
    for (int i = 0; i < 4; ++i) {
        int oy = oy0 + ly0 + 7*i, ox = ox0 + lx;
        float* op = out + ((size_t)(b*H_ + oy)*W_ + ox)*CO + co_base;
        #pragma unroll
        for (int co = 0; co < COB; ++co)
            if (co_base + co < CO) op[co] = acc[i][co];
    }
}

// ---------------------------------------------------------------------------
// Deformable depthwise sampling:
// out[b,h,w,c] = sum_kk dw[c,kk] * bilinear(img[b,:,:,c], h + ky*DIL-PAD + dy,
//                                                         w + kx*DIL-PAD + dx)
// block = one (b, h) row; 224 threads = 56 w x 4 channel-groups of 16.
// ---------------------------------------------------------------------------
template<int K, int DIL, int PAD>
__global__ void __launch_bounds__(224) deform_sample_kernel(
    const float* __restrict__ img,   // [B,H,W,64]
    const float* __restrict__ off,   // [B,H,W,2*K*K]  (chan = kk*2 + {0:dy,1:dx})
    const float* __restrict__ dw,    // [64,1,K,K]
    float* __restrict__ outp)        // [B,H,W,64]
{
    constexpr int KK = K*K;
    __shared__ float s_off[W_*2*KK];
    __shared__ float s_dw [KK*64];

    const int t = threadIdx.x;
    const int h = blockIdx.x, b = blockIdx.y;

    const float* orow = off + (size_t)(b*H_ + h)*W_*2*KK;
    for (int i = t; i < W_*2*KK; i += 224) s_off[i] = orow[i];
    for (int i = t; i < KK*64;   i += 224) {
        int kk = i >> 6, c = i & 63;
        s_dw[i] = dw[c*KK + kk];               // transpose to [kk][c]
    }
    __syncthreads();

    const int w  = t % W_;
    const int cg = t / W_;                     // 0..3
    const int c0 = cg * 16;
    const float4* s_dw4 = (const float4*)s_dw;

    float4 a[4];
    #pragma unroll
    for (int q = 0; q < 4; ++q) a[q] = make_float4(0.f, 0.f, 0.f, 0.f);

    for (int kk = 0; kk < KK; ++kk) {
        int ky = kk / K, kx = kk - ky*K;
        float dy = s_off[w*2*KK + 2*kk];
        float dx = s_off[w*2*KK + 2*kk + 1];
        float py = (float)(h + ky*DIL - PAD) + dy;
        float px = (float)(w + kx*DIL - PAD) + dx;
        float y0f = floorf(py), x0f = floorf(px);
        float wy = py - y0f,    wx = px - x0f;
        int y0 = (int)y0f, x0i = (int)x0f;
        int y1 = y0 + 1,   x1  = x0i + 1;
        float vy0 = (y0  >= 0 && y0  < H_) ? 1.f : 0.f;
        float vy1 = (y1  >= 0 && y1  < H_) ? 1.f : 0.f;
        float vx0 = (x0i >= 0 && x0i < W_) ? 1.f : 0.f;
        float vx1 = (x1  >= 0 && x1  < W_) ? 1.f : 0.f;
        int y0c = min(max(y0, 0), H_-1), y1c = min(max(y1, 0), H_-1);
        int x0c = min(max(x0i,0), W_-1), x1c = min(max(x1, 0), W_-1);
        float w00 = (1.f-wy)*(1.f-wx)*vy0*vx0;
        float w01 = (1.f-wy)*wx      *vy0*vx1;
        float w10 = wy      *(1.f-wx)*vy1*vx0;
        float w11 = wy      *wx      *vy1*vx1;

        const float4* p00 = (const float4*)(img + ((size_t)(b*H_+y0c)*W_+x0c)*64 + c0);
        const float4* p01 = (const float4*)(img + ((size_t)(b*H_+y0c)*W_+x1c)*64 + c0);
        const float4* p10 = (const float4*)(img + ((size_t)(b*H_+y1c)*W_+x0c)*64 + c0);
        const float4* p11 = (const float4*)(img + ((size_t)(b*H_+y1c)*W_+x1c)*64 + c0);

        #pragma unroll
        for (int q = 0; q < 4; ++q) {
            float4 g00 = p00[q], g01 = p01[q], g10 = p10[q], g11 = p11[q];
            float4 dv  = s_dw4[kk*16 + cg*4 + q];
            float gx_ = g00.x*w00 + g01.x*w01 + g10.x*w10 + g11.x*w11;
            float gy_ = g00.y*w00 + g01.y*w01 + g10.y*w10 + g11.y*w11;
            float gz_ = g00.z*w00 + g01.z*w01 + g10.z*w10 + g11.z*w11;
            float gw_ = g00.w*w00 + g01.w*w01 + g10.w*w10 + g11.w*w11;
            a[q].x += gx_*dv.x; a[q].y += gy_*dv.y;
            a[q].z += gz_*dv.z; a[q].w += gw_*dv.w;
        }
    }

    float* op = outp + ((size_t)(b*H_ + h)*W_ + w)*64 + c0;
    #pragma unroll
    for (int q = 0; q < 4; ++q) ((float4*)op)[q] = a[q];
}

// ---------------------------------------------------------------------------
// Pointwise 1x1 conv + bias, then out = x * attn. Output in NCHW.
// ---------------------------------------------------------------------------
__global__ void __launch_bounds__(224) pw_mul_kernel(
    const float* __restrict__ attn,  // [B,H,W,64]
    const float* __restrict__ pw,    // [64,64]
    const float* __restrict__ pb,    // [64]
    const float* __restrict__ x,     // [B,64,H,W]
    float* __restrict__ out)         // [B,64,H,W]
{
    __shared__ float s_a[W_*64];
    __shared__ float s_w[64*64];
    const int t = threadIdx.x;
    const int h = blockIdx.x, b = blockIdx.y;

    const float* arow = attn + (size_t)(b*H_ + h)*W_*64;
    for (int i = t; i < W_*64; i += 224) s_a[i] = arow[i];
    for (int i = t; i < 64*64; i += 224) s_w[i] = pw[i];
    __syncthreads();

    const int w = t % W_, cg = t / W_;
    float acc[16] = {};
    const float4* sa4 = (const float4*)s_a;
    const float4* sw4 = (const float4*)s_w;
    for (int ciq = 0; ciq < 16; ++ciq) {
        float4 av = sa4[w*16 + ciq];
        #pragma unroll
        for (int j = 0; j < 16; ++j) {
            float4 wv = sw4[(cg*16 + j)*16 + ciq];
            acc[j] += av.x*wv.x + av.y*wv.y + av.z*wv.z + av.w*wv.w;
        }
    }
    #pragma unroll
    for (int j = 0; j < 16; ++j) {
        int co = cg*16 + j;
        size_t idx = ((size_t)(b*64 + co)*H_ + h)*W_ + w;
        out[idx] = x[idx] * (acc[j] + pb[co]);
    }
}

// ---------------------------------------------------------------------------
extern "C" void kernel_launch(void* const* d_in, const int* in_sizes, int n_in,
                              void* d_out, int out_size)
{
    const float* x   = (const float*)d_in[0];
    const float* ow1 = (const float*)d_in[1];
    const float* ob1 = (const float*)d_in[2];
    const float* dw1 = (const float*)d_in[3];
    const float* ow2 = (const float*)d_in[4];
    const float* ob2 = (const float*)d_in[5];
    const float* dw2 = (const float*)d_in[6];
    const float* pww = (const float*)d_in[7];
    const float* pwb = (const float*)d_in[8];
    float* out = (float*)d_out;

    float *xT, *off1, *attn1, *off2, *attn2;
    cudaGetSymbolAddress((void**)&xT,    g_xT);
    cudaGetSymbolAddress((void**)&off1,  g_off1);
    cudaGetSymbolAddress((void**)&attn1, g_attn1);
    cudaGetSymbolAddress((void**)&off2,  g_off2);
    cudaGetSymbolAddress((void**)&attn2, g_attn2);

    transpose_kernel<<<dim3(H_, B_), 224>>>(x, xT);

    // stage 1: K=5, dil=1, pad=2, CO=50
    conv_off_kernel<5,1,2,50><<<dim3(4, 4, B_), 196>>>(xT, ow1, ob1, off1);
    deform_sample_kernel<5,1,2><<<dim3(H_, B_), 224>>>(xT, off1, dw1, attn1);

    // stage 2: K=7, dil=3, pad=9, CO=98
    conv_off_kernel<7,3,9,98><<<dim3(4, 7, B_), 196>>>(attn1, ow2, ob2, off2);
    deform_sample_kernel<7,3,9><<<dim3(H_, B_), 224>>>(attn1, off2, dw2, attn2);

    // pointwise + elementwise multiply
    pw_mul_kernel<<<dim3(H_, B_), 224>>>(attn2, pww, pwb, x, out);
}

// round 5
// speedup vs baseline: 1.4250x; 1.4250x over previous
#include <cuda_runtime.h>

#define B_ 4
#define C_ 64
#define H_ 56
#define W_ 56
#define HW_ (H_*W_)

// Scratch (device globals; no allocation allowed)
__device__ __align__(16) float g_xT   [B_*HW_*C_];    // x transposed to NHWC
__device__ __align__(16) float g_off1 [B_*HW_*50];    // offsets conv1, NHWC
__device__ __align__(16) float g_attn1[B_*HW_*C_];    // deform-dw 1 output, NHWC
__device__ __align__(16) float g_off2 [B_*HW_*98];    // offsets conv2, NHWC
__device__ __align__(16) float g_attn2[B_*HW_*C_];    // deform-dw 2 output, NHWC
// Pre-transposed weights
__device__ __align__(16) float g_w1T  [16*25*64*4];   // [cc][tap][co(64)][ci4]
__device__ __align__(16) float g_w2T  [16*49*112*4];  // [cc][tap][co(112)][ci4]
__device__ __align__(16) float g_dw1T [25*64];        // [kk][c]
__device__ __align__(16) float g_dw2T [49*64];        // [kk][c]

// ---------------------------------------------------------------------------
// Weight prep: OIHW -> [cc][tap][co][ci4] float4-friendly, + dw transpose
// ---------------------------------------------------------------------------
__global__ void __launch_bounds__(256) prep_kernel(
    const float* __restrict__ ow1, const float* __restrict__ ow2,
    const float* __restrict__ dw1, const float* __restrict__ dw2,
    float* __restrict__ w1T, float* __restrict__ w2T,
    float* __restrict__ dw1T, float* __restrict__ dw2T)
{
    const int N1 = 16*25*64*4;
    const int N2 = 16*49*112*4;
    const int N3 = 25*64;
    const int N4 = 49*64;
    int idx = blockIdx.x*256 + threadIdx.x;
    if (idx < N1) {
        int j = idx & 3; int r = idx >> 2;           // r = (cc*25+tap)*64+co
        int co = r % 64; int ct = r / 64;
        int tap = ct % 25; int cc = ct / 25;
        w1T[idx] = (co < 50) ? ow1[(size_t)(co*64 + cc*4 + j)*25 + tap] : 0.f;
    } else if (idx < N1 + N2) {
        int i = idx - N1;
        int j = i & 3; int r = i >> 2;               // r = (cc*49+tap)*112+co
        int co = r % 112; int ct = r / 112;
        int tap = ct % 49; int cc = ct / 49;
        w2T[i] = (co < 98) ? ow2[(size_t)(co*64 + cc*4 + j)*49 + tap] : 0.f;
    } else if (idx < N1 + N2 + N3) {
        int i = idx - N1 - N2;
        int kk = i >> 6, c = i & 63;
        dw1T[i] = dw1[c*25 + kk];
    } else if (idx < N1 + N2 + N3 + N4) {
        int i = idx - N1 - N2 - N3;
        int kk = i >> 6, c = i & 63;
        dw2T[i] = dw2[c*49 + kk];
    }
}

// ---------------------------------------------------------------------------
// NCHW -> NHWC transpose of x
// ---------------------------------------------------------------------------
__global__ void __launch_bounds__(224) transpose_kernel(
    const float* __restrict__ x, float* __restrict__ xT)
{
    int h = blockIdx.x, b = blockIdx.y;
    __shared__ float s[C_*W_];
    int t = threadIdx.x;
    for (int i = t; i < C_*W_; i += 224) {
        int c = i / W_, w = i - c*W_;
        s[i] = x[((b*C_ + c)*H_ + h)*W_ + w];
    }
    __syncthreads();
    float* orow = xT + (size_t)(b*H_ + h)*W_*C_;
    for (int j = t; j < C_*W_; j += 224) {
        int w = j >> 6, c = j & 63;
        orow[j] = s[c*W_ + w];
    }
}

// ---------------------------------------------------------------------------
// Offset convolution, NHWC in [B,H,W,64] -> NHWC out [B,H,W,CO]
// 14x14 spatial tile, 196 threads, each thread = 1 pixel x 16 output channels.
// grid = (16 tiles, ceil(CO/16), B)
// ---------------------------------------------------------------------------
template<int K, int DIL, int PAD, int CO, int COP>
__global__ void __launch_bounds__(196) conv_off_kernel(
    const float4* __restrict__ wT4,   // [cc][tap][COP] float4
    const float*  __restrict__ bias,  // [CO]
    const float*  __restrict__ in,    // [B,H,W,64]
    float*        __restrict__ out)   // [B,H,W,CO]
{
    constexpr int TILE = 14;
    constexpr int TWH  = TILE + 2*PAD;   // (K-1)*DIL == 2*PAD for both stages
    constexpr int KK   = K*K;
    __shared__ float4 s_in[TWH*TWH];
    __shared__ float4 s_w [KK*16];
    __shared__ float  s_bias[16];

    const int t       = threadIdx.x;
    const int tIdx    = blockIdx.x;          // 0..15 (4x4 tiles)
    const int co_base = blockIdx.y * 16;
    const int b       = blockIdx.z;
    const int oy0 = (tIdx >> 2) * TILE, ox0 = (tIdx & 3) * TILE;
    const int gy0 = oy0 - PAD,          gx0 = ox0 - PAD;
    const int ly  = t / TILE, lx = t - ly*TILE;

    if (t < 16) s_bias[t] = (co_base + t < CO) ? bias[co_base + t] : 0.f;
    __syncthreads();

    float acc[16];
    #pragma unroll
    for (int co = 0; co < 16; ++co) acc[co] = s_bias[co];

    const float4* in4 = (const float4*)in;

    for (int cc = 0; cc < 16; ++cc) {        // 64 input channels / 4
        __syncthreads();
        // stage haloed input tile (float4 = 4 ci), coalesced
        for (int i = t; i < TWH*TWH; i += 196) {
            int sy = i / TWH, sx = i - sy*TWH;
            int gy = gy0 + sy, gx = gx0 + sx;
            float4 v = make_float4(0.f, 0.f, 0.f, 0.f);
            if ((unsigned)gy < (unsigned)H_ && (unsigned)gx < (unsigned)W_)
                v = in4[((size_t)(b*H_ + gy)*W_ + gx)*16 + cc];
            s_in[i] = v;
        }
        // stage weights (pre-transposed, coalesced float4)
        for (int i = t; i < KK*16; i += 196) {
            int tap = i >> 4, co = i & 15;
            s_w[i] = wT4[(size_t)(cc*KK + tap)*COP + co_base + co];
        }
        __syncthreads();

        for (int ky = 0; ky < K; ++ky) {
            #pragma unroll
            for (int kx = 0; kx < K; ++kx) {
                float4 v = s_in[(ly + ky*DIL)*TWH + lx + kx*DIL];
                const float4* wr = &s_w[(ky*K + kx)*16];
                #pragma unroll
                for (int co = 0; co < 16; ++co) {
                    float4 wv = wr[co];
                    acc[co] += v.x*wv.x + v.y*wv.y + v.z*wv.z + v.w*wv.w;
                }
            }
        }
    }

    const int oy = oy0 + ly, ox = ox0 + lx;
    float* op = out + ((size_t)(b*H_ + oy)*W_ + ox)*CO + co_base;
    #pragma unroll
    for (int co = 0; co < 16; ++co)
        if (co_base + co < CO) op[co] = acc[co];
}

// ---------------------------------------------------------------------------
// Deformable depthwise sampling. 448 threads = 28 pixels x 16 channel-float4;
// warp = 2 pixels -> each corner warp-LDG touches only ~4 cache lines.
// grid = (2 half-rows, H, B)
// ---------------------------------------------------------------------------
template<int K, int DIL, int PAD>
__global__ void __launch_bounds__(448) deform_sample_kernel(
    const float* __restrict__ img,   // [B,H,W,64]
    const float* __restrict__ off,   // [B,H,W,2*K*K]
    const float* __restrict__ dwT,   // [kk][c] 64 floats per kk
    float* __restrict__ outp)        // [B,H,W,64]
{
    constexpr int KK = K*K;
    __shared__ float  s_off[28*2*KK];
    __shared__ float4 s_dw4[KK*16];

    const int t = threadIdx.x;
    const int half = blockIdx.x, h = blockIdx.y, b = blockIdx.z;
    const int w0 = half * 28;

    const float* obase = off + ((size_t)(b*H_ + h)*W_ + w0)*2*KK;
    for (int i = t; i < 28*2*KK; i += 448) s_off[i] = obase[i];
    const float4* dwT4 = (const float4*)dwT;
    for (int i = t; i < KK*16; i += 448) s_dw4[i] = dwT4[i];
    __syncthreads();

    const int c4 = t & 15;          // float4 channel group 0..15
    const int wl = t >> 4;          // pixel within half-row 0..27
    const int w  = w0 + wl;
    const float4* img4 = (const float4*)img;
    const size_t brow = (size_t)b*H_;

    float4 a = make_float4(0.f, 0.f, 0.f, 0.f);

    for (int ky = 0; ky < K; ++ky) {
        #pragma unroll
        for (int kx = 0; kx < K; ++kx) {
            const int kk = ky*K + kx;
            float dy = s_off[wl*2*KK + 2*kk];
            float dx = s_off[wl*2*KK + 2*kk + 1];
            float py = (float)(h + ky*DIL - PAD) + dy;
            float px = (float)(w + kx*DIL - PAD) + dx;
            float y0f = floorf(py), x0f = floorf(px);
            float wy = py - y0f,    wx = px - x0f;
            int y0 = (int)y0f, x0i = (int)x0f;
            int y1 = y0 + 1,   x1  = x0i + 1;
            float vy0 = (y0  >= 0 && y0  < H_) ? 1.f : 0.f;
            float vy1 = (y1  >= 0 && y1  < H_) ? 1.f : 0.f;
            float vx0 = (x0i >= 0 && x0i < W_) ? 1.f : 0.f;
            float vx1 = (x1  >= 0 && x1  < W_) ? 1.f : 0.f;
            int y0c = min(max(y0, 0), H_-1), y1c = min(max(y1, 0), H_-1);
            int x0c = min(max(x0i,0), W_-1), x1c = min(max(x1, 0), W_-1);
            float w00 = (1.f-wy)*(1.f-wx)*vy0*vx0;
            float w01 = (1.f-wy)*wx      *vy0*vx1;
            float w10 = wy      *(1.f-wx)*vy1*vx0;
            float w11 = wy      *wx      *vy1*vx1;

            size_t r0 = (brow + y0c)*W_, r1 = (brow + y1c)*W_;
            float4 g00 = img4[(r0 + x0c)*16 + c4];
            float4 g01 = img4[(r0 + x1c)*16 + c4];
            float4 g10 = img4[(r1 + x0c)*16 + c4];
            float4 g11 = img4[(r1 + x1c)*16 + c4];
            float4 dv  = s_dw4[kk*16 + c4];

            float gx_ = g00.x*w00 + g01.x*w01 + g10.x*w10 + g11.x*w11;
            float gy_ = g00.y*w00 + g01.y*w01 + g10.y*w10 + g11.y*w11;
            float gz_ = g00.z*w00 + g01.z*w01 + g10.z*w10 + g11.z*w11;
            float gw_ = g00.w*w00 + g01.w*w01 + g10.w*w10 + g11.w*w11;
            a.x += gx_*dv.x; a.y += gy_*dv.y;
            a.z += gz_*dv.z; a.w += gw_*dv.w;
        }
    }

    ((float4*)outp)[((size_t)(b*H_ + h)*W_ + w)*16 + c4] = a;
}

// ---------------------------------------------------------------------------
// Pointwise 1x1 conv + bias, then out = x * attn. Output in NCHW.
// ---------------------------------------------------------------------------
__global__ void __launch_bounds__(224) pw_mul_kernel(
    const float* __restrict__ attn,  // [B,H,W,64]
    const float* __restrict__ pw,    // [64,64]
    const float* __restrict__ pb,    // [64]
    const float* __restrict__ x,     // [B,64,H,W]
    float* __restrict__ out)         // [B,64,H,W]
{
    __shared__ float s_a[W_*64];
    __shared__ float s_w[64*64];
    const int t = threadIdx.x;
    const int h = blockIdx.x, b = blockIdx.y;

    const float* arow = attn + (size_t)(b*H_ + h)*W_*64;
    for (int i = t; i < W_*64; i += 224) s_a[i] = arow[i];
    for (int i = t; i < 64*64; i += 224) s_w[i] = pw[i];
    __syncthreads();

    const int w = t % W_, cg = t / W_;
    float acc[16] = {};
    const float4* sa4 = (const float4*)s_a;
    const float4* sw4 = (const float4*)s_w;
    for (int ciq = 0; ciq < 16; ++ciq) {
        float4 av = sa4[w*16 + ciq];
        #pragma unroll
        for (int j = 0; j < 16; ++j) {
            float4 wv = sw4[(cg*16 + j)*16 + ciq];
            acc[j] += av.x*wv.x + av.y*wv.y + av.z*wv.z + av.w*wv.w;
        }
    }
    #pragma unroll
    for (int j = 0; j < 16; ++j) {
        int co = cg*16 + j;
        size_t idx = ((size_t)(b*64 + co)*H_ + h)*W_ + w;
        out[idx] = x[idx] * (acc[j] + pb[co]);
    }
}

// ---------------------------------------------------------------------------
extern "C" void kernel_launch(void* const* d_in, const int* in_sizes, int n_in,
                              void* d_out, int out_size)
{
    const float* x   = (const float*)d_in[0];
    const float* ow1 = (const float*)d_in[1];
    const float* ob1 = (const float*)d_in[2];
    const float* dw1 = (const float*)d_in[3];
    const float* ow2 = (const float*)d_in[4];
    const float* ob2 = (const float*)d_in[5];
    const float* dw2 = (const float*)d_in[6];
    const float* pww = (const float*)d_in[7];
    const float* pwb = (const float*)d_in[8];
    float* out = (float*)d_out;

    float *xT, *off1, *attn1, *off2, *attn2, *w1T, *w2T, *dw1T, *dw2T;
    cudaGetSymbolAddress((void**)&xT,    g_xT);
    cudaGetSymbolAddress((void**)&off1,  g_off1);
    cudaGetSymbolAddress((void**)&attn1, g_attn1);
    cudaGetSymbolAddress((void**)&off2,  g_off2);
    cudaGetSymbolAddress((void**)&attn2, g_attn2);
    cudaGetSymbolAddress((void**)&w1T,   g_w1T);
    cudaGetSymbolAddress((void**)&w2T,   g_w2T);
    cudaGetSymbolAddress((void**)&dw1T,  g_dw1T);
    cudaGetSymbolAddress((void**)&dw2T,  g_dw2T);

    const int NPREP = 16*25*64*4 + 16*49*112*4 + 25*64 + 49*64;
    prep_kernel<<<(NPREP + 255)/256, 256>>>(ow1, ow2, dw1, dw2, w1T, w2T, dw1T, dw2T);
    transpose_kernel<<<dim3(H_, B_), 224>>>(x, xT);

    // stage 1: K=5, dil=1, pad=2, CO=50 (padded 64)
    conv_off_kernel<5,1,2,50,64><<<dim3(16, 4, B_), 196>>>(
        (const float4*)w1T, ob1, xT, off1);
    deform_sample_kernel<5,1,2><<<dim3(2, H_, B_), 448>>>(xT, off1, dw1T, attn1);

    // stage 2: K=7, dil=3, pad=9, CO=98 (padded 112)
    conv_off_kernel<7,3,9,98,112><<<dim3(16, 7, B_), 196>>>(
        (const float4*)w2T, ob2, attn1, off2);
    deform_sample_kernel<7,3,9><<<dim3(2, H_, B_), 448>>>(attn1, off2, dw2T, attn2);

    // pointwise + elementwise multiply
    pw_mul_kernel<<<dim3(H_, B_), 224>>>(attn2, pww, pwb, x, out);
}

// round 6
// speedup vs baseline: 1.9732x; 1.3847x over previous
#include <cuda_runtime.h>

#define B_ 4
#define C_ 64
#define H_ 56
#define W_ 56
#define HW_ (H_*W_)

typedef unsigned long long ull;

// Scratch (device globals; no allocation allowed)
__device__ __align__(16) float g_xT   [B_*HW_*C_];    // x transposed to NHWC
__device__ __align__(16) float g_off1 [B_*HW_*50];    // offsets conv1, NHWC
__device__ __align__(16) float g_attn1[B_*HW_*C_];    // deform-dw 1 output
__device__ __align__(16) float g_off2 [B_*HW_*98];    // offsets conv2, NHWC
__device__ __align__(16) float g_attn2[B_*HW_*C_];    // deform-dw 2 output
// Pre-transposed / pre-paired weights
// w layout (floats): (((cc*KK + tap)*(COP/2) + cpg)*4 + ci)*2 + j   j = co&1
__device__ __align__(16) float g_w1T  [16*25*28*4*2]; // COP1=56 -> 28 co-pairs
__device__ __align__(16) float g_w2T  [16*49*52*4*2]; // COP2=104 -> 52 co-pairs
__device__ __align__(16) float g_dw1T [25*64];        // [kk][c]
__device__ __align__(16) float g_dw2T [49*64];        // [kk][c]

// ---------------------------------------------------------------------------
// f32x2 helpers
// ---------------------------------------------------------------------------
__device__ __forceinline__ void ffma2(ull& acc, ull a, ull b) {
    asm("fma.rn.f32x2 %0, %1, %2, %0;" : "+l"(acc) : "l"(a), "l"(b));
}
__device__ __forceinline__ ull dup2(float v) {
    ull r; asm("mov.b64 %0, {%1, %1};" : "=l"(r) : "f"(v)); return r;
}
__device__ __forceinline__ ull pack2(float a, float b) {
    ull r; asm("mov.b64 %0, {%1, %2};" : "=l"(r) : "f"(a), "f"(b)); return r;
}
__device__ __forceinline__ float2 unpack2(ull v) {
    float2 r; asm("mov.b64 {%0, %1}, %2;" : "=f"(r.x), "=f"(r.y) : "l"(v)); return r;
}

// ---------------------------------------------------------------------------
// Weight prep: OIHW -> paired layout for f32x2, + dw transpose
// ---------------------------------------------------------------------------
__global__ void __launch_bounds__(256) prep_kernel(
    const float* __restrict__ ow1, const float* __restrict__ ow2,
    const float* __restrict__ dw1, const float* __restrict__ dw2,
    float* __restrict__ w1T, float* __restrict__ w2T,
    float* __restrict__ dw1T, float* __restrict__ dw2T)
{
    const int N1 = 16*25*28*4*2;     // 89600
    const int N2 = 16*49*52*4*2;     // 326144
    const int N3 = 25*64;
    const int N4 = 49*64;
    int idx = blockIdx.x*256 + threadIdx.x;
    if (idx < N1) {
        int i = idx;
        int j  = i & 1;
        int ci = (i >> 1) & 3;
        int cpg = (i >> 3) % 28;
        int r   = (i >> 3) / 28;
        int tap = r % 25, cc = r / 25;
        int co = cpg*2 + j;
        w1T[i] = (co < 50) ? ow1[(size_t)(co*64 + cc*4 + ci)*25 + tap] : 0.f;
    } else if (idx < N1 + N2) {
        int i = idx - N1;
        int j  = i & 1;
        int ci = (i >> 1) & 3;
        int cpg = (i >> 3) % 52;
        int r   = (i >> 3) / 52;
        int tap = r % 49, cc = r / 49;
        int co = cpg*2 + j;
        w2T[i] = (co < 98) ? ow2[(size_t)(co*64 + cc*4 + ci)*49 + tap] : 0.f;
    } else if (idx < N1 + N2 + N3) {
        int i = idx - N1 - N2;
        int kk = i >> 6, c = i & 63;
        dw1T[i] = dw1[c*25 + kk];
    } else if (idx < N1 + N2 + N3 + N4) {
        int i = idx - N1 - N2 - N3;
        int kk = i >> 6, c = i & 63;
        dw2T[i] = dw2[c*49 + kk];
    }
}

// ---------------------------------------------------------------------------
// NCHW -> NHWC transpose of x
// ---------------------------------------------------------------------------
__global__ void __launch_bounds__(224) transpose_kernel(
    const float* __restrict__ x, float* __restrict__ xT)
{
    int h = blockIdx.x, b = blockIdx.y;
    __shared__ float s[C_*W_];
    int t = threadIdx.x;
    for (int i = t; i < C_*W_; i += 224) {
        int c = i / W_, w = i - c*W_;
        s[i] = x[((b*C_ + c)*H_ + h)*W_ + w];
    }
    __syncthreads();
    float* orow = xT + (size_t)(b*H_ + h)*W_*C_;
    for (int j = t; j < C_*W_; j += 224) {
        int w = j >> 6, c = j & 63;
        orow[j] = s[c*W_ + w];
    }
}

// ---------------------------------------------------------------------------
// Offset conv with packed f32x2 FMA.
// Tile = 28(w) x 14(h); 196 threads; thread = 2 pixels (rows ly, ly+7) x 8 co
// (4 co-pairs). grid = (8 tiles, COP/8, B).
// ---------------------------------------------------------------------------
template<int K, int DIL, int PAD, int CO, int COP>
__global__ void __launch_bounds__(196) conv_off_kernel(
    const ull*   __restrict__ wT,    // paired weights (see prep)
    const float* __restrict__ bias,  // [CO]
    const float* __restrict__ in,    // [B,H,W,64]
    float*       __restrict__ out)   // [B,H,W,CO]
{
    constexpr int TW = 28 + 2*PAD;   // (K-1)*DIL == 2*PAD
    constexpr int TH = 14 + 2*PAD;
    constexpr int KK = K*K;
    __shared__ __align__(16) float4 s_in[TH*TW];
    __shared__ __align__(16) ull    s_w [KK*16];   // [tap][cp(4)][ci(4)] pairs

    const int t      = threadIdx.x;
    const int tIdx   = blockIdx.x;
    const int co_blk = blockIdx.y;
    const int b      = blockIdx.z;
    const int oy0 = (tIdx >> 1) * 14, ox0 = (tIdx & 1) * 28;
    const int gy0 = oy0 - PAD,        gx0 = ox0 - PAD;
    const int ly  = t / 28, lx = t - ly*28;      // ly 0..6

    ull accA[4], accB[4];
    #pragma unroll
    for (int cp = 0; cp < 4; ++cp) {
        int cog = co_blk*8 + cp*2;
        float b0 = (cog   < CO) ? bias[cog]   : 0.f;
        float b1 = (cog+1 < CO) ? bias[cog+1] : 0.f;
        accA[cp] = pack2(b0, b1);
        accB[cp] = pack2(b0, b1);
    }

    const float4* in4 = (const float4*)in;

    for (int cc = 0; cc < 16; ++cc) {            // 64 input channels / 4
        __syncthreads();
        for (int i = t; i < TH*TW; i += 196) {
            int sy = i / TW, sx = i - sy*TW;
            int gy = gy0 + sy, gx = gx0 + sx;
            float4 v = make_float4(0.f, 0.f, 0.f, 0.f);
            if ((unsigned)gy < (unsigned)H_ && (unsigned)gx < (unsigned)W_)
                v = in4[((size_t)(b*H_ + gy)*W_ + gx)*16 + cc];
            s_in[i] = v;
        }
        for (int i = t; i < KK*16; i += 196) {
            int tap = i >> 4, q = i & 15;        // q = cp*4+ci
            s_w[i] = wT[((size_t)(cc*KK + tap)*(COP/2) + co_blk*4 + (q>>2))*4 + (q&3)];
        }
        __syncthreads();

        for (int ky = 0; ky < K; ++ky) {
            #pragma unroll
            for (int kx = 0; kx < K; ++kx) {
                int sy = ly + ky*DIL, sx = lx + kx*DIL;
                float4 vA = s_in[sy*TW + sx];
                float4 vB = s_in[(sy+7)*TW + sx];
                ull a0 = dup2(vA.x), a1 = dup2(vA.y), a2 = dup2(vA.z), a3 = dup2(vA.w);
                ull b0 = dup2(vB.x), b1 = dup2(vB.y), b2 = dup2(vB.z), b3 = dup2(vB.w);
                const int tb = (ky*K + kx)*16;
                #pragma unroll
                for (int cp = 0; cp < 4; ++cp) {
                    const ulonglong2* wr = (const ulonglong2*)(s_w + tb + cp*4);
                    ulonglong2 w01 = wr[0], w23 = wr[1];
                    ffma2(accA[cp], a0, w01.x); ffma2(accA[cp], a1, w01.y);
                    ffma2(accA[cp], a2, w23.x); ffma2(accA[cp], a3, w23.y);
                    ffma2(accB[cp], b0, w01.x); ffma2(accB[cp], b1, w01.y);
                    ffma2(accB[cp], b2, w23.x); ffma2(accB[cp], b3, w23.y);
                }
            }
        }
    }

    const int oy = oy0 + ly, ox = ox0 + lx;
    float* opA = out + ((size_t)(b*H_ + oy)*W_ + ox)*CO + co_blk*8;
    float* opB = opA + (size_t)7*W_*CO;
    #pragma unroll
    for (int cp = 0; cp < 4; ++cp) {
        float2 rA = unpack2(accA[cp]);
        float2 rB = unpack2(accB[cp]);
        int cog = co_blk*8 + cp*2;
        if (cog   < CO) { opA[cp*2]   = rA.x; opB[cp*2]   = rB.x; }
        if (cog+1 < CO) { opA[cp*2+1] = rA.y; opB[cp*2+1] = rB.y; }
    }
}

// ---------------------------------------------------------------------------
// Deformable depthwise sampling, 2 phases:
//  phase 1: per (pixel, tap) compute bilinear indices + weights once (smem)
//  phase 2: 28 px x 16 channel-float4 threads gather and accumulate
// grid = (2 half-rows, H, B), 448 threads.
// ---------------------------------------------------------------------------
template<int K, int DIL, int PAD>
__global__ void __launch_bounds__(448) deform_sample_kernel(
    const float* __restrict__ img,   // [B,H,W,64]
    const float* __restrict__ off,   // [B,H,W,2*K*K]
    const float* __restrict__ dwT,   // [kk][c]
    float* __restrict__ outp)        // [B,H,W,64]
{
    constexpr int KK = K*K;
    constexpr int NT = 28*KK;
    __shared__ __align__(16) float4 s_dw4[KK*16];
    __shared__ __align__(16) short4 s_idx[NT];
    __shared__ __align__(16) float4 s_wt [NT];

    const int t = threadIdx.x;
    const int half = blockIdx.x, h = blockIdx.y, b = blockIdx.z;
    const int w0 = half * 28;

    const float4* dwT4 = (const float4*)dwT;
    for (int i = t; i < KK*16; i += 448) s_dw4[i] = dwT4[i];

    // phase 1: bilinear precompute, one task per (pixel-in-halfrow, tap)
    const float2* ob2 = (const float2*)(off + ((size_t)(b*H_ + h)*W_ + w0)*2*KK);
    for (int i = t; i < NT; i += 448) {
        int wl = i / KK, kk = i - wl*KK;
        int ky = kk / K, kx = kk - ky*K;
        float2 d = ob2[i];                       // (dy, dx), layout [w][kk][2]
        float py = (float)(h + ky*DIL - PAD) + d.x;
        float px = (float)(w0 + wl + kx*DIL - PAD) + d.y;
        float y0f = floorf(py), x0f = floorf(px);
        float wy = py - y0f,    wx = px - x0f;
        int y0 = (int)y0f, x0i = (int)x0f;
        int y1 = y0 + 1,   x1  = x0i + 1;
        float vy0 = (y0  >= 0 && y0  < H_) ? 1.f : 0.f;
        float vy1 = (y1  >= 0 && y1  < H_) ? 1.f : 0.f;
        float vx0 = (x0i >= 0 && x0i < W_) ? 1.f : 0.f;
        float vx1 = (x1  >= 0 && x1  < W_) ? 1.f : 0.f;
        int y0c = min(max(y0, 0), H_-1), y1c = min(max(y1, 0), H_-1);
        int x0c = min(max(x0i,0), W_-1), x1c = min(max(x1, 0), W_-1);
        int r0 = y0c*W_, r1 = y1c*W_;
        s_idx[i] = make_short4((short)(r0+x0c), (short)(r0+x1c),
                               (short)(r1+x0c), (short)(r1+x1c));
        s_wt[i]  = make_float4((1.f-wy)*(1.f-wx)*vy0*vx0,
                               (1.f-wy)*wx      *vy0*vx1,
                               wy      *(1.f-wx)*vy1*vx0,
                               wy      *wx      *vy1*vx1);
    }
    __syncthreads();

    // phase 2: gather
    const int c4 = t & 15;
    const int wl = t >> 4;
    const int w  = w0 + wl;
    const float4* imgb = (const float4*)img + (size_t)b*HW_*16;

    float4 a = make_float4(0.f, 0.f, 0.f, 0.f);
    for (int kk = 0; kk < KK; ++kk) {
        short4 id = s_idx[wl*KK + kk];
        float4 wt = s_wt [wl*KK + kk];
        float4 g00 = imgb[(int)id.x*16 + c4];
        float4 g01 = imgb[(int)id.y*16 + c4];
        float4 g10 = imgb[(int)id.z*16 + c4];
        float4 g11 = imgb[(int)id.w*16 + c4];
        float4 dv  = s_dw4[kk*16 + c4];
        float sx_ = g00.x*wt.x + g01.x*wt.y + g10.x*wt.z + g11.x*wt.w;
        float sy_ = g00.y*wt.x + g01.y*wt.y + g10.y*wt.z + g11.y*wt.w;
        float sz_ = g00.z*wt.x + g01.z*wt.y + g10.z*wt.z + g11.z*wt.w;
        float sw_ = g00.w*wt.x + g01.w*wt.y + g10.w*wt.z + g11.w*wt.w;
        a.x += sx_*dv.x; a.y += sy_*dv.y; a.z += sz_*dv.z; a.w += sw_*dv.w;
    }
    ((float4*)outp)[((size_t)(b*H_ + h)*W_ + w)*16 + c4] = a;
}

// ---------------------------------------------------------------------------
// Pointwise 1x1 conv + bias, then out = x * attn. Output in NCHW.
// ---------------------------------------------------------------------------
__global__ void __launch_bounds__(224) pw_mul_kernel(
    const float* __restrict__ attn,  // [B,H,W,64]
    const float* __restrict__ pw,    // [64,64]
    const float* __restrict__ pb,    // [64]
    const float* __restrict__ x,     // [B,64,H,W]
    float* __restrict__ out)         // [B,64,H,W]
{
    __shared__ float s_a[W_*64];
    __shared__ float s_w[64*64];
    const int t = threadIdx.x;
    const int h = blockIdx.x, b = blockIdx.y;

    const float* arow = attn + (size_t)(b*H_ + h)*W_*64;
    for (int i = t; i < W_*64; i += 224) s_a[i] = arow[i];
    for (int i = t; i < 64*64; i += 224) s_w[i] = pw[i];
    __syncthreads();

    const int w = t % W_, cg = t / W_;
    float acc[16] = {};
    const float4* sa4 = (const float4*)s_a;
    const float4* sw4 = (const float4*)s_w;
    for (int ciq = 0; ciq < 16; ++ciq) {
        float4 av = sa4[w*16 + ciq];
        #pragma unroll
        for (int j = 0; j < 16; ++j) {
            float4 wv = sw4[(cg*16 + j)*16 + ciq];
            acc[j] += av.x*wv.x + av.y*wv.y + av.z*wv.z + av.w*wv.w;
        }
    }
    #pragma unroll
    for (int j = 0; j < 16; ++j) {
        int co = cg*16 + j;
        size_t idx = ((size_t)(b*64 + co)*H_ + h)*W_ + w;
        out[idx] = x[idx] * (acc[j] + pb[co]);
    }
}

// ---------------------------------------------------------------------------
extern "C" void kernel_launch(void* const* d_in, const int* in_sizes, int n_in,
                              void* d_out, int out_size)
{
    const float* x   = (const float*)d_in[0];
    const float* ow1 = (const float*)d_in[1];
    const float* ob1 = (const float*)d_in[2];
    const float* dw1 = (const float*)d_in[3];
    const float* ow2 = (const float*)d_in[4];
    const float* ob2 = (const float*)d_in[5];
    const float* dw2 = (const float*)d_in[6];
    const float* pww = (const float*)d_in[7];
    const float* pwb = (const float*)d_in[8];
    float* out = (float*)d_out;

    float *xT, *off1, *attn1, *off2, *attn2, *w1T, *w2T, *dw1T, *dw2T;
    cudaGetSymbolAddress((void**)&xT,    g_xT);
    cudaGetSymbolAddress((void**)&off1,  g_off1);
    cudaGetSymbolAddress((void**)&attn1, g_attn1);
    cudaGetSymbolAddress((void**)&off2,  g_off2);
    cudaGetSymbolAddress((void**)&attn2, g_attn2);
    cudaGetSymbolAddress((void**)&w1T,   g_w1T);
    cudaGetSymbolAddress((void**)&w2T,   g_w2T);
    cudaGetSymbolAddress((void**)&dw1T,  g_dw1T);
    cudaGetSymbolAddress((void**)&dw2T,  g_dw2T);

    const int NPREP = 16*25*28*4*2 + 16*49*52*4*2 + 25*64 + 49*64;
    prep_kernel<<<(NPREP + 255)/256, 256>>>(ow1, ow2, dw1, dw2, w1T, w2T, dw1T, dw2T);
    transpose_kernel<<<dim3(H_, B_), 224>>>(x, xT);

    // stage 1: K=5, dil=1, pad=2, CO=50 (padded 56 -> 7 co-blocks of 8)
    conv_off_kernel<5,1,2,50,56><<<dim3(8, 7, B_), 196>>>(
        (const ull*)w1T, ob1, xT, off1);
    deform_sample_kernel<5,1,2><<<dim3(2, H_, B_), 448>>>(xT, off1, dw1T, attn1);

    // stage 2: K=7, dil=3, pad=9, CO=98 (padded 104 -> 13 co-blocks of 8)
    conv_off_kernel<7,3,9,98,104><<<dim3(8, 13, B_), 196>>>(
        (const ull*)w2T, ob2, attn1, off2);
    deform_sample_kernel<7,3,9><<<dim3(2, H_, B_), 448>>>(attn1, off2, dw2T, attn2);

    // pointwise + elementwise multiply
    pw_mul_kernel<<<dim3(H_, B_), 224>>>(attn2, pww, pwb, x, out);
}

// round 7
// speedup vs baseline: 3.7712x; 1.9112x over previous
#include <cuda_runtime.h>
#include <cuda_bf16.h>

#define B_ 4
#define H_ 56
#define W_ 56
#define HW_ (H_*W_)

typedef unsigned int  u32;
typedef unsigned short u16;

// ---------------------------------------------------------------------------
// Scratch (device globals; no allocation allowed)
// ---------------------------------------------------------------------------
__device__ __align__(16) float g_xT   [B_*HW_*64];
__device__ __align__(16) __nv_bfloat16 g_xh [B_*HW_*64];
__device__ __align__(16) __nv_bfloat16 g_xl [B_*HW_*64];
__device__ __align__(16) float g_off1 [B_*HW_*50];
__device__ __align__(16) float g_attn1[B_*HW_*64];
__device__ __align__(16) __nv_bfloat16 g_a1h[B_*HW_*64];
__device__ __align__(16) __nv_bfloat16 g_a1l[B_*HW_*64];
__device__ __align__(16) float g_off2 [B_*HW_*98];
__device__ __align__(16) float g_attn2[B_*HW_*64];
// bf16-split weights: [tap][co(COP)][ci(64)]
__device__ __align__(16) __nv_bfloat16 g_w1h[25*64*64];
__device__ __align__(16) __nv_bfloat16 g_w1l[25*64*64];
__device__ __align__(16) __nv_bfloat16 g_w2h[49*112*64];
__device__ __align__(16) __nv_bfloat16 g_w2l[49*112*64];
__device__ __align__(16) float g_dw1T [25*64];   // [kk][c]
__device__ __align__(16) float g_dw2T [49*64];

// ---------------------------------------------------------------------------
// helpers
// ---------------------------------------------------------------------------
__device__ __forceinline__ void split_bf16(float v, __nv_bfloat16& h, __nv_bfloat16& l){
    h = __float2bfloat16_rn(v);
    l = __float2bfloat16_rn(v - __bfloat162float(h));
}
__device__ __forceinline__ void cp16(u32 dst, const void* src){
    asm volatile("cp.async.cg.shared.global [%0], [%1], 16;" :: "r"(dst), "l"(src));
}
#define CP_COMMIT() asm volatile("cp.async.commit_group;")
#define CP_WAIT0()  asm volatile("cp.async.wait_group 0;")
__device__ __forceinline__ void mma_bf16(float* d, u32 a0,u32 a1,u32 a2,u32 a3,u32 b0,u32 b1){
    asm volatile("mma.sync.aligned.m16n8k16.row.col.f32.bf16.bf16.f32 "
      "{%0,%1,%2,%3}, {%4,%5,%6,%7}, {%8,%9}, {%0,%1,%2,%3};"
      : "+f"(d[0]),"+f"(d[1]),"+f"(d[2]),"+f"(d[3])
      : "r"(a0),"r"(a1),"r"(a2),"r"(a3),"r"(b0),"r"(b1));
}

// ---------------------------------------------------------------------------
// Weight prep: OIHW fp32 -> bf16 hi/lo in [tap][co][ci] + dw transpose
// ---------------------------------------------------------------------------
__global__ void __launch_bounds__(256) prep_kernel(
    const float* __restrict__ ow1, const float* __restrict__ ow2,
    const float* __restrict__ dw1, const float* __restrict__ dw2,
    __nv_bfloat16* __restrict__ w1h, __nv_bfloat16* __restrict__ w1l,
    __nv_bfloat16* __restrict__ w2h, __nv_bfloat16* __restrict__ w2l,
    float* __restrict__ dw1T, float* __restrict__ dw2T)
{
    const int N1 = 25*64*64;    // 102400
    const int N2 = 49*112*64;   // 351232
    const int N3 = 25*64;
    const int N4 = 49*64;
    int idx = blockIdx.x*256 + threadIdx.x;
    if (idx < N1) {
        int ci = idx & 63; int r = idx >> 6; int co = r & 63; int tap = r >> 6;
        float v = (co < 50) ? ow1[(size_t)(co*64 + ci)*25 + tap] : 0.f;
        __nv_bfloat16 hh, ll; split_bf16(v, hh, ll);
        w1h[idx] = hh; w1l[idx] = ll;
    } else if (idx < N1 + N2) {
        int i = idx - N1;
        int ci = i & 63; int r = i >> 6; int co = r % 112; int tap = r / 112;
        float v = (co < 98) ? ow2[(size_t)(co*64 + ci)*49 + tap] : 0.f;
        __nv_bfloat16 hh, ll; split_bf16(v, hh, ll);
        w2h[i] = hh; w2l[i] = ll;
    } else if (idx < N1 + N2 + N3) {
        int i = idx - N1 - N2;
        int kk = i >> 6, c = i & 63;
        dw1T[i] = dw1[c*25 + kk];
    } else if (idx < N1 + N2 + N3 + N4) {
        int i = idx - N1 - N2 - N3;
        int kk = i >> 6, c = i & 63;
        dw2T[i] = dw2[c*49 + kk];
    }
}

// ---------------------------------------------------------------------------
// NCHW -> NHWC transpose of x, also emitting bf16 hi/lo copies
// ---------------------------------------------------------------------------
__global__ void __launch_bounds__(224) transpose_kernel(
    const float* __restrict__ x, float* __restrict__ xT,
    __nv_bfloat16* __restrict__ xh, __nv_bfloat16* __restrict__ xl)
{
    int h = blockIdx.x, b = blockIdx.y;
    __shared__ float s[64*W_];
    int t = threadIdx.x;
    for (int i = t; i < 64*W_; i += 224) {
        int c = i / W_, w = i - c*W_;
        s[i] = x[((b*64 + c)*H_ + h)*W_ + w];
    }
    __syncthreads();
    size_t rb = (size_t)(b*H_ + h)*W_*64;
    for (int j = t; j < 32*W_; j += 224) {
        int w = j >> 5, cp = j & 31; int c0 = cp*2;
        float f0 = s[c0*W_ + w], f1 = s[(c0+1)*W_ + w];
        xT[rb + w*64 + c0]   = f0;
        xT[rb + w*64 + c0+1] = f1;
        __nv_bfloat16 h0,l0,h1,l1;
        split_bf16(f0, h0, l0); split_bf16(f1, h1, l1);
        __nv_bfloat162 hp; hp.x = h0; hp.y = h1;
        __nv_bfloat162 lp; lp.x = l0; lp.y = l1;
        *(__nv_bfloat162*)(xh + rb + w*64 + c0) = hp;
        *(__nv_bfloat162*)(xl + rb + w*64 + c0) = lp;
    }
}

// ---------------------------------------------------------------------------
// Offset conv as implicit GEMM on tensor cores, bf16x3 (hi/lo) for fp32 accuracy.
// Block = one (b,h) output row: M=56(pad 64) x N=COP, K = 64ci per tap.
// 256 threads = 8 warps: warp (mt = wid&3, half = wid>>2) owns m16 x (COP/2).
// A: extended row [WE][64ci] hi+lo staged per ky (stride 72 -> conflict-free).
// B: per-tap [co][64ci] hi+lo, cp.async double-buffered across taps.
// ---------------------------------------------------------------------------
template<int K, int DIL, int PAD, int CO, int COP>
__global__ void __launch_bounds__(256) conv_mma_kernel(
    const __nv_bfloat16* __restrict__ Ih, const __nv_bfloat16* __restrict__ Il,
    const __nv_bfloat16* __restrict__ Wh, const __nv_bfloat16* __restrict__ Wl,
    const float* __restrict__ bias, float* __restrict__ out)
{
    constexpr int KK = K*K;
    constexpr int WE = (K-1)*DIL + 64;   // extended row length (halo + 64 m-pad)
    constexpr int NT = COP/16;           // n-tiles (of 8) per warp
    constexpr int AE = WE*72;            // u16 elems per A array (stride 72)
    constexpr int BE = COP*72;           // u16 elems per B array per buffer

    extern __shared__ __align__(16) u16 sm[];
    u16* sAh = sm;
    u16* sAl = sAh + AE;
    u16* sB  = sAl + AE;                 // [buf][hi BE][lo BE]

    const int t = threadIdx.x, lane = t & 31, wid = t >> 5;
    const int h = blockIdx.x, b = blockIdx.y;
    const int mt = wid & 3, half = wid >> 2;
    const int kq = (lane & 3)*2;
    const int mrow = mt*16 + (lane >> 2);
    const int colbase = half*(COP/2);

    const u32 smbase = (u32)__cvta_generic_to_shared(sm);
    const u32 dAh = smbase;
    const u32 dAl = smbase + AE*2;
    const u32 dB  = smbase + 4*AE;       // bytes

    float acc[NT][4];
    #pragma unroll
    for (int nt = 0; nt < NT; ++nt) {
        int co0 = colbase + nt*8 + kq;
        float b0 = (co0   < CO) ? bias[co0]   : 0.f;
        float b1 = (co0+1 < CO) ? bias[co0+1] : 0.f;
        acc[nt][0] = b0; acc[nt][1] = b1; acc[nt][2] = b0; acc[nt][3] = b1;
    }

    // prologue: stage B for tap 0 into buffer 0
    {
        for (int c = t; c < COP*8; c += 256) {
            int co = c >> 3, kc = c & 7;
            u32 off = (u32)(co*72 + kc*8)*2;
            cp16(dB + off,        Wh + (size_t)co*64 + kc*8);
            cp16(dB + BE*2 + off, Wl + (size_t)co*64 + kc*8);
        }
        CP_COMMIT();
    }

    for (int ky = 0; ky < K; ++ky) {
        // stage A (extended input row for this ky), hi + lo
        const int hp = h + ky*DIL - PAD;
        const bool hv = ((unsigned)hp < (unsigned)H_);
        for (int c = t; c < WE*8; c += 256) {
            int j = c >> 3, kc = c & 7;
            int g = j - PAD;
            if (hv && (unsigned)g < (unsigned)W_) {
                size_t so = ((size_t)(b*H_ + hp)*W_ + g)*64 + kc*8;
                u32 off = (u32)(j*72 + kc*8)*2;
                cp16(dAh + off, Ih + so);
                cp16(dAl + off, Il + so);
            } else {
                float4 z = make_float4(0.f, 0.f, 0.f, 0.f);
                *(float4*)(sAh + j*72 + kc*8) = z;
                *(float4*)(sAl + j*72 + kc*8) = z;
            }
        }
        CP_COMMIT();
        CP_WAIT0();
        __syncthreads();

        for (int kx = 0; kx < K; ++kx) {
            const int tap = ky*K + kx;
            // prefetch next tap's B into the other buffer
            if (tap + 1 < KK) {
                u32 dst = dB + (u32)((tap+1) & 1)*(BE*4);
                const __nv_bfloat16* wh = Wh + (size_t)(tap+1)*COP*64;
                const __nv_bfloat16* wl = Wl + (size_t)(tap+1)*COP*64;
                for (int c = t; c < COP*8; c += 256) {
                    int co = c >> 3, kc = c & 7;
                    u32 off = (u32)(co*72 + kc*8)*2;
                    cp16(dst + off,        wh + (size_t)co*64 + kc*8);
                    cp16(dst + BE*2 + off, wl + (size_t)co*64 + kc*8);
                }
                CP_COMMIT();
            }

            // compute on buffer tap&1
            const u16* Bh = sB + (size_t)(tap & 1)*(BE*2);
            const u16* Bl = Bh + BE;
            const int ar0 = (kx*DIL + mrow)*72;
            const int ar1 = ar0 + 8*72;
            #pragma unroll
            for (int ks = 0; ks < 4; ++ks) {
                const int kk = ks*16 + kq;
                u32 ah0 = *(const u32*)(sAh + ar0 + kk);
                u32 ah1 = *(const u32*)(sAh + ar1 + kk);
                u32 ah2 = *(const u32*)(sAh + ar0 + kk + 8);
                u32 ah3 = *(const u32*)(sAh + ar1 + kk + 8);
                u32 al0 = *(const u32*)(sAl + ar0 + kk);
                u32 al1 = *(const u32*)(sAl + ar1 + kk);
                u32 al2 = *(const u32*)(sAl + ar0 + kk + 8);
                u32 al3 = *(const u32*)(sAl + ar1 + kk + 8);
                #pragma unroll
                for (int nt = 0; nt < NT; ++nt) {
                    const int cb = (colbase + nt*8 + (lane >> 2))*72;
                    u32 bh0 = *(const u32*)(Bh + cb + kk);
                    u32 bh1 = *(const u32*)(Bh + cb + kk + 8);
                    u32 bl0 = *(const u32*)(Bl + cb + kk);
                    u32 bl1 = *(const u32*)(Bl + cb + kk + 8);
                    mma_bf16(acc[nt], ah0,ah1,ah2,ah3, bh0,bh1);
                    mma_bf16(acc[nt], al0,al1,al2,al3, bh0,bh1);
                    mma_bf16(acc[nt], ah0,ah1,ah2,ah3, bl0,bl1);
                }
            }
            CP_WAIT0();
            __syncthreads();
        }
    }

    // epilogue: rows mrow / mrow+8, col pairs (kq, kq+1)
    float* po = out + (size_t)(b*H_ + h)*W_*CO;
    const int r1 = mrow + 8;
    #pragma unroll
    for (int nt = 0; nt < NT; ++nt) {
        int co0 = colbase + nt*8 + kq;
        if (co0   < CO) po[mrow*CO + co0]   = acc[nt][0];
        if (co0+1 < CO) po[mrow*CO + co0+1] = acc[nt][1];
        if (r1 < 56) {
            if (co0   < CO) po[r1*CO + co0]   = acc[nt][2];
            if (co0+1 < CO) po[r1*CO + co0+1] = acc[nt][3];
        }
    }
}

// ---------------------------------------------------------------------------
// Deformable depthwise sampling (2-phase). Optionally emits bf16 hi/lo output.
// grid = (2 half-rows, H, B), 448 threads = 28 px x 16 channel-float4.
// ---------------------------------------------------------------------------
template<int K, int DIL, int PAD, bool SPLIT>
__global__ void __launch_bounds__(448) deform_sample_kernel(
    const float* __restrict__ img,   // [B,H,W,64]
    const float* __restrict__ off,   // [B,H,W,2*K*K]
    const float* __restrict__ dwT,   // [kk][c]
    float* __restrict__ outp,        // [B,H,W,64]
    __nv_bfloat16* __restrict__ oh, __nv_bfloat16* __restrict__ ol)
{
    constexpr int KK = K*K;
    constexpr int NTASK = 28*KK;
    __shared__ __align__(16) float4 s_dw4[KK*16];
    __shared__ __align__(16) short4 s_idx[NTASK];
    __shared__ __align__(16) float4 s_wt [NTASK];

    const int t = threadIdx.x;
    const int half = blockIdx.x, h = blockIdx.y, b = blockIdx.z;
    const int w0 = half * 28;

    const float4* dwT4 = (const float4*)dwT;
    for (int i = t; i < KK*16; i += 448) s_dw4[i] = dwT4[i];

    const float2* ob2 = (const float2*)(off + ((size_t)(b*H_ + h)*W_ + w0)*2*KK);
    for (int i = t; i < NTASK; i += 448) {
        int wl = i / KK, kk = i - wl*KK;
        int ky = kk / K, kx = kk - ky*K;
        float2 d = ob2[i];
        float py = (float)(h + ky*DIL - PAD) + d.x;
        float px = (float)(w0 + wl + kx*DIL - PAD) + d.y;
        float y0f = floorf(py), x0f = floorf(px);
        float wy = py - y0f,    wx = px - x0f;
        int y0 = (int)y0f, x0i = (int)x0f;
        int y1 = y0 + 1,   x1  = x0i + 1;
        float vy0 = (y0  >= 0 && y0  < H_) ? 1.f : 0.f;
        float vy1 = (y1  >= 0 && y1  < H_) ? 1.f : 0.f;
        float vx0 = (x0i >= 0 && x0i < W_) ? 1.f : 0.f;
        float vx1 = (x1  >= 0 && x1  < W_) ? 1.f : 0.f;
        int y0c = min(max(y0, 0), H_-1), y1c = min(max(y1, 0), H_-1);
        int x0c = min(max(x0i,0), W_-1), x1c = min(max(x1, 0), W_-1);
        int r0 = y0c*W_, r1 = y1c*W_;
        s_idx[i] = make_short4((short)(r0+x0c), (short)(r0+x1c),
                               (short)(r1+x0c), (short)(r1+x1c));
        s_wt[i]  = make_float4((1.f-wy)*(1.f-wx)*vy0*vx0,
                               (1.f-wy)*wx      *vy0*vx1,
                               wy      *(1.f-wx)*vy1*vx0,
                               wy      *wx      *vy1*vx1);
    }
    __syncthreads();

    const int c4 = t & 15;
    const int wl = t >> 4;
    const int w  = w0 + wl;
    const float4* imgb = (const float4*)img + (size_t)b*HW_*16;

    float4 a = make_float4(0.f, 0.f, 0.f, 0.f);
    for (int kk = 0; kk < KK; ++kk) {
        short4 id = s_idx[wl*KK + kk];
        float4 wt = s_wt [wl*KK + kk];
        float4 g00 = imgb[(int)id.x*16 + c4];
        float4 g01 = imgb[(int)id.y*16 + c4];
        float4 g10 = imgb[(int)id.z*16 + c4];
        float4 g11 = imgb[(int)id.w*16 + c4];
        float4 dv  = s_dw4[kk*16 + c4];
        float sx_ = g00.x*wt.x + g01.x*wt.y + g10.x*wt.z + g11.x*wt.w;
        float sy_ = g00.y*wt.x + g01.y*wt.y + g10.y*wt.z + g11.y*wt.w;
        float sz_ = g00.z*wt.x + g01.z*wt.y + g10.z*wt.z + g11.z*wt.w;
        float sw_ = g00.w*wt.x + g01.w*wt.y + g10.w*wt.z + g11.w*wt.w;
        a.x += sx_*dv.x; a.y += sy_*dv.y; a.z += sz_*dv.z; a.w += sw_*dv.w;
    }
    const size_t p = (size_t)(b*H_ + h)*W_ + w;
    ((float4*)outp)[p*16 + c4] = a;
    if (SPLIT) {
        __nv_bfloat16 h0,l0,h1,l1,h2,l2,h3,l3;
        split_bf16(a.x, h0, l0); split_bf16(a.y, h1, l1);
        split_bf16(a.z, h2, l2); split_bf16(a.w, h3, l3);
        __nv_bfloat162 hp0; hp0.x = h0; hp0.y = h1;
        __nv_bfloat162 hp1; hp1.x = h2; hp1.y = h3;
        __nv_bfloat162 lp0; lp0.x = l0; lp0.y = l1;
        __nv_bfloat162 lp1; lp1.x = l2; lp1.y = l3;
        __nv_bfloat162* ph = (__nv_bfloat162*)(oh + p*64 + c4*4);
        __nv_bfloat162* pl = (__nv_bfloat162*)(ol + p*64 + c4*4);
        ph[0] = hp0; ph[1] = hp1;
        pl[0] = lp0; pl[1] = lp1;
    }
}

// ---------------------------------------------------------------------------
// Pointwise 1x1 conv + bias, then out = x * attn. Output in NCHW.
// ---------------------------------------------------------------------------
__global__ void __launch_bounds__(224) pw_mul_kernel(
    const float* __restrict__ attn,  // [B,H,W,64]
    const float* __restrict__ pw,    // [64,64]
    const float* __restrict__ pb,    // [64]
    const float* __restrict__ x,     // [B,64,H,W]
    float* __restrict__ out)         // [B,64,H,W]
{
    __shared__ float s_a[W_*64];
    __shared__ float s_w[64*64];
    const int t = threadIdx.x;
    const int h = blockIdx.x, b = blockIdx.y;

    const float* arow = attn + (size_t)(b*H_ + h)*W_*64;
    for (int i = t; i < W_*64; i += 224) s_a[i] = arow[i];
    for (int i = t; i < 64*64; i += 224) s_w[i] = pw[i];
    __syncthreads();

    const int w = t % W_, cg = t / W_;
    float acc[16] = {};
    const float4* sa4 = (const float4*)s_a;
    const float4* sw4 = (const float4*)s_w;
    for (int ciq = 0; ciq < 16; ++ciq) {
        float4 av = sa4[w*16 + ciq];
        #pragma unroll
        for (int j = 0; j < 16; ++j) {
            float4 wv = sw4[(cg*16 + j)*16 + ciq];
            acc[j] += av.x*wv.x + av.y*wv.y + av.z*wv.z + av.w*wv.w;
        }
    }
    #pragma unroll
    for (int j = 0; j < 16; ++j) {
        int co = cg*16 + j;
        size_t idx = ((size_t)(b*64 + co)*H_ + h)*W_ + w;
        out[idx] = x[idx] * (acc[j] + pb[co]);
    }
}

// ---------------------------------------------------------------------------
extern "C" void kernel_launch(void* const* d_in, const int* in_sizes, int n_in,
                              void* d_out, int out_size)
{
    const float* x   = (const float*)d_in[0];
    const float* ow1 = (const float*)d_in[1];
    const float* ob1 = (const float*)d_in[2];
    const float* dw1 = (const float*)d_in[3];
    const float* ow2 = (const float*)d_in[4];
    const float* ob2 = (const float*)d_in[5];
    const float* dw2 = (const float*)d_in[6];
    const float* pww = (const float*)d_in[7];
    const float* pwb = (const float*)d_in[8];
    float* out = (float*)d_out;

    float *xT, *off1, *attn1, *off2, *attn2, *dw1T, *dw2T;
    __nv_bfloat16 *xh, *xl, *a1h, *a1l, *w1h, *w1l, *w2h, *w2l;
    cudaGetSymbolAddress((void**)&xT,    g_xT);
    cudaGetSymbolAddress((void**)&xh,    g_xh);
    cudaGetSymbolAddress((void**)&xl,    g_xl);
    cudaGetSymbolAddress((void**)&off1,  g_off1);
    cudaGetSymbolAddress((void**)&attn1, g_attn1);
    cudaGetSymbolAddress((void**)&a1h,   g_a1h);
    cudaGetSymbolAddress((void**)&a1l,   g_a1l);
    cudaGetSymbolAddress((void**)&off2,  g_off2);
    cudaGetSymbolAddress((void**)&attn2, g_attn2);
    cudaGetSymbolAddress((void**)&w1h,   g_w1h);
    cudaGetSymbolAddress((void**)&w1l,   g_w1l);
    cudaGetSymbolAddress((void**)&w2h,   g_w2h);
    cudaGetSymbolAddress((void**)&w2l,   g_w2l);
    cudaGetSymbolAddress((void**)&dw1T,  g_dw1T);
    cudaGetSymbolAddress((void**)&dw2T,  g_dw2T);

    // dynamic smem: bytes = 4*AE + 8*BE
    const int SMEM1 = 4*(68*72) + 8*(64*72);    // 56448
    const int SMEM2 = 4*(82*72) + 8*(112*72);   // 88128
    cudaFuncSetAttribute(conv_mma_kernel<5,1,2,50,64>,
        cudaFuncAttributeMaxDynamicSharedMemorySize, SMEM1);
    cudaFuncSetAttribute(conv_mma_kernel<7,3,9,98,112>,
        cudaFuncAttributeMaxDynamicSharedMemorySize, SMEM2);

    const int NPREP = 25*64*64 + 49*112*64 + 25*64 + 49*64;
    prep_kernel<<<(NPREP + 255)/256, 256>>>(ow1, ow2, dw1, dw2,
                                            w1h, w1l, w2h, w2l, dw1T, dw2T);
    transpose_kernel<<<dim3(H_, B_), 224>>>(x, xT, xh, xl);

    // stage 1: K=5, dil=1, pad=2, CO=50 (pad 64)
    conv_mma_kernel<5,1,2,50,64><<<dim3(H_, B_), 256, SMEM1>>>(
        xh, xl, w1h, w1l, ob1, off1);
    deform_sample_kernel<5,1,2,true><<<dim3(2, H_, B_), 448>>>(
        xT, off1, dw1T, attn1, a1h, a1l);

    // stage 2: K=7, dil=3, pad=9, CO=98 (pad 112)
    conv_mma_kernel<7,3,9,98,112><<<dim3(H_, B_), 256, SMEM2>>>(
        a1h, a1l, w2h, w2l, ob2, off2);
    deform_sample_kernel<7,3,9,false><<<dim3(2, H_, B_), 448>>>(
        attn1, off2, dw2T, attn2, (__nv_bfloat16*)nullptr, (__nv_bfloat16*)nullptr);

    // pointwise + elementwise multiply
    pw_mul_kernel<<<dim3(H_, B_), 224>>>(attn2, pww, pwb, x, out);
}

// round 8
// speedup vs baseline: 3.9922x; 1.0586x over previous
#include <cuda_runtime.h>
#include <cuda_bf16.h>

#define B_ 4
#define H_ 56
#define W_ 56
#define HW_ (H_*W_)

typedef unsigned int  u32;
typedef unsigned short u16;

// ---------------------------------------------------------------------------
// Scratch (device globals; no allocation allowed)
// ---------------------------------------------------------------------------
__device__ __align__(16) float g_xT   [B_*HW_*64];
__device__ __align__(16) __nv_bfloat16 g_xh [B_*HW_*64];
__device__ __align__(16) __nv_bfloat16 g_xl [B_*HW_*64];
__device__ __align__(16) float g_off1 [B_*HW_*50];
__device__ __align__(16) float g_attn1[B_*HW_*64];
__device__ __align__(16) __nv_bfloat16 g_a1h[B_*HW_*64];
__device__ __align__(16) __nv_bfloat16 g_a1l[B_*HW_*64];
__device__ __align__(16) float g_off2 [B_*HW_*98];
// bf16-split weights: [tap][co(COP)][ci(64)]
__device__ __align__(16) __nv_bfloat16 g_w1h[25*64*64];
__device__ __align__(16) __nv_bfloat16 g_w1l[25*64*64];
__device__ __align__(16) __nv_bfloat16 g_w2h[49*112*64];
__device__ __align__(16) __nv_bfloat16 g_w2l[49*112*64];
__device__ __align__(16) float g_dw1T [25*64];   // [kk][c]
__device__ __align__(16) float g_dw2T [49*64];

// ---------------------------------------------------------------------------
// helpers
// ---------------------------------------------------------------------------
__device__ __forceinline__ void split_bf16(float v, __nv_bfloat16& h, __nv_bfloat16& l){
    h = __float2bfloat16_rn(v);
    l = __float2bfloat16_rn(v - __bfloat162float(h));
}
__device__ __forceinline__ void cp16(u32 dst, const void* src){
    asm volatile("cp.async.cg.shared.global [%0], [%1], 16;" :: "r"(dst), "l"(src));
}
#define CP_COMMIT() asm volatile("cp.async.commit_group;")
#define CP_WAIT0()  asm volatile("cp.async.wait_group 0;")
__device__ __forceinline__ void mma_bf16(float* d, u32 a0,u32 a1,u32 a2,u32 a3,u32 b0,u32 b1){
    asm volatile("mma.sync.aligned.m16n8k16.row.col.f32.bf16.bf16.f32 "
      "{%0,%1,%2,%3}, {%4,%5,%6,%7}, {%8,%9}, {%0,%1,%2,%3};"
      : "+f"(d[0]),"+f"(d[1]),"+f"(d[2]),"+f"(d[3])
      : "r"(a0),"r"(a1),"r"(a2),"r"(a3),"r"(b0),"r"(b1));
}

// ---------------------------------------------------------------------------
// Weight prep: OIHW fp32 -> bf16 hi/lo in [tap][co][ci] + dw transpose
// ---------------------------------------------------------------------------
__global__ void __launch_bounds__(256) prep_kernel(
    const float* __restrict__ ow1, const float* __restrict__ ow2,
    const float* __restrict__ dw1, const float* __restrict__ dw2,
    __nv_bfloat16* __restrict__ w1h, __nv_bfloat16* __restrict__ w1l,
    __nv_bfloat16* __restrict__ w2h, __nv_bfloat16* __restrict__ w2l,
    float* __restrict__ dw1T, float* __restrict__ dw2T)
{
    const int N1 = 25*64*64;
    const int N2 = 49*112*64;
    const int N3 = 25*64;
    const int N4 = 49*64;
    int idx = blockIdx.x*256 + threadIdx.x;
    if (idx < N1) {
        int ci = idx & 63; int r = idx >> 6; int co = r & 63; int tap = r >> 6;
        float v = (co < 50) ? ow1[(size_t)(co*64 + ci)*25 + tap] : 0.f;
        __nv_bfloat16 hh, ll; split_bf16(v, hh, ll);
        w1h[idx] = hh; w1l[idx] = ll;
    } else if (idx < N1 + N2) {
        int i = idx - N1;
        int ci = i & 63; int r = i >> 6; int co = r % 112; int tap = r / 112;
        float v = (co < 98) ? ow2[(size_t)(co*64 + ci)*49 + tap] : 0.f;
        __nv_bfloat16 hh, ll; split_bf16(v, hh, ll);
        w2h[i] = hh; w2l[i] = ll;
    } else if (idx < N1 + N2 + N3) {
        int i = idx - N1 - N2;
        int kk = i >> 6, c = i & 63;
        dw1T[i] = dw1[c*25 + kk];
    } else if (idx < N1 + N2 + N3 + N4) {
        int i = idx - N1 - N2 - N3;
        int kk = i >> 6, c = i & 63;
        dw2T[i] = dw2[c*49 + kk];
    }
}

// ---------------------------------------------------------------------------
// NCHW -> NHWC transpose of x, also emitting bf16 hi/lo copies
// ---------------------------------------------------------------------------
__global__ void __launch_bounds__(224) transpose_kernel(
    const float* __restrict__ x, float* __restrict__ xT,
    __nv_bfloat16* __restrict__ xh, __nv_bfloat16* __restrict__ xl)
{
    int h = blockIdx.x, b = blockIdx.y;
    __shared__ float s[64*W_];
    int t = threadIdx.x;
    for (int i = t; i < 64*W_; i += 224) {
        int c = i / W_, w = i - c*W_;
        s[i] = x[((b*64 + c)*H_ + h)*W_ + w];
    }
    __syncthreads();
    size_t rb = (size_t)(b*H_ + h)*W_*64;
    for (int j = t; j < 32*W_; j += 224) {
        int w = j >> 5, cp = j & 31; int c0 = cp*2;
        float f0 = s[c0*W_ + w], f1 = s[(c0+1)*W_ + w];
        xT[rb + w*64 + c0]   = f0;
        xT[rb + w*64 + c0+1] = f1;
        __nv_bfloat16 h0,l0,h1,l1;
        split_bf16(f0, h0, l0); split_bf16(f1, h1, l1);
        __nv_bfloat162 hp; hp.x = h0; hp.y = h1;
        __nv_bfloat162 lp; lp.x = l0; lp.y = l1;
        *(__nv_bfloat162*)(xh + rb + w*64 + c0) = hp;
        *(__nv_bfloat162*)(xl + rb + w*64 + c0) = lp;
    }
}

// ---------------------------------------------------------------------------
// Offset conv, implicit GEMM on tensor cores, bf16x3 (hi/lo split).
// Block = 2 output rows (h0, h0+1) x half the co range.
// M = 128 (2 rows x 64-pad), 8 warps each own one m16 tile x all COH co.
// A: per-ky extended rows [r][hi/lo][WE][64ci], stride 72 (conflict-free).
// B: per-tap co-half [co][64ci] hi/lo, cp.async double-buffered across taps.
// grid = (28, B, 2)
// ---------------------------------------------------------------------------
template<int K, int DIL, int PAD, int CO, int COP>
__global__ void __launch_bounds__(256) conv_mma_kernel(
    const __nv_bfloat16* __restrict__ Ih, const __nv_bfloat16* __restrict__ Il,
    const __nv_bfloat16* __restrict__ Wh, const __nv_bfloat16* __restrict__ Wl,
    const float* __restrict__ bias, float* __restrict__ out)
{
    constexpr int KK  = K*K;
    constexpr int WE  = (K-1)*DIL + 64;   // extended row (halo + 64 m-pad)
    constexpr int COH = COP/2;
    constexpr int NTn = COH/8;            // n-tiles of 8 per warp
    constexpr int AE  = WE*72;            // u16 elems per (r, hi/lo) plane
    constexpr int BE  = COH*72;           // u16 elems per B plane per buffer

    extern __shared__ __align__(16) u16 sm[];
    u16* sA = sm;                         // [r][hi,lo] : r0h, r0l, r1h, r1l
    u16* sB = sm + 4*AE;                  // [buf][hi BE][lo BE]

    const int t = threadIdx.x, lane = t & 31, wid = t >> 5;
    const int h0 = blockIdx.x*2, b = blockIdx.y;
    const int colbase = blockIdx.z * COH;
    const int mt = wid & 3, r = wid >> 2;
    const int kq = (lane & 3)*2;
    const int mrow = mt*16 + (lane >> 2);    // pixel index 0..63 (pad >=56)

    const u32 smbase = (u32)__cvta_generic_to_shared(sm);
    const u32 dB = smbase + 4*AE*2;          // bytes

    float acc[NTn][4];
    #pragma unroll
    for (int nt = 0; nt < NTn; ++nt) {
        int co0 = colbase + nt*8 + kq;
        float b0 = (co0   < CO) ? bias[co0]   : 0.f;
        float b1 = (co0+1 < CO) ? bias[co0+1] : 0.f;
        acc[nt][0] = b0; acc[nt][1] = b1; acc[nt][2] = b0; acc[nt][3] = b1;
    }

    // prologue: stage B for tap 0 into buffer 0
    for (int c = t; c < COH*8; c += 256) {
        int co = c >> 3, kc = c & 7;
        size_t so = (size_t)(colbase + co)*64 + kc*8;
        u32 off = (u32)(co*72 + kc*8)*2;
        cp16(dB + off,        Wh + so);
        cp16(dB + BE*2 + off, Wl + so);
    }
    CP_COMMIT();

    for (int ky = 0; ky < K; ++ky) {
        const int hp = h0 + ky*DIL - PAD;    // input row for r=0; r=1 -> hp+1
        for (int c = t; c < 2*WE*8; c += 256) {
            int rr = c / (WE*8);
            int j  = (c >> 3) % WE;
            int kc = c & 7;
            int g = j - PAD, hh = hp + rr;
            u32 off = (u32)(rr*2*AE + j*72 + kc*8)*2;
            if ((unsigned)hh < (unsigned)H_ && (unsigned)g < (unsigned)W_) {
                size_t so = ((size_t)(b*H_ + hh)*W_ + g)*64 + kc*8;
                cp16(smbase + off,        Ih + so);
                cp16(smbase + AE*2 + off, Il + so);
            } else {
                float4 z = make_float4(0.f,0.f,0.f,0.f);
                *(float4*)(sA + rr*2*AE + j*72 + kc*8)      = z;
                *(float4*)(sA + rr*2*AE + AE + j*72 + kc*8) = z;
            }
        }
        CP_COMMIT();
        CP_WAIT0();
        __syncthreads();

        for (int kx = 0; kx < K; ++kx) {
            const int tap = ky*K + kx;
            if (tap + 1 < KK) {
                u32 dst = dB + (u32)((tap+1) & 1)*(BE*4);
                const __nv_bfloat16* wh = Wh + (size_t)(tap+1)*COP*64;
                const __nv_bfloat16* wl = Wl + (size_t)(tap+1)*COP*64;
                for (int c = t; c < COH*8; c += 256) {
                    int co = c >> 3, kc = c & 7;
                    size_t so = (size_t)(colbase + co)*64 + kc*8;
                    u32 off = (u32)(co*72 + kc*8)*2;
                    cp16(dst + off,        wh + so);
                    cp16(dst + BE*2 + off, wl + so);
                }
                CP_COMMIT();
            }

            const u16* Bh = sB + (size_t)(tap & 1)*(BE*2);
            const u16* Bl = Bh + BE;
            const u16* Ah = sA + r*2*AE;
            const u16* Al = Ah + AE;
            const int ar0 = (kx*DIL + mrow)*72;
            const int ar1 = ar0 + 8*72;
            #pragma unroll
            for (int ks = 0; ks < 4; ++ks) {
                const int kk = ks*16 + kq;
                u32 ah0 = *(const u32*)(Ah + ar0 + kk);
                u32 ah1 = *(const u32*)(Ah + ar1 + kk);
                u32 ah2 = *(const u32*)(Ah + ar0 + kk + 8);
                u32 ah3 = *(const u32*)(Ah + ar1 + kk + 8);
                u32 al0 = *(const u32*)(Al + ar0 + kk);
                u32 al1 = *(const u32*)(Al + ar1 + kk);
                u32 al2 = *(const u32*)(Al + ar0 + kk + 8);
                u32 al3 = *(const u32*)(Al + ar1 + kk + 8);
                #pragma unroll
                for (int nt = 0; nt < NTn; ++nt) {
                    const int cb = (nt*8 + (lane >> 2))*72;
                    u32 bh0 = *(const u32*)(Bh + cb + kk);
                    u32 bh1 = *(const u32*)(Bh + cb + kk + 8);
                    u32 bl0 = *(const u32*)(Bl + cb + kk);
                    u32 bl1 = *(const u32*)(Bl + cb + kk + 8);
                    mma_bf16(acc[nt], ah0,ah1,ah2,ah3, bh0,bh1);
                    mma_bf16(acc[nt], al0,al1,al2,al3, bh0,bh1);
                    mma_bf16(acc[nt], ah0,ah1,ah2,ah3, bl0,bl1);
                }
            }
            CP_WAIT0();
            __syncthreads();
        }
    }

    // epilogue: pixels mrow / mrow+8 of output row h0+r
    float* po = out + (size_t)(b*H_ + h0 + r)*W_*CO;
    const int px1 = mrow + 8;
    #pragma unroll
    for (int nt = 0; nt < NTn; ++nt) {
        int co0 = colbase + nt*8 + kq;
        if (mrow < 56) {
            if (co0   < CO) po[mrow*CO + co0]   = acc[nt][0];
            if (co0+1 < CO) po[mrow*CO + co0+1] = acc[nt][1];
        }
        if (px1 < 56) {
            if (co0   < CO) po[px1*CO + co0]   = acc[nt][2];
            if (co0+1 < CO) po[px1*CO + co0+1] = acc[nt][3];
        }
    }
}

// ---------------------------------------------------------------------------
// Deformable depthwise sampling, stage 1 (emits fp32 + bf16 hi/lo).
// grid = (2 half-rows, H, B), 448 threads = 28 px x 16 channel-float4.
// ---------------------------------------------------------------------------
template<int K, int DIL, int PAD>
__global__ void __launch_bounds__(448) deform_sample_kernel(
    const float* __restrict__ img, const float* __restrict__ off,
    const float* __restrict__ dwT, float* __restrict__ outp,
    __nv_bfloat16* __restrict__ oh, __nv_bfloat16* __restrict__ ol)
{
    constexpr int KK = K*K;
    constexpr int NTASK = 28*KK;
    __shared__ __align__(16) float4 s_dw4[KK*16];
    __shared__ __align__(16) short4 s_idx[NTASK];
    __shared__ __align__(16) float4 s_wt [NTASK];

    const int t = threadIdx.x;
    const int half = blockIdx.x, h = blockIdx.y, b = blockIdx.z;
    const int w0 = half * 28;

    const float4* dwT4 = (const float4*)dwT;
    for (int i = t; i < KK*16; i += 448) s_dw4[i] = dwT4[i];

    const float2* ob2 = (const float2*)(off + ((size_t)(b*H_ + h)*W_ + w0)*2*KK);
    for (int i = t; i < NTASK; i += 448) {
        int wl = i / KK, kk = i - wl*KK;
        int ky = kk / K, kx = kk - ky*K;
        float2 d = ob2[i];
        float py = (float)(h + ky*DIL - PAD) + d.x;
        float px = (float)(w0 + wl + kx*DIL - PAD) + d.y;
        float y0f = floorf(py), x0f = floorf(px);
        float wy = py - y0f,    wx = px - x0f;
        int y0 = (int)y0f, x0i = (int)x0f;
        int y1 = y0 + 1,   x1  = x0i + 1;
        float vy0 = (y0  >= 0 && y0  < H_) ? 1.f : 0.f;
        float vy1 = (y1  >= 0 && y1  < H_) ? 1.f : 0.f;
        float vx0 = (x0i >= 0 && x0i < W_) ? 1.f : 0.f;
        float vx1 = (x1  >= 0 && x1  < W_) ? 1.f : 0.f;
        int y0c = min(max(y0, 0), H_-1), y1c = min(max(y1, 0), H_-1);
        int x0c = min(max(x0i,0), W_-1), x1c = min(max(x1, 0), W_-1);
        int r0 = y0c*W_, r1 = y1c*W_;
        s_idx[i] = make_short4((short)(r0+x0c), (short)(r0+x1c),
                               (short)(r1+x0c), (short)(r1+x1c));
        s_wt[i]  = make_float4((1.f-wy)*(1.f-wx)*vy0*vx0,
                               (1.f-wy)*wx      *vy0*vx1,
                               wy      *(1.f-wx)*vy1*vx0,
                               wy      *wx      *vy1*vx1);
    }
    __syncthreads();

    const int c4 = t & 15;
    const int wl = t >> 4;
    const int w  = w0 + wl;
    const float4* imgb = (const float4*)img + (size_t)b*HW_*16;

    float4 a = make_float4(0.f, 0.f, 0.f, 0.f);
    for (int kk = 0; kk < KK; ++kk) {
        short4 id = s_idx[wl*KK + kk];
        float4 wt = s_wt [wl*KK + kk];
        float4 g00 = imgb[(int)id.x*16 + c4];
        float4 g01 = imgb[(int)id.y*16 + c4];
        float4 g10 = imgb[(int)id.z*16 + c4];
        float4 g11 = imgb[(int)id.w*16 + c4];
        float4 dv  = s_dw4[kk*16 + c4];
        float sx_ = g00.x*wt.x + g01.x*wt.y + g10.x*wt.z + g11.x*wt.w;
        float sy_ = g00.y*wt.x + g01.y*wt.y + g10.y*wt.z + g11.y*wt.w;
        float sz_ = g00.z*wt.x + g01.z*wt.y + g10.z*wt.z + g11.z*wt.w;
        float sw_ = g00.w*wt.x + g01.w*wt.y + g10.w*wt.z + g11.w*wt.w;
        a.x += sx_*dv.x; a.y += sy_*dv.y; a.z += sz_*dv.z; a.w += sw_*dv.w;
    }
    const size_t p = (size_t)(b*H_ + h)*W_ + w;
    ((float4*)outp)[p*16 + c4] = a;
    __nv_bfloat16 h0,l0,h1,l1,h2,l2,h3,l3;
    split_bf16(a.x, h0, l0); split_bf16(a.y, h1, l1);
    split_bf16(a.z, h2, l2); split_bf16(a.w, h3, l3);
    __nv_bfloat162 hp0; hp0.x = h0; hp0.y = h1;
    __nv_bfloat162 hp1; hp1.x = h2; hp1.y = h3;
    __nv_bfloat162 lp0; lp0.x = l0; lp0.y = l1;
    __nv_bfloat162 lp1; lp1.x = l2; lp1.y = l3;
    __nv_bfloat162* ph = (__nv_bfloat162*)(oh + p*64 + c4*4);
    __nv_bfloat162* pl = (__nv_bfloat162*)(ol + p*64 + c4*4);
    ph[0] = hp0; ph[1] = hp1;
    pl[0] = lp0; pl[1] = lp1;
}

// ---------------------------------------------------------------------------
// Stage-2 deform + fused 1x1 pointwise conv + x-multiply (NCHW output).
// Phase 1: bilinear idx/weights. Phase 2: gather -> s_attn[28px][64c].
// Phase 3: overlay pw weights (transposed [ci][co]) on the dead idx/wt smem,
//          per-thread 4-co dot products, smem transpose, coalesced NCHW write.
// grid = (2 half-rows, H, B), 448 threads. Dynamic smem.
// ---------------------------------------------------------------------------
template<int K, int DIL, int PAD>
__global__ void __launch_bounds__(448) deform_pw_kernel(
    const float* __restrict__ img,   // attn1 NHWC
    const float* __restrict__ off,   // off2 NHWC
    const float* __restrict__ dwT,   // [kk][c]
    const float* __restrict__ pw,    // [64,64] (co,ci)
    const float* __restrict__ pb,    // [64]
    const float* __restrict__ x,     // original x, NCHW
    float* __restrict__ out)         // NCHW
{
    constexpr int KK = K*K;
    constexpr int NTASK = 28*KK;
    extern __shared__ __align__(16) char sraw[];
    float4* s_dw4 = (float4*)sraw;                               // KK*16*16 B
    char*   reg   = sraw + KK*16*16;
    short4* s_idx = (short4*)reg;                                // NTASK*8
    float4* s_wt  = (float4*)(reg + NTASK*8);                    // NTASK*16
    float*  s_attn= (float*) (reg + NTASK*24);                   // 28*64*4
    // overlay (valid after gather):
    float*  s_pwT = (float*)reg;                                 // 64*64*4 = 16384
    float*  s_pb  = (float*)(reg + 16384);                       // 256
    float*  s_out = (float*)(reg + 16640);                       // 28*64*4

    const int t = threadIdx.x;
    const int half = blockIdx.x, h = blockIdx.y, b = blockIdx.z;
    const int w0 = half * 28;

    const float4* dwT4 = (const float4*)dwT;
    for (int i = t; i < KK*16; i += 448) s_dw4[i] = dwT4[i];

    const float2* ob2 = (const float2*)(off + ((size_t)(b*H_ + h)*W_ + w0)*2*KK);
    for (int i = t; i < NTASK; i += 448) {
        int wl = i / KK, kk = i - wl*KK;
        int ky = kk / K, kx = kk - ky*K;
        float2 d = ob2[i];
        float py = (float)(h + ky*DIL - PAD) + d.x;
        float px = (float)(w0 + wl + kx*DIL - PAD) + d.y;
        float y0f = floorf(py), x0f = floorf(px);
        float wy = py - y0f,    wx = px - x0f;
        int y0 = (int)y0f, x0i = (int)x0f;
        int y1 = y0 + 1,   x1  = x0i + 1;
        float vy0 = (y0  >= 0 && y0  < H_) ? 1.f : 0.f;
        float vy1 = (y1  >= 0 && y1  < H_) ? 1.f : 0.f;
        float vx0 = (x0i >= 0 && x0i < W_) ? 1.f : 0.f;
        float vx1 = (x1  >= 0 && x1  < W_) ? 1.f : 0.f;
        int y0c = min(max(y0, 0), H_-1), y1c = min(max(y1, 0), H_-1);
        int x0c = min(max(x0i,0), W_-1), x1c = min(max(x1, 0), W_-1);
        int r0 = y0c*W_, r1 = y1c*W_;
        s_idx[i] = make_short4((short)(r0+x0c), (short)(r0+x1c),
                               (short)(r1+x0c), (short)(r1+x1c));
        s_wt[i]  = make_float4((1.f-wy)*(1.f-wx)*vy0*vx0,
                               (1.f-wy)*wx      *vy0*vx1,
                               wy      *(1.f-wx)*vy1*vx0,
                               wy      *wx      *vy1*vx1);
    }
    __syncthreads();

    const int c4 = t & 15;
    const int wl = t >> 4;
    const float4* imgb = (const float4*)img + (size_t)b*HW_*16;

    float4 a = make_float4(0.f, 0.f, 0.f, 0.f);
    for (int kk = 0; kk < KK; ++kk) {
        short4 id = s_idx[wl*KK + kk];
        float4 wt = s_wt [wl*KK + kk];
        float4 g00 = imgb[(int)id.x*16 + c4];
        float4 g01 = imgb[(int)id.y*16 + c4];
        float4 g10 = imgb[(int)id.z*16 + c4];
        float4 g11 = imgb[(int)id.w*16 + c4];
        float4 dv  = s_dw4[kk*16 + c4];
        float sx_ = g00.x*wt.x + g01.x*wt.y + g10.x*wt.z + g11.x*wt.w;
        float sy_ = g00.y*wt.x + g01.y*wt.y + g10.y*wt.z + g11.y*wt.w;
        float sz_ = g00.z*wt.x + g01.z*wt.y + g10.z*wt.z + g11.z*wt.w;
        float sw_ = g00.w*wt.x + g01.w*wt.y + g10.w*wt.z + g11.w*wt.w;
        a.x += sx_*dv.x; a.y += sy_*dv.y; a.z += sz_*dv.z; a.w += sw_*dv.w;
    }
    ((float4*)s_attn)[wl*16 + c4] = a;
    __syncthreads();                         // gather done; idx/wt now dead

    // overlay load: pw transposed to [ci][co], plus pb
    for (int i = t; i < 4096; i += 448) {
        int co = i >> 6, ci = i & 63;
        s_pwT[ci*64 + co] = pw[i];
    }
    if (t < 64) s_pb[t] = pb[t];
    __syncthreads();

    // pointwise: thread (wl, cg=c4) computes co = c4*4 .. +3 for pixel wl
    const int co0 = c4*4;
    float4 accp = make_float4(0.f, 0.f, 0.f, 0.f);
    const float* ar = s_attn + wl*64;
    #pragma unroll 8
    for (int ci = 0; ci < 64; ++ci) {
        float av = ar[ci];
        float4 wv = ((const float4*)(s_pwT + ci*64))[c4];
        accp.x += av*wv.x; accp.y += av*wv.y;
        accp.z += av*wv.z; accp.w += av*wv.w;
    }
    s_out[(co0  )*28 + wl] = accp.x + s_pb[co0];
    s_out[(co0+1)*28 + wl] = accp.y + s_pb[co0+1];
    s_out[(co0+2)*28 + wl] = accp.z + s_pb[co0+2];
    s_out[(co0+3)*28 + wl] = accp.w + s_pb[co0+3];
    __syncthreads();

    // coalesced NCHW write: out = x * attn
    for (int i = t; i < 64*28; i += 448) {
        int c = i / 28, wl2 = i - c*28;
        size_t idx = ((size_t)(b*64 + c)*H_ + h)*W_ + w0 + wl2;
        out[idx] = x[idx] * s_out[c*28 + wl2];
    }
}

// ---------------------------------------------------------------------------
extern "C" void kernel_launch(void* const* d_in, const int* in_sizes, int n_in,
                              void* d_out, int out_size)
{
    const float* x   = (const float*)d_in[0];
    const float* ow1 = (const float*)d_in[1];
    const float* ob1 = (const float*)d_in[2];
    const float* dw1 = (const float*)d_in[3];
    const float* ow2 = (const float*)d_in[4];
    const float* ob2 = (const float*)d_in[5];
    const float* dw2 = (const float*)d_in[6];
    const float* pww = (const float*)d_in[7];
    const float* pwb = (const float*)d_in[8];
    float* out = (float*)d_out;

    float *xT, *off1, *attn1, *off2, *dw1T, *dw2T;
    __nv_bfloat16 *xh, *xl, *a1h, *a1l, *w1h, *w1l, *w2h, *w2l;
    cudaGetSymbolAddress((void**)&xT,    g_xT);
    cudaGetSymbolAddress((void**)&xh,    g_xh);
    cudaGetSymbolAddress((void**)&xl,    g_xl);
    cudaGetSymbolAddress((void**)&off1,  g_off1);
    cudaGetSymbolAddress((void**)&attn1, g_attn1);
    cudaGetSymbolAddress((void**)&a1h,   g_a1h);
    cudaGetSymbolAddress((void**)&a1l,   g_a1l);
    cudaGetSymbolAddress((void**)&off2,  g_off2);
    cudaGetSymbolAddress((void**)&w1h,   g_w1h);
    cudaGetSymbolAddress((void**)&w1l,   g_w1l);
    cudaGetSymbolAddress((void**)&w2h,   g_w2h);
    cudaGetSymbolAddress((void**)&w2l,   g_w2l);
    cudaGetSymbolAddress((void**)&dw1T,  g_dw1T);
    cudaGetSymbolAddress((void**)&dw2T,  g_dw2T);

    // conv smem: 4*AE*2 + 4*BE*2 bytes
    const int SMEM1 = 4*(68*72)*2 + 4*(32*72)*2;    // 57600
    const int SMEM2 = 4*(82*72)*2 + 4*(56*72)*2;    // 79488
    // deform_pw smem
    const int SMEMD = 49*16*16 + 28*49*24 + 28*64*4; // 52640
    cudaFuncSetAttribute(conv_mma_kernel<5,1,2,50,64>,
        cudaFuncAttributeMaxDynamicSharedMemorySize, SMEM1);
    cudaFuncSetAttribute(conv_mma_kernel<7,3,9,98,112>,
        cudaFuncAttributeMaxDynamicSharedMemorySize, SMEM2);
    cudaFuncSetAttribute(deform_pw_kernel<7,3,9>,
        cudaFuncAttributeMaxDynamicSharedMemorySize, SMEMD);

    const int NPREP = 25*64*64 + 49*112*64 + 25*64 + 49*64;
    prep_kernel<<<(NPREP + 255)/256, 256>>>(ow1, ow2, dw1, dw2,
                                            w1h, w1l, w2h, w2l, dw1T, dw2T);
    transpose_kernel<<<dim3(H_, B_), 224>>>(x, xT, xh, xl);

    // stage 1: K=5, dil=1, pad=2, CO=50 (pad 64)
    conv_mma_kernel<5,1,2,50,64><<<dim3(28, B_, 2), 256, SMEM1>>>(
        xh, xl, w1h, w1l, ob1, off1);
    deform_sample_kernel<5,1,2><<<dim3(2, H_, B_), 448>>>(
        xT, off1, dw1T, attn1, a1h, a1l);

    // stage 2: K=7, dil=3, pad=9, CO=98 (pad 112)
    conv_mma_kernel<7,3,9,98,112><<<dim3(28, B_, 2), 256, SMEM2>>>(
        a1h, a1l, w2h, w2l, ob2, off2);

    // deform2 + pointwise + x-multiply, fused
    deform_pw_kernel<7,3,9><<<dim3(2, H_, B_), 448, SMEMD>>>(
        attn1, off2, dw2T, pww, pwb, x, out);
}

// round 9
// speedup vs baseline: 4.0653x; 1.0183x over previous
#include <cuda_runtime.h>
#include <cuda_bf16.h>

#define B_ 4
#define H_ 56
#define W_ 56
#define HW_ (H_*W_)

typedef unsigned int  u32;
typedef unsigned short u16;

// ---------------------------------------------------------------------------
// Scratch (device globals; no allocation allowed)
// ---------------------------------------------------------------------------
__device__ __align__(16) float g_xT   [B_*HW_*64];
__device__ __align__(16) __nv_bfloat16 g_xh [B_*HW_*64];
__device__ __align__(16) __nv_bfloat16 g_xl [B_*HW_*64];
__device__ __align__(16) float g_off1 [B_*HW_*50];
__device__ __align__(16) float g_attn1[B_*HW_*64];
__device__ __align__(16) __nv_bfloat16 g_a1h[B_*HW_*64];
__device__ __align__(16) __nv_bfloat16 g_a1l[B_*HW_*64];
__device__ __align__(16) float g_off2 [B_*HW_*98];
// bf16-split weights: [tap][co(COP)][ci(64)]
__device__ __align__(16) __nv_bfloat16 g_w1h[25*64*64];
__device__ __align__(16) __nv_bfloat16 g_w1l[25*64*64];
__device__ __align__(16) __nv_bfloat16 g_w2h[49*112*64];
__device__ __align__(16) __nv_bfloat16 g_w2l[49*112*64];
__device__ __align__(16) float g_dw1T [25*64];   // [kk][c]
__device__ __align__(16) float g_dw2T [49*64];

// ---------------------------------------------------------------------------
// helpers
// ---------------------------------------------------------------------------
__device__ __forceinline__ void split_bf16(float v, __nv_bfloat16& h, __nv_bfloat16& l){
    h = __float2bfloat16_rn(v);
    l = __float2bfloat16_rn(v - __bfloat162float(h));
}
__device__ __forceinline__ void cp16(u32 dst, const void* src){
    asm volatile("cp.async.cg.shared.global [%0], [%1], 16;" :: "r"(dst), "l"(src));
}
#define CP_COMMIT() asm volatile("cp.async.commit_group;")
#define CP_WAIT0()  asm volatile("cp.async.wait_group 0;")
__device__ __forceinline__ void mma_bf16(float* d, u32 a0,u32 a1,u32 a2,u32 a3,u32 b0,u32 b1){
    asm volatile("mma.sync.aligned.m16n8k16.row.col.f32.bf16.bf16.f32 "
      "{%0,%1,%2,%3}, {%4,%5,%6,%7}, {%8,%9}, {%0,%1,%2,%3};"
      : "+f"(d[0]),"+f"(d[1]),"+f"(d[2]),"+f"(d[3])
      : "r"(a0),"r"(a1),"r"(a2),"r"(a3),"r"(b0),"r"(b1));
}

// ---------------------------------------------------------------------------
// Weight prep: OIHW fp32 -> bf16 hi/lo in [tap][co][ci] + dw transpose
// ---------------------------------------------------------------------------
__global__ void __launch_bounds__(256) prep_kernel(
    const float* __restrict__ ow1, const float* __restrict__ ow2,
    const float* __restrict__ dw1, const float* __restrict__ dw2,
    __nv_bfloat16* __restrict__ w1h, __nv_bfloat16* __restrict__ w1l,
    __nv_bfloat16* __restrict__ w2h, __nv_bfloat16* __restrict__ w2l,
    float* __restrict__ dw1T, float* __restrict__ dw2T)
{
    const int N1 = 25*64*64;
    const int N2 = 49*112*64;
    const int N3 = 25*64;
    const int N4 = 49*64;
    int idx = blockIdx.x*256 + threadIdx.x;
    if (idx < N1) {
        int ci = idx & 63; int r = idx >> 6; int co = r & 63; int tap = r >> 6;
        float v = (co < 50) ? ow1[(size_t)(co*64 + ci)*25 + tap] : 0.f;
        __nv_bfloat16 hh, ll; split_bf16(v, hh, ll);
        w1h[idx] = hh; w1l[idx] = ll;
    } else if (idx < N1 + N2) {
        int i = idx - N1;
        int ci = i & 63; int r = i >> 6; int co = r % 112; int tap = r / 112;
        float v = (co < 98) ? ow2[(size_t)(co*64 + ci)*49 + tap] : 0.f;
        __nv_bfloat16 hh, ll; split_bf16(v, hh, ll);
        w2h[i] = hh; w2l[i] = ll;
    } else if (idx < N1 + N2 + N3) {
        int i = idx - N1 - N2;
        int kk = i >> 6, c = i & 63;
        dw1T[i] = dw1[c*25 + kk];
    } else if (idx < N1 + N2 + N3 + N4) {
        int i = idx - N1 - N2 - N3;
        int kk = i >> 6, c = i & 63;
        dw2T[i] = dw2[c*49 + kk];
    }
}

// ---------------------------------------------------------------------------
// NCHW -> NHWC transpose of x, also emitting bf16 hi/lo copies
// ---------------------------------------------------------------------------
__global__ void __launch_bounds__(224) transpose_kernel(
    const float* __restrict__ x, float* __restrict__ xT,
    __nv_bfloat16* __restrict__ xh, __nv_bfloat16* __restrict__ xl)
{
    int h = blockIdx.x, b = blockIdx.y;
    __shared__ float s[64*W_];
    int t = threadIdx.x;
    for (int i = t; i < 64*W_; i += 224) {
        int c = i / W_, w = i - c*W_;
        s[i] = x[((b*64 + c)*H_ + h)*W_ + w];
    }
    __syncthreads();
    size_t rb = (size_t)(b*H_ + h)*W_*64;
    for (int j = t; j < 32*W_; j += 224) {
        int w = j >> 5, cp = j & 31; int c0 = cp*2;
        float f0 = s[c0*W_ + w], f1 = s[(c0+1)*W_ + w];
        xT[rb + w*64 + c0]   = f0;
        xT[rb + w*64 + c0+1] = f1;
        __nv_bfloat16 h0,l0,h1,l1;
        split_bf16(f0, h0, l0); split_bf16(f1, h1, l1);
        __nv_bfloat162 hp; hp.x = h0; hp.y = h1;
        __nv_bfloat162 lp; lp.x = l0; lp.y = l1;
        *(__nv_bfloat162*)(xh + rb + w*64 + c0) = hp;
        *(__nv_bfloat162*)(xl + rb + w*64 + c0) = lp;
    }
}

// ---------------------------------------------------------------------------
// Offset conv, implicit GEMM on tensor cores, bf16x3 (hi/lo split).
// Block = 4 output rows (h0..h0+3) x half the co range. M = 256 (4x64-pad).
// 256 threads = 8 warps, each warp owns TWO m16 tiles (B-fragment reuse
// halves the shared-memory crossbar traffic, which is the bottleneck).
// A: per-ky extended rows [rr(4)][hi/lo][WE][64ci], stride 72 (conflict-free).
// B: per-tap co-half [co][64ci] hi/lo, cp.async double-buffered across taps.
// grid = (14, B, 2) = 112 blocks -> exactly one wave on 148 SMs.
// ---------------------------------------------------------------------------
template<int K, int DIL, int PAD, int CO, int COP>
__global__ void __launch_bounds__(256) conv_mma_kernel(
    const __nv_bfloat16* __restrict__ Ih, const __nv_bfloat16* __restrict__ Il,
    const __nv_bfloat16* __restrict__ Wh, const __nv_bfloat16* __restrict__ Wl,
    const float* __restrict__ bias, float* __restrict__ out)
{
    constexpr int KK  = K*K;
    constexpr int WE  = (K-1)*DIL + 64;   // extended row (halo + 64 m-pad)
    constexpr int COH = COP/2;
    constexpr int NTn = COH/8;            // n-tiles of 8 per warp
    constexpr int AE  = WE*72;            // u16 elems per (rr, hi/lo) plane
    constexpr int BE  = COH*72;           // u16 elems per B plane per buffer

    extern __shared__ __align__(16) u16 sm[];
    u16* sA = sm;                         // 8 planes: rr0h, rr0l, ..., rr3h, rr3l
    u16* sB = sm + 8*AE;                  // [buf][hi BE][lo BE]

    const int t = threadIdx.x, lane = t & 31, wid = t >> 5;
    const int h0 = blockIdx.x*4, b = blockIdx.y;
    const int colbase = blockIdx.z * COH;
    const int kq   = (lane & 3)*2;
    const int qrow = lane >> 2;
    const int mt0 = wid*2, mt1 = mt0 + 1;

    const u32 smbase = (u32)__cvta_generic_to_shared(sm);
    const u32 dB = smbase + 8*AE*2;          // bytes

    float acc[2][NTn][4];
    #pragma unroll
    for (int s = 0; s < 2; ++s)
        #pragma unroll
        for (int nt = 0; nt < NTn; ++nt) {
            int co0 = colbase + nt*8 + kq;
            float b0 = (co0   < CO) ? bias[co0]   : 0.f;
            float b1 = (co0+1 < CO) ? bias[co0+1] : 0.f;
            acc[s][nt][0] = b0; acc[s][nt][1] = b1;
            acc[s][nt][2] = b0; acc[s][nt][3] = b1;
        }

    // prologue: stage B for tap 0 into buffer 0
    for (int c = t; c < COH*8; c += 256) {
        int co = c >> 3, kc = c & 7;
        size_t so = (size_t)(colbase + co)*64 + kc*8;
        u32 off = (u32)(co*72 + kc*8)*2;
        cp16(dB + off,        Wh + so);
        cp16(dB + BE*2 + off, Wl + so);
    }
    CP_COMMIT();

    for (int ky = 0; ky < K; ++ky) {
        const int hp = h0 + ky*DIL - PAD;    // input row for rr=0
        for (int c = t; c < 4*WE*8; c += 256) {
            int rr = c / (WE*8);
            int j  = (c >> 3) % WE;
            int kc = c & 7;
            int g = j - PAD, hh = hp + rr;
            u32 off = (u32)(rr*2*AE + j*72 + kc*8)*2;
            if ((unsigned)hh < (unsigned)H_ && (unsigned)g < (unsigned)W_) {
                size_t so = ((size_t)(b*H_ + hh)*W_ + g)*64 + kc*8;
                cp16(smbase + off,        Ih + so);
                cp16(smbase + AE*2 + off, Il + so);
            } else {
                float4 z = make_float4(0.f,0.f,0.f,0.f);
                *(float4*)(sA + rr*2*AE + j*72 + kc*8)      = z;
                *(float4*)(sA + rr*2*AE + AE + j*72 + kc*8) = z;
            }
        }
        CP_COMMIT();
        CP_WAIT0();
        __syncthreads();

        for (int kx = 0; kx < K; ++kx) {
            const int tap = ky*K + kx;
            if (tap + 1 < KK) {
                u32 dst = dB + (u32)((tap+1) & 1)*(BE*4);
                const __nv_bfloat16* wh = Wh + (size_t)(tap+1)*COP*64;
                const __nv_bfloat16* wl = Wl + (size_t)(tap+1)*COP*64;
                for (int c = t; c < COH*8; c += 256) {
                    int co = c >> 3, kc = c & 7;
                    size_t so = (size_t)(colbase + co)*64 + kc*8;
                    u32 off = (u32)(co*72 + kc*8)*2;
                    cp16(dst + off,        wh + so);
                    cp16(dst + BE*2 + off, wl + so);
                }
                CP_COMMIT();
            }

            const u16* Bh  = sB + (size_t)(tap & 1)*(BE*2);
            const u16* Bl  = Bh + BE;
            const u16* Ah0 = sA + (mt0>>2)*2*AE;
            const u16* Al0 = Ah0 + AE;
            const u16* Ah1 = sA + (mt1>>2)*2*AE;
            const u16* Al1 = Ah1 + AE;
            const int a0 = ((mt0 & 3)*16 + qrow + kx*DIL)*72;
            const int a1 = ((mt1 & 3)*16 + qrow + kx*DIL)*72;

            #pragma unroll
            for (int ks = 0; ks < 4; ++ks) {
                const int kk = ks*16 + kq;
                // m-tile 0 fragments (hi, lo)
                u32 xh0 = *(const u32*)(Ah0 + a0 + kk);
                u32 xh1 = *(const u32*)(Ah0 + a0 + 8*72 + kk);
                u32 xh2 = *(const u32*)(Ah0 + a0 + kk + 8);
                u32 xh3 = *(const u32*)(Ah0 + a0 + 8*72 + kk + 8);
                u32 xl0 = *(const u32*)(Al0 + a0 + kk);
                u32 xl1 = *(const u32*)(Al0 + a0 + 8*72 + kk);
                u32 xl2 = *(const u32*)(Al0 + a0 + kk + 8);
                u32 xl3 = *(const u32*)(Al0 + a0 + 8*72 + kk + 8);
                // m-tile 1 fragments (hi, lo)
                u32 yh0 = *(const u32*)(Ah1 + a1 + kk);
                u32 yh1 = *(const u32*)(Ah1 + a1 + 8*72 + kk);
                u32 yh2 = *(const u32*)(Ah1 + a1 + kk + 8);
                u32 yh3 = *(const u32*)(Ah1 + a1 + 8*72 + kk + 8);
                u32 yl0 = *(const u32*)(Al1 + a1 + kk);
                u32 yl1 = *(const u32*)(Al1 + a1 + 8*72 + kk);
                u32 yl2 = *(const u32*)(Al1 + a1 + kk + 8);
                u32 yl3 = *(const u32*)(Al1 + a1 + 8*72 + kk + 8);
                #pragma unroll
                for (int nt = 0; nt < NTn; ++nt) {
                    const int cb = (nt*8 + qrow)*72;
                    u32 bh0 = *(const u32*)(Bh + cb + kk);
                    u32 bh1 = *(const u32*)(Bh + cb + kk + 8);
                    u32 bl0 = *(const u32*)(Bl + cb + kk);
                    u32 bl1 = *(const u32*)(Bl + cb + kk + 8);
                    mma_bf16(acc[0][nt], xh0,xh1,xh2,xh3, bh0,bh1);
                    mma_bf16(acc[0][nt], xl0,xl1,xl2,xl3, bh0,bh1);
                    mma_bf16(acc[0][nt], xh0,xh1,xh2,xh3, bl0,bl1);
                    mma_bf16(acc[1][nt], yh0,yh1,yh2,yh3, bh0,bh1);
                    mma_bf16(acc[1][nt], yl0,yl1,yl2,yl3, bh0,bh1);
                    mma_bf16(acc[1][nt], yh0,yh1,yh2,yh3, bl0,bl1);
                }
            }
            CP_WAIT0();
            __syncthreads();
        }
    }

    // epilogue: two m-tiles per warp
    #pragma unroll
    for (int s = 0; s < 2; ++s) {
        const int mt = wid*2 + s;
        const int row = h0 + (mt >> 2);
        const int px0 = (mt & 3)*16 + qrow;   // always < 56
        const int px1 = px0 + 8;
        float* po = out + (size_t)(b*H_ + row)*W_*CO;
        #pragma unroll
        for (int nt = 0; nt < NTn; ++nt) {
            int co0 = colbase + nt*8 + kq;
            if (co0   < CO) po[px0*CO + co0]   = acc[s][nt][0];
            if (co0+1 < CO) po[px0*CO + co0+1] = acc[s][nt][1];
            if (px1 < 56) {
                if (co0   < CO) po[px1*CO + co0]   = acc[s][nt][2];
                if (co0+1 < CO) po[px1*CO + co0+1] = acc[s][nt][3];
            }
        }
    }
}

// ---------------------------------------------------------------------------
// Deformable depthwise sampling, stage 1 (emits fp32 + bf16 hi/lo).
// grid = (2 half-rows, H, B), 448 threads = 28 px x 16 channel-float4.
// ---------------------------------------------------------------------------
template<int K, int DIL, int PAD>
__global__ void __launch_bounds__(448) deform_sample_kernel(
    const float* __restrict__ img, const float* __restrict__ off,
    const float* __restrict__ dwT, float* __restrict__ outp,
    __nv_bfloat16* __restrict__ oh, __nv_bfloat16* __restrict__ ol)
{
    constexpr int KK = K*K;
    constexpr int NTASK = 28*KK;
    __shared__ __align__(16) float4 s_dw4[KK*16];
    __shared__ __align__(16) short4 s_idx[NTASK];
    __shared__ __align__(16) float4 s_wt [NTASK];

    const int t = threadIdx.x;
    const int half = blockIdx.x, h = blockIdx.y, b = blockIdx.z;
    const int w0 = half * 28;

    const float4* dwT4 = (const float4*)dwT;
    for (int i = t; i < KK*16; i += 448) s_dw4[i] = dwT4[i];

    const float2* ob2 = (const float2*)(off + ((size_t)(b*H_ + h)*W_ + w0)*2*KK);
    for (int i = t; i < NTASK; i += 448) {
        int wl = i / KK, kk = i - wl*KK;
        int ky = kk / K, kx = kk - ky*K;
        float2 d = ob2[i];
        float py = (float)(h + ky*DIL - PAD) + d.x;
        float px = (float)(w0 + wl + kx*DIL - PAD) + d.y;
        float y0f = floorf(py), x0f = floorf(px);
        float wy = py - y0f,    wx = px - x0f;
        int y0 = (int)y0f, x0i = (int)x0f;
        int y1 = y0 + 1,   x1  = x0i + 1;
        float vy0 = (y0  >= 0 && y0  < H_) ? 1.f : 0.f;
        float vy1 = (y1  >= 0 && y1  < H_) ? 1.f : 0.f;
        float vx0 = (x0i >= 0 && x0i < W_) ? 1.f : 0.f;
        float vx1 = (x1  >= 0 && x1  < W_) ? 1.f : 0.f;
        int y0c = min(max(y0, 0), H_-1), y1c = min(max(y1, 0), H_-1);
        int x0c = min(max(x0i,0), W_-1), x1c = min(max(x1, 0), W_-1);
        int r0 = y0c*W_, r1 = y1c*W_;
        s_idx[i] = make_short4((short)(r0+x0c), (short)(r0+x1c),
                               (short)(r1+x0c), (short)(r1+x1c));
        s_wt[i]  = make_float4((1.f-wy)*(1.f-wx)*vy0*vx0,
                               (1.f-wy)*wx      *vy0*vx1,
                               wy      *(1.f-wx)*vy1*vx0,
                               wy      *wx      *vy1*vx1);
    }
    __syncthreads();

    const int c4 = t & 15;
    const int wl = t >> 4;
    const int w  = w0 + wl;
    const float4* imgb = (const float4*)img + (size_t)b*HW_*16;

    float4 a = make_float4(0.f, 0.f, 0.f, 0.f);
    for (int kk = 0; kk < KK; ++kk) {
        short4 id = s_idx[wl*KK + kk];
        float4 wt = s_wt [wl*KK + kk];
        float4 g00 = imgb[(int)id.x*16 + c4];
        float4 g01 = imgb[(int)id.y*16 + c4];
        float4 g10 = imgb[(int)id.z*16 + c4];
        float4 g11 = imgb[(int)id.w*16 + c4];
        float4 dv  = s_dw4[kk*16 + c4];
        float sx_ = g00.x*wt.x + g01.x*wt.y + g10.x*wt.z + g11.x*wt.w;
        float sy_ = g00.y*wt.x + g01.y*wt.y + g10.y*wt.z + g11.y*wt.w;
        float sz_ = g00.z*wt.x + g01.z*wt.y + g10.z*wt.z + g11.z*wt.w;
        float sw_ = g00.w*wt.x + g01.w*wt.y + g10.w*wt.z + g11.w*wt.w;
        a.x += sx_*dv.x; a.y += sy_*dv.y; a.z += sz_*dv.z; a.w += sw_*dv.w;
    }
    const size_t p = (size_t)(b*H_ + h)*W_ + w;
    ((float4*)outp)[p*16 + c4] = a;
    __nv_bfloat16 h0,l0,h1,l1,h2,l2,h3,l3;
    split_bf16(a.x, h0, l0); split_bf16(a.y, h1, l1);
    split_bf16(a.z, h2, l2); split_bf16(a.w, h3, l3);
    __nv_bfloat162 hp0; hp0.x = h0; hp0.y = h1;
    __nv_bfloat162 hp1; hp1.x = h2; hp1.y = h3;
    __nv_bfloat162 lp0; lp0.x = l0; lp0.y = l1;
    __nv_bfloat162 lp1; lp1.x = l2; lp1.y = l3;
    __nv_bfloat162* ph = (__nv_bfloat162*)(oh + p*64 + c4*4);
    __nv_bfloat162* pl = (__nv_bfloat162*)(ol + p*64 + c4*4);
    ph[0] = hp0; ph[1] = hp1;
    pl[0] = lp0; pl[1] = lp1;
}

// ---------------------------------------------------------------------------
// Stage-2 deform + fused 1x1 pointwise conv + x-multiply (NCHW output).
// grid = (2 half-rows, H, B), 448 threads. Dynamic smem.
// ---------------------------------------------------------------------------
template<int K, int DIL, int PAD>
__global__ void __launch_bounds__(448) deform_pw_kernel(
    const float* __restrict__ img,   // attn1 NHWC
    const float* __restrict__ off,   // off2 NHWC
    const float* __restrict__ dwT,   // [kk][c]
    const float* __restrict__ pw,    // [64,64] (co,ci)
    const float* __restrict__ pb,    // [64]
    const float* __restrict__ x,     // original x, NCHW
    float* __restrict__ out)         // NCHW
{
    constexpr int KK = K*K;
    constexpr int NTASK = 28*KK;
    extern __shared__ __align__(16) char sraw[];
    float4* s_dw4 = (float4*)sraw;                               // KK*16*16 B
    char*   reg   = sraw + KK*16*16;
    short4* s_idx = (short4*)reg;                                // NTASK*8
    float4* s_wt  = (float4*)(reg + NTASK*8);                    // NTASK*16
    float*  s_attn= (float*) (reg + NTASK*24);                   // 28*64*4
    // overlay (valid after gather):
    float*  s_pwT = (float*)reg;                                 // 16384
    float*  s_pb  = (float*)(reg + 16384);                       // 256
    float*  s_out = (float*)(reg + 16640);                       // 28*64*4

    const int t = threadIdx.x;
    const int half = blockIdx.x, h = blockIdx.y, b = blockIdx.z;
    const int w0 = half * 28;

    const float4* dwT4 = (const float4*)dwT;
    for (int i = t; i < KK*16; i += 448) s_dw4[i] = dwT4[i];

    const float2* ob2 = (const float2*)(off + ((size_t)(b*H_ + h)*W_ + w0)*2*KK);
    for (int i = t; i < NTASK; i += 448) {
        int wl = i / KK, kk = i - wl*KK;
        int ky = kk / K, kx = kk - ky*K;
        float2 d = ob2[i];
        float py = (float)(h + ky*DIL - PAD) + d.x;
        float px = (float)(w0 + wl + kx*DIL - PAD) + d.y;
        float y0f = floorf(py), x0f = floorf(px);
        float wy = py - y0f,    wx = px - x0f;
        int y0 = (int)y0f, x0i = (int)x0f;
        int y1 = y0 + 1,   x1  = x0i + 1;
        float vy0 = (y0  >= 0 && y0  < H_) ? 1.f : 0.f;
        float vy1 = (y1  >= 0 && y1  < H_) ? 1.f : 0.f;
        float vx0 = (x0i >= 0 && x0i < W_) ? 1.f : 0.f;
        float vx1 = (x1  >= 0 && x1  < W_) ? 1.f : 0.f;
        int y0c = min(max(y0, 0), H_-1), y1c = min(max(y1, 0), H_-1);
        int x0c = min(max(x0i,0), W_-1), x1c = min(max(x1, 0), W_-1);
        int r0 = y0c*W_, r1 = y1c*W_;
        s_idx[i] = make_short4((short)(r0+x0c), (short)(r0+x1c),
                               (short)(r1+x0c), (short)(r1+x1c));
        s_wt[i]  = make_float4((1.f-wy)*(1.f-wx)*vy0*vx0,
                               (1.f-wy)*wx      *vy0*vx1,
                               wy      *(1.f-wx)*vy1*vx0,
                               wy      *wx      *vy1*vx1);
    }
    __syncthreads();

    const int c4 = t & 15;
    const int wl = t >> 4;
    const float4* imgb = (const float4*)img + (size_t)b*HW_*16;

    float4 a = make_float4(0.f, 0.f, 0.f, 0.f);
    for (int kk = 0; kk < KK; ++kk) {
        short4 id = s_idx[wl*KK + kk];
        float4 wt = s_wt [wl*KK + kk];
        float4 g00 = imgb[(int)id.x*16 + c4];
        float4 g01 = imgb[(int)id.y*16 + c4];
        float4 g10 = imgb[(int)id.z*16 + c4];
        float4 g11 = imgb[(int)id.w*16 + c4];
        float4 dv  = s_dw4[kk*16 + c4];
        float sx_ = g00.x*wt.x + g01.x*wt.y + g10.x*wt.z + g11.x*wt.w;
        float sy_ = g00.y*wt.x + g01.y*wt.y + g10.y*wt.z + g11.y*wt.w;
        float sz_ = g00.z*wt.x + g01.z*wt.y + g10.z*wt.z + g11.z*wt.w;
        float sw_ = g00.w*wt.x + g01.w*wt.y + g10.w*wt.z + g11.w*wt.w;
        a.x += sx_*dv.x; a.y += sy_*dv.y; a.z += sz_*dv.z; a.w += sw_*dv.w;
    }
    ((float4*)s_attn)[wl*16 + c4] = a;
    __syncthreads();                         // gather done; idx/wt now dead

    for (int i = t; i < 4096; i += 448) {
        int co = i >> 6, ci = i & 63;
        s_pwT[ci*64 + co] = pw[i];
    }
    if (t < 64) s_pb[t] = pb[t];
    __syncthreads();

    const int co0 = c4*4;
    float4 accp = make_float4(0.f, 0.f, 0.f, 0.f);
    const float* ar = s_attn + wl*64;
    #pragma unroll 8
    for (int ci = 0; ci < 64; ++ci) {
        float av = ar[ci];
        float4 wv = ((const float4*)(s_pwT + ci*64))[c4];
        accp.x += av*wv.x; accp.y += av*wv.y;
        accp.z += av*wv.z; accp.w += av*wv.w;
    }
    s_out[(co0  )*28 + wl] = accp.x + s_pb[co0];
    s_out[(co0+1)*28 + wl] = accp.y + s_pb[co0+1];
    s_out[(co0+2)*28 + wl] = accp.z + s_pb[co0+2];
    s_out[(co0+3)*28 + wl] = accp.w + s_pb[co0+3];
    __syncthreads();

    for (int i = t; i < 64*28; i += 448) {
        int c = i / 28, wl2 = i - c*28;
        size_t idx = ((size_t)(b*64 + c)*H_ + h)*W_ + w0 + wl2;
        out[idx] = x[idx] * s_out[c*28 + wl2];
    }
}

// ---------------------------------------------------------------------------
extern "C" void kernel_launch(void* const* d_in, const int* in_sizes, int n_in,
                              void* d_out, int out_size)
{
    const float* x   = (const float*)d_in[0];
    const float* ow1 = (const float*)d_in[1];
    const float* ob1 = (const float*)d_in[2];
    const float* dw1 = (const float*)d_in[3];
    const float* ow2 = (const float*)d_in[4];
    const float* ob2 = (const float*)d_in[5];
    const float* dw2 = (const float*)d_in[6];
    const float* pww = (const float*)d_in[7];
    const float* pwb = (const float*)d_in[8];
    float* out = (float*)d_out;

    float *xT, *off1, *attn1, *off2, *dw1T, *dw2T;
    __nv_bfloat16 *xh, *xl, *a1h, *a1l, *w1h, *w1l, *w2h, *w2l;
    cudaGetSymbolAddress((void**)&xT,    g_xT);
    cudaGetSymbolAddress((void**)&xh,    g_xh);
    cudaGetSymbolAddress((void**)&xl,    g_xl);
    cudaGetSymbolAddress((void**)&off1,  g_off1);
    cudaGetSymbolAddress((void**)&attn1, g_attn1);
    cudaGetSymbolAddress((void**)&a1h,   g_a1h);
    cudaGetSymbolAddress((void**)&a1l,   g_a1l);
    cudaGetSymbolAddress((void**)&off2,  g_off2);
    cudaGetSymbolAddress((void**)&w1h,   g_w1h);
    cudaGetSymbolAddress((void**)&w1l,   g_w1l);
    cudaGetSymbolAddress((void**)&w2h,   g_w2h);
    cudaGetSymbolAddress((void**)&w2l,   g_w2l);
    cudaGetSymbolAddress((void**)&dw1T,  g_dw1T);
    cudaGetSymbolAddress((void**)&dw2T,  g_dw2T);

    // conv smem: 8 A planes + 2x2 B buffers (bytes)
    const int SMEM1 = 8*(68*72)*2 + 4*(32*72)*2;    // 96768
    const int SMEM2 = 8*(82*72)*2 + 4*(56*72)*2;    // 126720
    const int SMEMD = 49*16*16 + 28*49*24 + 28*64*4; // 52640
    cudaFuncSetAttribute(conv_mma_kernel<5,1,2,50,64>,
        cudaFuncAttributeMaxDynamicSharedMemorySize, SMEM1);
    cudaFuncSetAttribute(conv_mma_kernel<7,3,9,98,112>,
        cudaFuncAttributeMaxDynamicSharedMemorySize, SMEM2);
    cudaFuncSetAttribute(deform_pw_kernel<7,3,9>,
        cudaFuncAttributeMaxDynamicSharedMemorySize, SMEMD);

    const int NPREP = 25*64*64 + 49*112*64 + 25*64 + 49*64;
    prep_kernel<<<(NPREP + 255)/256, 256>>>(ow1, ow2, dw1, dw2,
                                            w1h, w1l, w2h, w2l, dw1T, dw2T);
    transpose_kernel<<<dim3(H_, B_), 224>>>(x, xT, xh, xl);

    // stage 1: K=5, dil=1, pad=2, CO=50 (pad 64)
    conv_mma_kernel<5,1,2,50,64><<<dim3(14, B_, 2), 256, SMEM1>>>(
        xh, xl, w1h, w1l, ob1, off1);
    deform_sample_kernel<5,1,2><<<dim3(2, H_, B_), 448>>>(
        xT, off1, dw1T, attn1, a1h, a1l);

    // stage 2: K=7, dil=3, pad=9, CO=98 (pad 112)
    conv_mma_kernel<7,3,9,98,112><<<dim3(14, B_, 2), 256, SMEM2>>>(
        a1h, a1l, w2h, w2l, ob2, off2);

    // deform2 + pointwise + x-multiply, fused
    deform_pw_kernel<7,3,9><<<dim3(2, H_, B_), 448, SMEMD>>>(
        attn1, off2, dw2T, pww, pwb, x, out);
}

// round 12
// speedup vs baseline: 4.7168x; 1.1603x over previous
#include <cuda_runtime.h>
#include <cuda_fp16.h>

#define B_ 4
#define H_ 56
#define W_ 56
#define HW_ (H_*W_)

typedef unsigned int  u32;
typedef unsigned short u16;
typedef unsigned long long ull;

// ---------------------------------------------------------------------------
// Scratch (device globals; no allocation allowed)
// ---------------------------------------------------------------------------
__device__ __align__(16) float g_xT   [B_*HW_*64];
__device__ __align__(16) __half g_xh [B_*HW_*64];
__device__ __align__(16) __half g_xl [B_*HW_*64];
__device__ __align__(16) float g_off1 [B_*HW_*50];
__device__ __align__(16) float g_attn1[B_*HW_*64];
__device__ __align__(16) __half g_a1h[B_*HW_*64];
__device__ __align__(16) __half g_a1l[B_*HW_*64];
__device__ __align__(16) float g_off2 [B_*HW_*98];
// fp16 weights: [tap][co(COP)][ci(64)]
__device__ __align__(16) __half g_w1h[25*64*64];
__device__ __align__(16) __half g_w2h[49*112*64];
__device__ __align__(16) float g_dw1T [25*64];   // [kk][c]
__device__ __align__(16) float g_dw2T [49*64];

// ---------------------------------------------------------------------------
// helpers
// ---------------------------------------------------------------------------
__device__ __forceinline__ void split_f16(float v, __half& h, __half& l){
    h = __float2half_rn(v);
    l = __float2half_rn(v - __half2float(h));
}
__device__ __forceinline__ void cp16(u32 dst, const void* src){
    asm volatile("cp.async.cg.shared.global [%0], [%1], 16;" :: "r"(dst), "l"(src));
}
#define CP_COMMIT() asm volatile("cp.async.commit_group;")
#define CP_WAIT0()  asm volatile("cp.async.wait_group 0;")
__device__ __forceinline__ void mma_f16(float* d, u32 a0,u32 a1,u32 a2,u32 a3,u32 b0,u32 b1){
    asm volatile("mma.sync.aligned.m16n8k16.row.col.f32.f16.f16.f32 "
      "{%0,%1,%2,%3}, {%4,%5,%6,%7}, {%8,%9}, {%0,%1,%2,%3};"
      : "+f"(d[0]),"+f"(d[1]),"+f"(d[2]),"+f"(d[3])
      : "r"(a0),"r"(a1),"r"(a2),"r"(a3),"r"(b0),"r"(b1));
}

// ---------------------------------------------------------------------------
// Weight prep: OIHW fp32 -> fp16 in [tap][co][ci] + dw transpose
// ---------------------------------------------------------------------------
__global__ void __launch_bounds__(256) prep_kernel(
    const float* __restrict__ ow1, const float* __restrict__ ow2,
    const float* __restrict__ dw1, const float* __restrict__ dw2,
    __half* __restrict__ w1h, __half* __restrict__ w2h,
    float* __restrict__ dw1T, float* __restrict__ dw2T)
{
    const int N1 = 25*64*64;
    const int N2 = 49*112*64;
    const int N3 = 25*64;
    const int N4 = 49*64;
    int idx = blockIdx.x*256 + threadIdx.x;
    if (idx < N1) {
        int ci = idx & 63; int r = idx >> 6; int co = r & 63; int tap = r >> 6;
        float v = (co < 50) ? ow1[(size_t)(co*64 + ci)*25 + tap] : 0.f;
        w1h[idx] = __float2half_rn(v);
    } else if (idx < N1 + N2) {
        int i = idx - N1;
        int ci = i & 63; int r = i >> 6; int co = r % 112; int tap = r / 112;
        float v = (co < 98) ? ow2[(size_t)(co*64 + ci)*49 + tap] : 0.f;
        w2h[i] = __float2half_rn(v);
    } else if (idx < N1 + N2 + N3) {
        int i = idx - N1 - N2;
        int kk = i >> 6, c = i & 63;
        dw1T[i] = dw1[c*25 + kk];
    } else if (idx < N1 + N2 + N3 + N4) {
        int i = idx - N1 - N2 - N3;
        int kk = i >> 6, c = i & 63;
        dw2T[i] = dw2[c*49 + kk];
    }
}

// ---------------------------------------------------------------------------
// NCHW -> NHWC transpose of x, also emitting fp16 hi/lo copies
// ---------------------------------------------------------------------------
__global__ void __launch_bounds__(224) transpose_kernel(
    const float* __restrict__ x, float* __restrict__ xT,
    __half* __restrict__ xh, __half* __restrict__ xl)
{
    int h = blockIdx.x, b = blockIdx.y;
    __shared__ float s[64*W_];
    int t = threadIdx.x;
    for (int i = t; i < 64*W_; i += 224) {
        int c = i / W_, w = i - c*W_;
        s[i] = x[((b*64 + c)*H_ + h)*W_ + w];
    }
    __syncthreads();
    size_t rb = (size_t)(b*H_ + h)*W_*64;
    for (int j = t; j < 32*W_; j += 224) {
        int w = j >> 5, cp = j & 31; int c0 = cp*2;
        float f0 = s[c0*W_ + w], f1 = s[(c0+1)*W_ + w];
        xT[rb + w*64 + c0]   = f0;
        xT[rb + w*64 + c0+1] = f1;
        __half h0,l0,h1,l1;
        split_f16(f0, h0, l0); split_f16(f1, h1, l1);
        __half2 hp; hp.x = h0; hp.y = h1;
        __half2 lp; lp.x = l0; lp.y = l1;
        *(__half2*)(xh + rb + w*64 + c0) = hp;
        *(__half2*)(xl + rb + w*64 + c0) = lp;
    }
}

// ---------------------------------------------------------------------------
// Offset conv, implicit GEMM on tensor cores, fp16x2 (activation hi/lo split;
// weights single fp16 -> dropped term ~2^-11, aggregate ~1e-4 relative).
// Block = 4 output rows x half the co range; M = 256; 8 warps x 2 m-tiles.
// A: per-ky extended rows [rr(4)][hi/lo][WE][64ci], stride 72 (conflict-free).
// B: per-tap co-half [co][64ci] fp16, cp.async double-buffered across taps.
// grid = (14, B, 2) = 112 blocks -> one wave on 148 SMs.
// ---------------------------------------------------------------------------
template<int K, int DIL, int PAD, int CO, int COP>
__global__ void __launch_bounds__(256) conv_mma_kernel(
    const __half* __restrict__ Ih, const __half* __restrict__ Il,
    const __half* __restrict__ Wh,
    const float* __restrict__ bias, float* __restrict__ out)
{
    constexpr int KK  = K*K;
    constexpr int WE  = (K-1)*DIL + 64;   // extended row (halo + 64 m-pad)
    constexpr int COH = COP/2;
    constexpr int NTn = COH/8;            // n-tiles of 8 per warp
    constexpr int AE  = WE*72;            // u16 elems per (rr, hi/lo) plane
    constexpr int BE  = COH*72;           // u16 elems per B buffer

    extern __shared__ __align__(16) u16 sm[];
    u16* sA = sm;                         // 8 planes: rr0h, rr0l, ..., rr3h, rr3l
    u16* sB = sm + 8*AE;                  // [buf] BE each

    const int t = threadIdx.x, lane = t & 31, wid = t >> 5;
    const int h0 = blockIdx.x*4, b = blockIdx.y;
    const int colbase = blockIdx.z * COH;
    const int kq   = (lane & 3)*2;
    const int qrow = lane >> 2;
    const int mt0 = wid*2, mt1 = mt0 + 1;

    const u32 smbase = (u32)__cvta_generic_to_shared(sm);
    const u32 dB = smbase + 8*AE*2;          // bytes

    float acc[2][NTn][4];
    #pragma unroll
    for (int s = 0; s < 2; ++s)
        #pragma unroll
        for (int nt = 0; nt < NTn; ++nt) {
            int co0 = colbase + nt*8 + kq;
            float b0 = (co0   < CO) ? bias[co0]   : 0.f;
            float b1 = (co0+1 < CO) ? bias[co0+1] : 0.f;
            acc[s][nt][0] = b0; acc[s][nt][1] = b1;
            acc[s][nt][2] = b0; acc[s][nt][3] = b1;
        }

    // prologue: stage B for tap 0 into buffer 0
    for (int c = t; c < COH*8; c += 256) {
        int co = c >> 3, kc = c & 7;
        cp16(dB + (u32)(co*72 + kc*8)*2, Wh + (size_t)(colbase + co)*64 + kc*8);
    }
    CP_COMMIT();

    for (int ky = 0; ky < K; ++ky) {
        const int hp = h0 + ky*DIL - PAD;    // input row for rr=0
        for (int c = t; c < 4*WE*8; c += 256) {
            int rr = c / (WE*8);
            int j  = (c >> 3) % WE;
            int kc = c & 7;
            int g = j - PAD, hh = hp + rr;
            u32 off = (u32)(rr*2*AE + j*72 + kc*8)*2;
            if ((unsigned)hh < (unsigned)H_ && (unsigned)g < (unsigned)W_) {
                size_t so = ((size_t)(b*H_ + hh)*W_ + g)*64 + kc*8;
                cp16(smbase + off,        Ih + so);
                cp16(smbase + AE*2 + off, Il + so);
            } else {
                float4 z = make_float4(0.f,0.f,0.f,0.f);
                *(float4*)(sA + rr*2*AE + j*72 + kc*8)      = z;
                *(float4*)(sA + rr*2*AE + AE + j*72 + kc*8) = z;
            }
        }
        CP_COMMIT();
        CP_WAIT0();
        __syncthreads();

        for (int kx = 0; kx < K; ++kx) {
            const int tap = ky*K + kx;
            if (tap + 1 < KK) {
                u32 dst = dB + (u32)((tap+1) & 1)*(BE*2);
                const __half* wh = Wh + (size_t)(tap+1)*COP*64;
                for (int c = t; c < COH*8; c += 256) {
                    int co = c >> 3, kc = c & 7;
                    cp16(dst + (u32)(co*72 + kc*8)*2,
                         wh + (size_t)(colbase + co)*64 + kc*8);
                }
                CP_COMMIT();
            }

            const u16* Bh  = sB + (size_t)(tap & 1)*BE;
            const u16* Ah0 = sA + (mt0>>2)*2*AE;
            const u16* Al0 = Ah0 + AE;
            const u16* Ah1 = sA + (mt1>>2)*2*AE;
            const u16* Al1 = Ah1 + AE;
            const int a0 = ((mt0 & 3)*16 + qrow + kx*DIL)*72;
            const int a1 = ((mt1 & 3)*16 + qrow + kx*DIL)*72;

            #pragma unroll
            for (int ks = 0; ks < 4; ++ks) {
                const int kk = ks*16 + kq;
                u32 xh0 = *(const u32*)(Ah0 + a0 + kk);
                u32 xh1 = *(const u32*)(Ah0 + a0 + 8*72 + kk);
                u32 xh2 = *(const u32*)(Ah0 + a0 + kk + 8);
                u32 xh3 = *(const u32*)(Ah0 + a0 + 8*72 + kk + 8);
                u32 xl0 = *(const u32*)(Al0 + a0 + kk);
                u32 xl1 = *(const u32*)(Al0 + a0 + 8*72 + kk);
                u32 xl2 = *(const u32*)(Al0 + a0 + kk + 8);
                u32 xl3 = *(const u32*)(Al0 + a0 + 8*72 + kk + 8);
                u32 yh0 = *(const u32*)(Ah1 + a1 + kk);
                u32 yh1 = *(const u32*)(Ah1 + a1 + 8*72 + kk);
                u32 yh2 = *(const u32*)(Ah1 + a1 + kk + 8);
                u32 yh3 = *(const u32*)(Ah1 + a1 + 8*72 + kk + 8);
                u32 yl0 = *(const u32*)(Al1 + a1 + kk);
                u32 yl1 = *(const u32*)(Al1 + a1 + 8*72 + kk);
                u32 yl2 = *(const u32*)(Al1 + a1 + kk + 8);
                u32 yl3 = *(const u32*)(Al1 + a1 + 8*72 + kk + 8);
                #pragma unroll
                for (int nt = 0; nt < NTn; ++nt) {
                    const int cb = (nt*8 + qrow)*72;
                    u32 bh0 = *(const u32*)(Bh + cb + kk);
                    u32 bh1 = *(const u32*)(Bh + cb + kk + 8);
                    mma_f16(acc[0][nt], xh0,xh1,xh2,xh3, bh0,bh1);
                    mma_f16(acc[0][nt], xl0,xl1,xl2,xl3, bh0,bh1);
                    mma_f16(acc[1][nt], yh0,yh1,yh2,yh3, bh0,bh1);
                    mma_f16(acc[1][nt], yl0,yl1,yl2,yl3, bh0,bh1);
                }
            }
            CP_WAIT0();
            __syncthreads();
        }
    }

    // epilogue: two m-tiles per warp
    #pragma unroll
    for (int s = 0; s < 2; ++s) {
        const int mt = wid*2 + s;
        const int row = h0 + (mt >> 2);
        const int px0 = (mt & 3)*16 + qrow;   // always < 56
        const int px1 = px0 + 8;
        float* po = out + (size_t)(b*H_ + row)*W_*CO;
        #pragma unroll
        for (int nt = 0; nt < NTn; ++nt) {
            int co0 = colbase + nt*8 + kq;
            if (co0   < CO) po[px0*CO + co0]   = acc[s][nt][0];
            if (co0+1 < CO) po[px0*CO + co0+1] = acc[s][nt][1];
            if (px1 < 56) {
                if (co0   < CO) po[px1*CO + co0]   = acc[s][nt][2];
                if (co0+1 < CO) po[px1*CO + co0+1] = acc[s][nt][3];
            }
        }
    }
}

// ---------------------------------------------------------------------------
// Deformable depthwise sampling, stage 1 (emits fp32 + fp16 hi/lo).
// grid = (2 half-rows, H, B), 448 threads = 28 px x 16 channel-float4.
// ---------------------------------------------------------------------------
template<int K, int DIL, int PAD>
__global__ void __launch_bounds__(448) deform_sample_kernel(
    const float* __restrict__ img, const float* __restrict__ off,
    const float* __restrict__ dwT, float* __restrict__ outp,
    __half* __restrict__ oh, __half* __restrict__ ol)
{
    constexpr int KK = K*K;
    constexpr int NTASK = 28*KK;
    __shared__ __align__(16) float4 s_dw4[KK*16];
    __shared__ __align__(16) short4 s_idx[NTASK];
    __shared__ __align__(16) float4 s_wt [NTASK];

    const int t = threadIdx.x;
    const int half = blockIdx.x, h = blockIdx.y, b = blockIdx.z;
    const int w0 = half * 28;

    const float4* dwT4 = (const float4*)dwT;
    for (int i = t; i < KK*16; i += 448) s_dw4[i] = dwT4[i];

    const float2* ob2 = (const float2*)(off + ((size_t)(b*H_ + h)*W_ + w0)*2*KK);
    for (int i = t; i < NTASK; i += 448) {
        int wl = i / KK, kk = i - wl*KK;
        int ky = kk / K, kx = kk - ky*K;
        float2 d = ob2[i];
        float py = (float)(h + ky*DIL - PAD) + d.x;
        float px = (float)(w0 + wl + kx*DIL - PAD) + d.y;
        float y0f = floorf(py), x0f = floorf(px);
        float wy = py - y0f,    wx = px - x0f;
        int y0 = (int)y0f, x0i = (int)x0f;
        int y1 = y0 + 1,   x1  = x0i + 1;
        float vy0 = (y0  >= 0 && y0  < H_) ? 1.f : 0.f;
        float vy1 = (y1  >= 0 && y1  < H_) ? 1.f : 0.f;
        float vx0 = (x0i >= 0 && x0i < W_) ? 1.f : 0.f;
        float vx1 = (x1  >= 0 && x1  < W_) ? 1.f : 0.f;
        int y0c = min(max(y0, 0), H_-1), y1c = min(max(y1, 0), H_-1);
        int x0c = min(max(x0i,0), W_-1), x1c = min(max(x1, 0), W_-1);
        int r0 = y0c*W_, r1 = y1c*W_;
        s_idx[i] = make_short4((short)(r0+x0c), (short)(r0+x1c),
                               (short)(r1+x0c), (short)(r1+x1c));
        s_wt[i]  = make_float4((1.f-wy)*(1.f-wx)*vy0*vx0,
                               (1.f-wy)*wx      *vy0*vx1,
                               wy      *(1.f-wx)*vy1*vx0,
                               wy      *wx      *vy1*vx1);
    }
    __syncthreads();

    const int c4 = t & 15;
    const int wl = t >> 4;
    const int w  = w0 + wl;
    const float4* imgb = (const float4*)img + (size_t)b*HW_*16;

    float4 a = make_float4(0.f, 0.f, 0.f, 0.f);
    for (int kk = 0; kk < KK; ++kk) {
        short4 id = s_idx[wl*KK + kk];
        float4 wt = s_wt [wl*KK + kk];
        float4 g00 = imgb[(int)id.x*16 + c4];
        float4 g01 = imgb[(int)id.y*16 + c4];
        float4 g10 = imgb[(int)id.z*16 + c4];
        float4 g11 = imgb[(int)id.w*16 + c4];
        float4 dv  = s_dw4[kk*16 + c4];
        float sx_ = g00.x*wt.x + g01.x*wt.y + g10.x*wt.z + g11.x*wt.w;
        float sy_ = g00.y*wt.x + g01.y*wt.y + g10.y*wt.z + g11.y*wt.w;
        float sz_ = g00.z*wt.x + g01.z*wt.y + g10.z*wt.z + g11.z*wt.w;
        float sw_ = g00.w*wt.x + g01.w*wt.y + g10.w*wt.z + g11.w*wt.w;
        a.x += sx_*dv.x; a.y += sy_*dv.y; a.z += sz_*dv.z; a.w += sw_*dv.w;
    }
    const size_t p = (size_t)(b*H_ + h)*W_ + w;
    ((float4*)outp)[p*16 + c4] = a;
    __half h0,l0,h1,l1,h2,l2,h3,l3;
    split_f16(a.x, h0, l0); split_f16(a.y, h1, l1);
    split_f16(a.z, h2, l2); split_f16(a.w, h3, l3);
    __half2 hp0; hp0.x = h0; hp0.y = h1;
    __half2 hp1; hp1.x = h2; hp1.y = h3;
    __half2 lp0; lp0.x = l0; lp0.y = l1;
    __half2 lp1; lp1.x = l2; lp1.y = l3;
    __half2* ph = (__half2*)(oh + p*64 + c4*4);
    __half2* pl = (__half2*)(ol + p*64 + c4*4);
    ph[0] = hp0; ph[1] = hp1;
    pl[0] = lp0; pl[1] = lp1;
}

// ---------------------------------------------------------------------------
// Stage-2 deform + fused 1x1 pointwise conv + x-multiply (NCHW output).
// grid = (2 half-rows, H, B), 448 threads. Dynamic smem.
// ---------------------------------------------------------------------------
template<int K, int DIL, int PAD>
__global__ void __launch_bounds__(448) deform_pw_kernel(
    const float* __restrict__ img,   // attn1 NHWC
    const float* __restrict__ off,   // off2 NHWC
    const float* __restrict__ dwT,   // [kk][c]
    const float* __restrict__ pw,    // [64,64] (co,ci)
    const float* __restrict__ pb,    // [64]
    const float* __restrict__ x,     // original x, NCHW
    float* __restrict__ out)         // NCHW
{
    constexpr int KK = K*K;
    constexpr int NTASK = 28*KK;
    extern __shared__ __align__(16) char sraw[];
    float4* s_dw4 = (float4*)sraw;                               // KK*16*16 B
    char*   reg   = sraw + KK*16*16;
    short4* s_idx = (short4*)reg;                                // NTASK*8
    float4* s_wt  = (float4*)(reg + NTASK*8);                    // NTASK*16
    float*  s_attn= (float*) (reg + NTASK*24);                   // 28*64*4
    // overlay (valid after gather):
    float*  s_pwT = (float*)reg;                                 // 16384
    float*  s_pb  = (float*)(reg + 16384);                       // 256
    float*  s_out = (float*)(reg + 16640);                       // 28*64*4

    const int t = threadIdx.x;
    const int half = blockIdx.x, h = blockIdx.y, b = blockIdx.z;
    const int w0 = half * 28;

    const float4* dwT4 = (const float4*)dwT;
    for (int i = t; i < KK*16; i += 448) s_dw4[i] = dwT4[i];

    const float2* ob2 = (const float2*)(off + ((size_t)(b*H_ + h)*W_ + w0)*2*KK);
    for (int i = t; i < NTASK; i += 448) {
        int wl = i / KK, kk = i - wl*KK;
        int ky = kk / K, kx = kk - ky*K;
        float2 d = ob2[i];
        float py = (float)(h + ky*DIL - PAD) + d.x;
        float px = (float)(w0 + wl + kx*DIL - PAD) + d.y;
        float y0f = floorf(py), x0f = floorf(px);
        float wy = py - y0f,    wx = px - x0f;
        int y0 = (int)y0f, x0i = (int)x0f;
        int y1 = y0 + 1,   x1  = x0i + 1;
        float vy0 = (y0  >= 0 && y0  < H_) ? 1.f : 0.f;
        float vy1 = (y1  >= 0 && y1  < H_) ? 1.f : 0.f;
        float vx0 = (x0i >= 0 && x0i < W_) ? 1.f : 0.f;
        float vx1 = (x1  >= 0 && x1  < W_) ? 1.f : 0.f;
        int y0c = min(max(y0, 0), H_-1), y1c = min(max(y1, 0), H_-1);
        int x0c = min(max(x0i,0), W_-1), x1c = min(max(x1, 0), W_-1);
        int r0 = y0c*W_, r1 = y1c*W_;
        s_idx[i] = make_short4((short)(r0+x0c), (short)(r0+x1c),
                               (short)(r1+x0c), (short)(r1+x1c));
        s_wt[i]  = make_float4((1.f-wy)*(1.f-wx)*vy0*vx0,
                               (1.f-wy)*wx      *vy0*vx1,
                               wy      *(1.f-wx)*vy1*vx0,
                               wy      *wx      *vy1*vx1);
    }
    __syncthreads();

    const int c4 = t & 15;
    const int wl = t >> 4;
    const float4* imgb = (const float4*)img + (size_t)b*HW_*16;

    float4 a = make_float4(0.f, 0.f, 0.f, 0.f);
    for (int kk = 0; kk < KK; ++kk) {
        short4 id = s_idx[wl*KK + kk];
        float4 wt = s_wt [wl*KK + kk];
        float4 g00 = imgb[(int)id.x*16 + c4];
        float4 g01 = imgb[(int)id.y*16 + c4];
        float4 g10 = imgb[(int)id.z*16 + c4];
        float4 g11 = imgb[(int)id.w*16 + c4];
        float4 dv  = s_dw4[kk*16 + c4];
        float sx_ = g00.x*wt.x + g01.x*wt.y + g10.x*wt.z + g11.x*wt.w;
        float sy_ = g00.y*wt.x + g01.y*wt.y + g10.y*wt.z + g11.y*wt.w;
        float sz_ = g00.z*wt.x + g01.z*wt.y + g10.z*wt.z + g11.z*wt.w;
        float sw_ = g00.w*wt.x + g01.w*wt.y + g10.w*wt.z + g11.w*wt.w;
        a.x += sx_*dv.x; a.y += sy_*dv.y; a.z += sz_*dv.z; a.w += sw_*dv.w;
    }
    ((float4*)s_attn)[wl*16 + c4] = a;
    __syncthreads();                         // gather done; idx/wt now dead

    for (int i = t; i < 4096; i += 448) {
        int co = i >> 6, ci = i & 63;
        s_pwT[ci*64 + co] = pw[i];
    }
    if (t < 64) s_pb[t] = pb[t];
    __syncthreads();

    const int co0 = c4*4;
    float4 accp = make_float4(0.f, 0.f, 0.f, 0.f);
    const float* ar = s_attn + wl*64;
    #pragma unroll 8
    for (int ci = 0; ci < 64; ++ci) {
        float av = ar[ci];
        float4 wv = ((const float4*)(s_pwT + ci*64))[c4];
        accp.x += av*wv.x; accp.y += av*wv.y;
        accp.z += av*wv.z; accp.w += av*wv.w;
    }
    s_out[(co0  )*28 + wl] = accp.x + s_pb[co0];
    s_out[(co0+1)*28 + wl] = accp.y + s_pb[co0+1];
    s_out[(co0+2)*28 + wl] = accp.z + s_pb[co0+2];
    s_out[(co0+3)*28 + wl] = accp.w + s_pb[co0+3];
    __syncthreads();

    for (int i = t; i < 64*28; i += 448) {
        int c = i / 28, wl2 = i - c*28;
        size_t idx = ((size_t)(b*64 + c)*H_ + h)*W_ + w0 + wl2;
        out[idx] = x[idx] * s_out[c*28 + wl2];
    }
}

// ---------------------------------------------------------------------------
extern "C" void kernel_launch(void* const* d_in, const int* in_sizes, int n_in,
                              void* d_out, int out_size)
{
    const float* x   = (const float*)d_in[0];
    const float* ow1 = (const float*)d_in[1];
    const float* ob1 = (const float*)d_in[2];
    const float* dw1 = (const float*)d_in[3];
    const float* ow2 = (const float*)d_in[4];
    const float* ob2 = (const float*)d_in[5];
    const float* dw2 = (const float*)d_in[6];
    const float* pww = (const float*)d_in[7];
    const float* pwb = (const float*)d_in[8];
    float* out = (float*)d_out;

    float *xT, *off1, *attn1, *off2, *dw1T, *dw2T;
    __half *xh, *xl, *a1h, *a1l, *w1h, *w2h;
    cudaGetSymbolAddress((void**)&xT,    g_xT);
    cudaGetSymbolAddress((void**)&xh,    g_xh);
    cudaGetSymbolAddress((void**)&xl,    g_xl);
    cudaGetSymbolAddress((void**)&off1,  g_off1);
    cudaGetSymbolAddress((void**)&attn1, g_attn1);
    cudaGetSymbolAddress((void**)&a1h,   g_a1h);
    cudaGetSymbolAddress((void**)&a1l,   g_a1l);
    cudaGetSymbolAddress((void**)&off2,  g_off2);
    cudaGetSymbolAddress((void**)&w1h,   g_w1h);
    cudaGetSymbolAddress((void**)&w2h,   g_w2h);
    cudaGetSymbolAddress((void**)&dw1T,  g_dw1T);
    cudaGetSymbolAddress((void**)&dw2T,  g_dw2T);

    // conv smem: 8 A planes + 2 B buffers (bytes)
    const int SMEM1 = 8*(68*72)*2 + 2*(32*72)*2;    // 87552
    const int SMEM2 = 8*(82*72)*2 + 2*(56*72)*2;    // 110592
    const int SMEMD = 49*16*16 + 28*49*24 + 28*64*4; // 52640
    cudaFuncSetAttribute(conv_mma_kernel<5,1,2,50,64>,
        cudaFuncAttributeMaxDynamicSharedMemorySize, SMEM1);
    cudaFuncSetAttribute(conv_mma_kernel<7,3,9,98,112>,
        cudaFuncAttributeMaxDynamicSharedMemorySize, SMEM2);
    cudaFuncSetAttribute(deform_pw_kernel<7,3,9>,
        cudaFuncAttributeMaxDynamicSharedMemorySize, SMEMD);

    const int NPREP = 25*64*64 + 49*112*64 + 25*64 + 49*64;
    prep_kernel<<<(NPREP + 255)/256, 256>>>(ow1, ow2, dw1, dw2,
                                            w1h, w2h, dw1T, dw2T);
    transpose_kernel<<<dim3(H_, B_), 224>>>(x, xT, xh, xl);

    // stage 1: K=5, dil=1, pad=2, CO=50 (pad 64)
    conv_mma_kernel<5,1,2,50,64><<<dim3(14, B_, 2), 256, SMEM1>>>(
        xh, xl, w1h, ob1, off1);
    deform_sample_kernel<5,1,2><<<dim3(2, H_, B_), 448>>>(
        xT, off1, dw1T, attn1, a1h, a1l);

    // stage 2: K=7, dil=3, pad=9, CO=98 (pad 112)
    conv_mma_kernel<7,3,9,98,112><<<dim3(14, B_, 2), 256, SMEM2>>>(
        a1h, a1l, w2h, ob2, off2);

    // deform2 + pointwise + x-multiply, fused
    deform_pw_kernel<7,3,9><<<dim3(2, H_, B_), 448, SMEMD>>>(
        attn1, off2, dw2T, pww, pwb, x, out);
}

// round 13
// speedup vs baseline: 5.7791x; 1.2252x over previous
#include <cuda_runtime.h>
#include <cuda_fp16.h>

#define B_ 4
#define H_ 56
#define W_ 56
#define HW_ (H_*W_)

typedef unsigned int  u32;
typedef unsigned short u16;

// ---------------------------------------------------------------------------
// Scratch (device globals; no allocation allowed)
// ---------------------------------------------------------------------------
__device__ __align__(16) float g_xT   [B_*HW_*64];
__device__ __align__(16) __half g_xh [B_*HW_*64];
__device__ __align__(16) float g_off1 [B_*HW_*50];
__device__ __align__(16) float g_attn1[B_*HW_*64];
__device__ __align__(16) __half g_a1h[B_*HW_*64];
__device__ __align__(16) float g_off2 [B_*HW_*98];
// fp16 weights: [tap][co(COP)][ci(64)]
__device__ __align__(16) __half g_w1h[25*64*64];
__device__ __align__(16) __half g_w2h[49*112*64];
__device__ __align__(16) float g_dw1T [25*64];   // [kk][c]
__device__ __align__(16) float g_dw2T [49*64];

// ---------------------------------------------------------------------------
// helpers
// ---------------------------------------------------------------------------
__device__ __forceinline__ void cp16(u32 dst, const void* src){
    asm volatile("cp.async.cg.shared.global [%0], [%1], 16;" :: "r"(dst), "l"(src));
}
#define CP_COMMIT() asm volatile("cp.async.commit_group;")
#define CP_WAIT0()  asm volatile("cp.async.wait_group 0;")
__device__ __forceinline__ void mma_f16(float* d, u32 a0,u32 a1,u32 a2,u32 a3,u32 b0,u32 b1){
    asm volatile("mma.sync.aligned.m16n8k16.row.col.f32.f16.f16.f32 "
      "{%0,%1,%2,%3}, {%4,%5,%6,%7}, {%8,%9}, {%0,%1,%2,%3};"
      : "+f"(d[0]),"+f"(d[1]),"+f"(d[2]),"+f"(d[3])
      : "r"(a0),"r"(a1),"r"(a2),"r"(a3),"r"(b0),"r"(b1));
}

// ---------------------------------------------------------------------------
// Weight prep: OIHW fp32 -> fp16 in [tap][co][ci] + dw transpose
// ---------------------------------------------------------------------------
__global__ void __launch_bounds__(256) prep_kernel(
    const float* __restrict__ ow1, const float* __restrict__ ow2,
    const float* __restrict__ dw1, const float* __restrict__ dw2,
    __half* __restrict__ w1h, __half* __restrict__ w2h,
    float* __restrict__ dw1T, float* __restrict__ dw2T)
{
    const int N1 = 25*64*64;
    const int N2 = 49*112*64;
    const int N3 = 25*64;
    const int N4 = 49*64;
    int idx = blockIdx.x*256 + threadIdx.x;
    if (idx < N1) {
        int ci = idx & 63; int r = idx >> 6; int co = r & 63; int tap = r >> 6;
        float v = (co < 50) ? ow1[(size_t)(co*64 + ci)*25 + tap] : 0.f;
        w1h[idx] = __float2half_rn(v);
    } else if (idx < N1 + N2) {
        int i = idx - N1;
        int ci = i & 63; int r = i >> 6; int co = r % 112; int tap = r / 112;
        float v = (co < 98) ? ow2[(size_t)(co*64 + ci)*49 + tap] : 0.f;
        w2h[i] = __float2half_rn(v);
    } else if (idx < N1 + N2 + N3) {
        int i = idx - N1 - N2;
        int kk = i >> 6, c = i & 63;
        dw1T[i] = dw1[c*25 + kk];
    } else if (idx < N1 + N2 + N3 + N4) {
        int i = idx - N1 - N2 - N3;
        int kk = i >> 6, c = i & 63;
        dw2T[i] = dw2[c*49 + kk];
    }
}

// ---------------------------------------------------------------------------
// NCHW -> NHWC transpose of x, also emitting fp16 copy
// ---------------------------------------------------------------------------
__global__ void __launch_bounds__(224) transpose_kernel(
    const float* __restrict__ x, float* __restrict__ xT,
    __half* __restrict__ xh)
{
    int h = blockIdx.x, b = blockIdx.y;
    __shared__ float s[64*W_];
    int t = threadIdx.x;
    for (int i = t; i < 64*W_; i += 224) {
        int c = i / W_, w = i - c*W_;
        s[i] = x[((b*64 + c)*H_ + h)*W_ + w];
    }
    __syncthreads();
    size_t rb = (size_t)(b*H_ + h)*W_*64;
    for (int j = t; j < 32*W_; j += 224) {
        int w = j >> 5, cp = j & 31; int c0 = cp*2;
        float f0 = s[c0*W_ + w], f1 = s[(c0+1)*W_ + w];
        xT[rb + w*64 + c0]   = f0;
        xT[rb + w*64 + c0+1] = f1;
        __half2 hp; hp.x = __float2half_rn(f0); hp.y = __float2half_rn(f1);
        *(__half2*)(xh + rb + w*64 + c0) = hp;
    }
}

// ---------------------------------------------------------------------------
// Offset conv, implicit GEMM on tensor cores, single fp16 pass
// (a and w both fp16-rounded -> aggregate error ~3e-4 relative, gate 1e-3).
// Block = 4 output rows x half the co range; M = 256; 8 warps x 2 m-tiles.
// A: per-ky extended rows [rr(4)][WE][64ci], stride 72 (conflict-free).
// B: per-tap co-half [co][64ci] fp16, cp.async double-buffered across taps.
// grid = (14, B, 2) = 112 blocks -> one wave on 148 SMs.
// ---------------------------------------------------------------------------
template<int K, int DIL, int PAD, int CO, int COP>
__global__ void __launch_bounds__(256) conv_mma_kernel(
    const __half* __restrict__ Ih,
    const __half* __restrict__ Wh,
    const float* __restrict__ bias, float* __restrict__ out)
{
    constexpr int KK  = K*K;
    constexpr int WE  = (K-1)*DIL + 64;   // extended row (halo + 64 m-pad)
    constexpr int COH = COP/2;
    constexpr int NTn = COH/8;            // n-tiles of 8 per warp
    constexpr int AE  = WE*72;            // u16 elems per rr plane
    constexpr int BE  = COH*72;           // u16 elems per B buffer

    extern __shared__ __align__(16) u16 sm[];
    u16* sA = sm;                         // 4 planes: rr0..rr3
    u16* sB = sm + 4*AE;                  // [buf] BE each

    const int t = threadIdx.x, lane = t & 31, wid = t >> 5;
    const int h0 = blockIdx.x*4, b = blockIdx.y;
    const int colbase = blockIdx.z * COH;
    const int kq   = (lane & 3)*2;
    const int qrow = lane >> 2;
    const int mt0 = wid*2, mt1 = mt0 + 1;

    const u32 smbase = (u32)__cvta_generic_to_shared(sm);
    const u32 dB = smbase + 4*AE*2;          // bytes

    float acc[2][NTn][4];
    #pragma unroll
    for (int s = 0; s < 2; ++s)
        #pragma unroll
        for (int nt = 0; nt < NTn; ++nt) {
            int co0 = colbase + nt*8 + kq;
            float b0 = (co0   < CO) ? bias[co0]   : 0.f;
            float b1 = (co0+1 < CO) ? bias[co0+1] : 0.f;
            acc[s][nt][0] = b0; acc[s][nt][1] = b1;
            acc[s][nt][2] = b0; acc[s][nt][3] = b1;
        }

    // prologue: stage B for tap 0 into buffer 0
    for (int c = t; c < COH*8; c += 256) {
        int co = c >> 3, kc = c & 7;
        cp16(dB + (u32)(co*72 + kc*8)*2, Wh + (size_t)(colbase + co)*64 + kc*8);
    }
    CP_COMMIT();

    for (int ky = 0; ky < K; ++ky) {
        const int hp = h0 + ky*DIL - PAD;    // input row for rr=0
        for (int c = t; c < 4*WE*8; c += 256) {
            int rr = c / (WE*8);
            int j  = (c >> 3) % WE;
            int kc = c & 7;
            int g = j - PAD, hh = hp + rr;
            u32 off = (u32)(rr*AE + j*72 + kc*8)*2;
            if ((unsigned)hh < (unsigned)H_ && (unsigned)g < (unsigned)W_) {
                cp16(smbase + off, Ih + ((size_t)(b*H_ + hh)*W_ + g)*64 + kc*8);
            } else {
                float4 z = make_float4(0.f,0.f,0.f,0.f);
                *(float4*)(sA + rr*AE + j*72 + kc*8) = z;
            }
        }
        CP_COMMIT();
        CP_WAIT0();
        __syncthreads();

        for (int kx = 0; kx < K; ++kx) {
            const int tap = ky*K + kx;
            if (tap + 1 < KK) {
                u32 dst = dB + (u32)((tap+1) & 1)*(BE*2);
                const __half* wh = Wh + (size_t)(tap+1)*COP*64;
                for (int c = t; c < COH*8; c += 256) {
                    int co = c >> 3, kc = c & 7;
                    cp16(dst + (u32)(co*72 + kc*8)*2,
                         wh + (size_t)(colbase + co)*64 + kc*8);
                }
                CP_COMMIT();
            }

            const u16* Bh = sB + (size_t)(tap & 1)*BE;
            const u16* A0 = sA + (mt0>>2)*AE;
            const u16* A1 = sA + (mt1>>2)*AE;
            const int a0 = ((mt0 & 3)*16 + qrow + kx*DIL)*72;
            const int a1 = ((mt1 & 3)*16 + qrow + kx*DIL)*72;

            #pragma unroll
            for (int ks = 0; ks < 4; ++ks) {
                const int kk = ks*16 + kq;
                u32 xh0 = *(const u32*)(A0 + a0 + kk);
                u32 xh1 = *(const u32*)(A0 + a0 + 8*72 + kk);
                u32 xh2 = *(const u32*)(A0 + a0 + kk + 8);
                u32 xh3 = *(const u32*)(A0 + a0 + 8*72 + kk + 8);
                u32 yh0 = *(const u32*)(A1 + a1 + kk);
                u32 yh1 = *(const u32*)(A1 + a1 + 8*72 + kk);
                u32 yh2 = *(const u32*)(A1 + a1 + kk + 8);
                u32 yh3 = *(const u32*)(A1 + a1 + 8*72 + kk + 8);
                #pragma unroll
                for (int nt = 0; nt < NTn; ++nt) {
                    const int cb = (nt*8 + qrow)*72;
                    u32 bh0 = *(const u32*)(Bh + cb + kk);
                    u32 bh1 = *(const u32*)(Bh + cb + kk + 8);
                    mma_f16(acc[0][nt], xh0,xh1,xh2,xh3, bh0,bh1);
                    mma_f16(acc[1][nt], yh0,yh1,yh2,yh3, bh0,bh1);
                }
            }
            CP_WAIT0();
            __syncthreads();
        }
    }

    // epilogue: two m-tiles per warp
    #pragma unroll
    for (int s = 0; s < 2; ++s) {
        const int mt = wid*2 + s;
        const int row = h0 + (mt >> 2);
        const int px0 = (mt & 3)*16 + qrow;   // always < 56
        const int px1 = px0 + 8;
        float* po = out + (size_t)(b*H_ + row)*W_*CO;
        #pragma unroll
        for (int nt = 0; nt < NTn; ++nt) {
            int co0 = colbase + nt*8 + kq;
            if (co0   < CO) po[px0*CO + co0]   = acc[s][nt][0];
            if (co0+1 < CO) po[px0*CO + co0+1] = acc[s][nt][1];
            if (px1 < 56) {
                if (co0   < CO) po[px1*CO + co0]   = acc[s][nt][2];
                if (co0+1 < CO) po[px1*CO + co0+1] = acc[s][nt][3];
            }
        }
    }
}

// ---------------------------------------------------------------------------
// Deformable depthwise sampling, stage 1 (emits fp32 + fp16).
// grid = (2 half-rows, H, B), 448 threads = 28 px x 16 channel-float4.
// ---------------------------------------------------------------------------
template<int K, int DIL, int PAD>
__global__ void __launch_bounds__(448) deform_sample_kernel(
    const float* __restrict__ img, const float* __restrict__ off,
    const float* __restrict__ dwT, float* __restrict__ outp,
    __half* __restrict__ oh)
{
    constexpr int KK = K*K;
    constexpr int NTASK = 28*KK;
    __shared__ __align__(16) float4 s_dw4[KK*16];
    __shared__ __align__(16) short4 s_idx[NTASK];
    __shared__ __align__(16) float4 s_wt [NTASK];

    const int t = threadIdx.x;
    const int half = blockIdx.x, h = blockIdx.y, b = blockIdx.z;
    const int w0 = half * 28;

    const float4* dwT4 = (const float4*)dwT;
    for (int i = t; i < KK*16; i += 448) s_dw4[i] = dwT4[i];

    const float2* ob2 = (const float2*)(off + ((size_t)(b*H_ + h)*W_ + w0)*2*KK);
    for (int i = t; i < NTASK; i += 448) {
        int wl = i / KK, kk = i - wl*KK;
        int ky = kk / K, kx = kk - ky*K;
        float2 d = ob2[i];
        float py = (float)(h + ky*DIL - PAD) + d.x;
        float px = (float)(w0 + wl + kx*DIL - PAD) + d.y;
        float y0f = floorf(py), x0f = floorf(px);
        float wy = py - y0f,    wx = px - x0f;
        int y0 = (int)y0f, x0i = (int)x0f;
        int y1 = y0 + 1,   x1  = x0i + 1;
        float vy0 = (y0  >= 0 && y0  < H_) ? 1.f : 0.f;
        float vy1 = (y1  >= 0 && y1  < H_) ? 1.f : 0.f;
        float vx0 = (x0i >= 0 && x0i < W_) ? 1.f : 0.f;
        float vx1 = (x1  >= 0 && x1  < W_) ? 1.f : 0.f;
        int y0c = min(max(y0, 0), H_-1), y1c = min(max(y1, 0), H_-1);
        int x0c = min(max(x0i,0), W_-1), x1c = min(max(x1, 0), W_-1);
        int r0 = y0c*W_, r1 = y1c*W_;
        s_idx[i] = make_short4((short)(r0+x0c), (short)(r0+x1c),
                               (short)(r1+x0c), (short)(r1+x1c));
        s_wt[i]  = make_float4((1.f-wy)*(1.f-wx)*vy0*vx0,
                               (1.f-wy)*wx      *vy0*vx1,
                               wy      *(1.f-wx)*vy1*vx0,
                               wy      *wx      *vy1*vx1);
    }
    __syncthreads();

    const int c4 = t & 15;
    const int wl = t >> 4;
    const int w  = w0 + wl;
    const float4* imgb = (const float4*)img + (size_t)b*HW_*16;

    float4 a = make_float4(0.f, 0.f, 0.f, 0.f);
    for (int kk = 0; kk < KK; ++kk) {
        short4 id = s_idx[wl*KK + kk];
        float4 wt = s_wt [wl*KK + kk];
        float4 g00 = imgb[(int)id.x*16 + c4];
        float4 g01 = imgb[(int)id.y*16 + c4];
        float4 g10 = imgb[(int)id.z*16 + c4];
        float4 g11 = imgb[(int)id.w*16 + c4];
        float4 dv  = s_dw4[kk*16 + c4];
        float sx_ = g00.x*wt.x + g01.x*wt.y + g10.x*wt.z + g11.x*wt.w;
        float sy_ = g00.y*wt.x + g01.y*wt.y + g10.y*wt.z + g11.y*wt.w;
        float sz_ = g00.z*wt.x + g01.z*wt.y + g10.z*wt.z + g11.z*wt.w;
        float sw_ = g00.w*wt.x + g01.w*wt.y + g10.w*wt.z + g11.w*wt.w;
        a.x += sx_*dv.x; a.y += sy_*dv.y; a.z += sz_*dv.z; a.w += sw_*dv.w;
    }
    const size_t p = (size_t)(b*H_ + h)*W_ + w;
    ((float4*)outp)[p*16 + c4] = a;
    __half2 hp0; hp0.x = __float2half_rn(a.x); hp0.y = __float2half_rn(a.y);
    __half2 hp1; hp1.x = __float2half_rn(a.z); hp1.y = __float2half_rn(a.w);
    __half2* ph = (__half2*)(oh + p*64 + c4*4);
    ph[0] = hp0; ph[1] = hp1;
}

// ---------------------------------------------------------------------------
// Stage-2 deform + fused 1x1 pointwise conv + x-multiply (NCHW output).
// grid = (2 half-rows, H, B), 448 threads. Dynamic smem.
// ---------------------------------------------------------------------------
template<int K, int DIL, int PAD>
__global__ void __launch_bounds__(448) deform_pw_kernel(
    const float* __restrict__ img,   // attn1 NHWC
    const float* __restrict__ off,   // off2 NHWC
    const float* __restrict__ dwT,   // [kk][c]
    const float* __restrict__ pw,    // [64,64] (co,ci)
    const float* __restrict__ pb,    // [64]
    const float* __restrict__ x,     // original x, NCHW
    float* __restrict__ out)         // NCHW
{
    constexpr int KK = K*K;
    constexpr int NTASK = 28*KK;
    extern __shared__ __align__(16) char sraw[];
    float4* s_dw4 = (float4*)sraw;                               // KK*16*16 B
    char*   reg   = sraw + KK*16*16;
    short4* s_idx = (short4*)reg;                                // NTASK*8
    float4* s_wt  = (float4*)(reg + NTASK*8);                    // NTASK*16
    float*  s_attn= (float*) (reg + NTASK*24);                   // 28*64*4
    // overlay (valid after gather):
    float*  s_pwT = (float*)reg;                                 // 16384
    float*  s_pb  = (float*)(reg + 16384);                       // 256
    float*  s_out = (float*)(reg + 16640);                       // 28*64*4

    const int t = threadIdx.x;
    const int half = blockIdx.x, h = blockIdx.y, b = blockIdx.z;
    const int w0 = half * 28;

    const float4* dwT4 = (const float4*)dwT;
    for (int i = t; i < KK*16; i += 448) s_dw4[i] = dwT4[i];

    const float2* ob2 = (const float2*)(off + ((size_t)(b*H_ + h)*W_ + w0)*2*KK);
    for (int i = t; i < NTASK; i += 448) {
        int wl = i / KK, kk = i - wl*KK;
        int ky = kk / K, kx = kk - ky*K;
        float2 d = ob2[i];
        float py = (float)(h + ky*DIL - PAD) + d.x;
        float px = (float)(w0 + wl + kx*DIL - PAD) + d.y;
        float y0f = floorf(py), x0f = floorf(px);
        float wy = py - y0f,    wx = px - x0f;
        int y0 = (int)y0f, x0i = (int)x0f;
        int y1 = y0 + 1,   x1  = x0i + 1;
        float vy0 = (y0  >= 0 && y0  < H_) ? 1.f : 0.f;
        float vy1 = (y1  >= 0 && y1  < H_) ? 1.f : 0.f;
        float vx0 = (x0i >= 0 && x0i < W_) ? 1.f : 0.f;
        float vx1 = (x1  >= 0 && x1  < W_) ? 1.f : 0.f;
        int y0c = min(max(y0, 0), H_-1), y1c = min(max(y1, 0), H_-1);
        int x0c = min(max(x0i,0), W_-1), x1c = min(max(x1, 0), W_-1);
        int r0 = y0c*W_, r1 = y1c*W_;
        s_idx[i] = make_short4((short)(r0+x0c), (short)(r0+x1c),
                               (short)(r1+x0c), (short)(r1+x1c));
        s_wt[i]  = make_float4((1.f-wy)*(1.f-wx)*vy0*vx0,
                               (1.f-wy)*wx      *vy0*vx1,
                               wy      *(1.f-wx)*vy1*vx0,
                               wy      *wx      *vy1*vx1);
    }
    __syncthreads();

    const int c4 = t & 15;
    const int wl = t >> 4;
    const float4* imgb = (const float4*)img + (size_t)b*HW_*16;

    float4 a = make_float4(0.f, 0.f, 0.f, 0.f);
    for (int kk = 0; kk < KK; ++kk) {
        short4 id = s_idx[wl*KK + kk];
        float4 wt = s_wt [wl*KK + kk];
        float4 g00 = imgb[(int)id.x*16 + c4];
        float4 g01 = imgb[(int)id.y*16 + c4];
        float4 g10 = imgb[(int)id.z*16 + c4];
        float4 g11 = imgb[(int)id.w*16 + c4];
        float4 dv  = s_dw4[kk*16 + c4];
        float sx_ = g00.x*wt.x + g01.x*wt.y + g10.x*wt.z + g11.x*wt.w;
        float sy_ = g00.y*wt.x + g01.y*wt.y + g10.y*wt.z + g11.y*wt.w;
        float sz_ = g00.z*wt.x + g01.z*wt.y + g10.z*wt.z + g11.z*wt.w;
        float sw_ = g00.w*wt.x + g01.w*wt.y + g10.w*wt.z + g11.w*wt.w;
        a.x += sx_*dv.x; a.y += sy_*dv.y; a.z += sz_*dv.z; a.w += sw_*dv.w;
    }
    ((float4*)s_attn)[wl*16 + c4] = a;
    __syncthreads();                         // gather done; idx/wt now dead

    for (int i = t; i < 4096; i += 448) {
        int co = i >> 6, ci = i & 63;
        s_pwT[ci*64 + co] = pw[i];
    }
    if (t < 64) s_pb[t] = pb[t];
    __syncthreads();

    const int co0 = c4*4;
    float4 accp = make_float4(0.f, 0.f, 0.f, 0.f);
    const float* ar = s_attn + wl*64;
    #pragma unroll 8
    for (int ci = 0; ci < 64; ++ci) {
        float av = ar[ci];
        float4 wv = ((const float4*)(s_pwT + ci*64))[c4];
        accp.x += av*wv.x; accp.y += av*wv.y;
        accp.z += av*wv.z; accp.w += av*wv.w;
    }
    s_out[(co0  )*28 + wl] = accp.x + s_pb[co0];
    s_out[(co0+1)*28 + wl] = accp.y + s_pb[co0+1];
    s_out[(co0+2)*28 + wl] = accp.z + s_pb[co0+2];
    s_out[(co0+3)*28 + wl] = accp.w + s_pb[co0+3];
    __syncthreads();

    for (int i = t; i < 64*28; i += 448) {
        int c = i / 28, wl2 = i - c*28;
        size_t idx = ((size_t)(b*64 + c)*H_ + h)*W_ + w0 + wl2;
        out[idx] = x[idx] * s_out[c*28 + wl2];
    }
}

// ---------------------------------------------------------------------------
extern "C" void kernel_launch(void* const* d_in, const int* in_sizes, int n_in,
                              void* d_out, int out_size)
{
    const float* x   = (const float*)d_in[0];
    const float* ow1 = (const float*)d_in[1];
    const float* ob1 = (const float*)d_in[2];
    const float* dw1 = (const float*)d_in[3];
    const float* ow2 = (const float*)d_in[4];
    const float* ob2 = (const float*)d_in[5];
    const float* dw2 = (const float*)d_in[6];
    const float* pww = (const float*)d_in[7];
    const float* pwb = (const float*)d_in[8];
    float* out = (float*)d_out;

    float *xT, *off1, *attn1, *off2, *dw1T, *dw2T;
    __half *xh, *a1h, *w1h, *w2h;
    cudaGetSymbolAddress((void**)&xT,    g_xT);
    cudaGetSymbolAddress((void**)&xh,    g_xh);
    cudaGetSymbolAddress((void**)&off1,  g_off1);
    cudaGetSymbolAddress((void**)&attn1, g_attn1);
    cudaGetSymbolAddress((void**)&a1h,   g_a1h);
    cudaGetSymbolAddress((void**)&off2,  g_off2);
    cudaGetSymbolAddress((void**)&w1h,   g_w1h);
    cudaGetSymbolAddress((void**)&w2h,   g_w2h);
    cudaGetSymbolAddress((void**)&dw1T,  g_dw1T);
    cudaGetSymbolAddress((void**)&dw2T,  g_dw2T);

    // conv smem: 4 A planes + 2 B buffers (bytes)
    const int SMEM1 = 4*(68*72)*2 + 2*(32*72)*2;    // 48384
    const int SMEM2 = 4*(82*72)*2 + 2*(56*72)*2;    // 63360
    const int SMEMD = 49*16*16 + 28*49*24 + 28*64*4; // 52640
    cudaFuncSetAttribute(conv_mma_kernel<5,1,2,50,64>,
        cudaFuncAttributeMaxDynamicSharedMemorySize, SMEM1);
    cudaFuncSetAttribute(conv_mma_kernel<7,3,9,98,112>,
        cudaFuncAttributeMaxDynamicSharedMemorySize, SMEM2);
    cudaFuncSetAttribute(deform_pw_kernel<7,3,9>,
        cudaFuncAttributeMaxDynamicSharedMemorySize, SMEMD);

    const int NPREP = 25*64*64 + 49*112*64 + 25*64 + 49*64;
    prep_kernel<<<(NPREP + 255)/256, 256>>>(ow1, ow2, dw1, dw2,
                                            w1h, w2h, dw1T, dw2T);
    transpose_kernel<<<dim3(H_, B_), 224>>>(x, xT, xh);

    // stage 1: K=5, dil=1, pad=2, CO=50 (pad 64)
    conv_mma_kernel<5,1,2,50,64><<<dim3(14, B_, 2), 256, SMEM1>>>(
        xh, w1h, ob1, off1);
    deform_sample_kernel<5,1,2><<<dim3(2, H_, B_), 448>>>(
        xT, off1, dw1T, attn1, a1h);

    // stage 2: K=7, dil=3, pad=9, CO=98 (pad 112)
    conv_mma_kernel<7,3,9,98,112><<<dim3(14, B_, 2), 256, SMEM2>>>(
        a1h, w2h, ob2, off2);

    // deform2 + pointwise + x-multiply, fused
    deform_pw_kernel<7,3,9><<<dim3(2, H_, B_), 448, SMEMD>>>(
        attn1, off2, dw2T, pww, pwb, x, out);
}

// round 14
// speedup vs baseline: 5.8592x; 1.0139x over previous
#include <cuda_runtime.h>
#include <cuda_fp16.h>

#define B_ 4
#define H_ 56
#define W_ 56
#define HW_ (H_*W_)

typedef unsigned int  u32;
typedef unsigned short u16;

// ---------------------------------------------------------------------------
// Scratch (device globals; no allocation allowed)
// ---------------------------------------------------------------------------
__device__ __align__(16) float g_xT   [B_*HW_*64];
__device__ __align__(16) __half g_xh [B_*HW_*64];
__device__ __align__(16) float g_off1 [B_*HW_*50];
__device__ __align__(16) float g_attn1[B_*HW_*64];
__device__ __align__(16) __half g_a1h[B_*HW_*64];
__device__ __align__(16) float g_off2 [B_*HW_*98];
// fp16 weights: [tap][co(COP)][ci(64)]
__device__ __align__(16) __half g_w1h[25*64*64];
__device__ __align__(16) __half g_w2h[49*112*64];
__device__ __align__(16) float g_dw1T [25*64];   // [kk][c]
__device__ __align__(16) float g_dw2T [49*64];

// ---------------------------------------------------------------------------
// helpers
// ---------------------------------------------------------------------------
__device__ __forceinline__ void cp16(u32 dst, const void* src){
    asm volatile("cp.async.cg.shared.global [%0], [%1], 16;" :: "r"(dst), "l"(src));
}
#define CP_COMMIT() asm volatile("cp.async.commit_group;")
#define CP_WAIT0()  asm volatile("cp.async.wait_group 0;")
__device__ __forceinline__ void mma_f16(float* d, u32 a0,u32 a1,u32 a2,u32 a3,u32 b0,u32 b1){
    asm volatile("mma.sync.aligned.m16n8k16.row.col.f32.f16.f16.f32 "
      "{%0,%1,%2,%3}, {%4,%5,%6,%7}, {%8,%9}, {%0,%1,%2,%3};"
      : "+f"(d[0]),"+f"(d[1]),"+f"(d[2]),"+f"(d[3])
      : "r"(a0),"r"(a1),"r"(a2),"r"(a3),"r"(b0),"r"(b1));
}

// ---------------------------------------------------------------------------
// Fused prelude: transpose blocks [0, 224) + weight-prep blocks [224, ...)
// Runs as ONE kernel so both fill the chip concurrently.
// ---------------------------------------------------------------------------
#define NPREP_ (25*64*64 + 49*112*64 + 25*64 + 49*64)
#define PREP_BLOCKS ((NPREP_ + 255)/256)

__global__ void __launch_bounds__(256) prelude_kernel(
    const float* __restrict__ x, float* __restrict__ xT, __half* __restrict__ xh,
    const float* __restrict__ ow1, const float* __restrict__ ow2,
    const float* __restrict__ dw1, const float* __restrict__ dw2,
    __half* __restrict__ w1h, __half* __restrict__ w2h,
    float* __restrict__ dw1T, float* __restrict__ dw2T)
{
    const int t = threadIdx.x;
    if (blockIdx.x < 224) {
        // transpose: NCHW -> NHWC + fp16 copy
        int h = blockIdx.x % H_, b = blockIdx.x / H_;
        __shared__ float s[64*W_];
        for (int i = t; i < 64*W_; i += 256) {
            int c = i / W_, w = i - c*W_;
            s[i] = x[((b*64 + c)*H_ + h)*W_ + w];
        }
        __syncthreads();
        size_t rb = (size_t)(b*H_ + h)*W_*64;
        for (int j = t; j < 32*W_; j += 256) {
            int w = j >> 5, cp = j & 31; int c0 = cp*2;
            float f0 = s[c0*W_ + w], f1 = s[(c0+1)*W_ + w];
            xT[rb + w*64 + c0]   = f0;
            xT[rb + w*64 + c0+1] = f1;
            __half2 hp; hp.x = __float2half_rn(f0); hp.y = __float2half_rn(f1);
            *(__half2*)(xh + rb + w*64 + c0) = hp;
        }
        return;
    }
    // weight prep
    const int N1 = 25*64*64;
    const int N2 = 49*112*64;
    const int N3 = 25*64;
    const int N4 = 49*64;
    int idx = (blockIdx.x - 224)*256 + t;
    if (idx < N1) {
        int ci = idx & 63; int r = idx >> 6; int co = r & 63; int tap = r >> 6;
        float v = (co < 50) ? ow1[(size_t)(co*64 + ci)*25 + tap] : 0.f;
        w1h[idx] = __float2half_rn(v);
    } else if (idx < N1 + N2) {
        int i = idx - N1;
        int ci = i & 63; int r = i >> 6; int co = r % 112; int tap = r / 112;
        float v = (co < 98) ? ow2[(size_t)(co*64 + ci)*49 + tap] : 0.f;
        w2h[i] = __float2half_rn(v);
    } else if (idx < N1 + N2 + N3) {
        int i = idx - N1 - N2;
        int kk = i >> 6, c = i & 63;
        dw1T[i] = dw1[c*25 + kk];
    } else if (idx < N1 + N2 + N3 + N4) {
        int i = idx - N1 - N2 - N3;
        int kk = i >> 6, c = i & 63;
        dw2T[i] = dw2[c*49 + kk];
    }
}

// ---------------------------------------------------------------------------
// Offset conv, implicit GEMM on tensor cores, single fp16 pass.
// Block = 4 output rows x half the co range; M = 256; 8 warps x 2 m-tiles.
// grid = (14, B, 2) = 112 blocks -> one wave on 148 SMs.
// ---------------------------------------------------------------------------
template<int K, int DIL, int PAD, int CO, int COP>
__global__ void __launch_bounds__(256) conv_mma_kernel(
    const __half* __restrict__ Ih,
    const __half* __restrict__ Wh,
    const float* __restrict__ bias, float* __restrict__ out)
{
    constexpr int KK  = K*K;
    constexpr int WE  = (K-1)*DIL + 64;   // extended row (halo + 64 m-pad)
    constexpr int COH = COP/2;
    constexpr int NTn = COH/8;            // n-tiles of 8 per warp
    constexpr int AE  = WE*72;            // u16 elems per rr plane
    constexpr int BE  = COH*72;           // u16 elems per B buffer

    extern __shared__ __align__(16) u16 sm[];
    u16* sA = sm;                         // 4 planes: rr0..rr3
    u16* sB = sm + 4*AE;                  // [buf] BE each

    const int t = threadIdx.x, lane = t & 31, wid = t >> 5;
    const int h0 = blockIdx.x*4, b = blockIdx.y;
    const int colbase = blockIdx.z * COH;
    const int kq   = (lane & 3)*2;
    const int qrow = lane >> 2;
    const int mt0 = wid*2, mt1 = mt0 + 1;

    const u32 smbase = (u32)__cvta_generic_to_shared(sm);
    const u32 dB = smbase + 4*AE*2;          // bytes

    float acc[2][NTn][4];
    #pragma unroll
    for (int s = 0; s < 2; ++s)
        #pragma unroll
        for (int nt = 0; nt < NTn; ++nt) {
            int co0 = colbase + nt*8 + kq;
            float b0 = (co0   < CO) ? bias[co0]   : 0.f;
            float b1 = (co0+1 < CO) ? bias[co0+1] : 0.f;
            acc[s][nt][0] = b0; acc[s][nt][1] = b1;
            acc[s][nt][2] = b0; acc[s][nt][3] = b1;
        }

    // prologue: stage B for tap 0 into buffer 0
    for (int c = t; c < COH*8; c += 256) {
        int co = c >> 3, kc = c & 7;
        cp16(dB + (u32)(co*72 + kc*8)*2, Wh + (size_t)(colbase + co)*64 + kc*8);
    }
    CP_COMMIT();

    for (int ky = 0; ky < K; ++ky) {
        const int hp = h0 + ky*DIL - PAD;    // input row for rr=0
        for (int c = t; c < 4*WE*8; c += 256) {
            int rr = c / (WE*8);
            int j  = (c >> 3) % WE;
            int kc = c & 7;
            int g = j - PAD, hh = hp + rr;
            u32 off = (u32)(rr*AE + j*72 + kc*8)*2;
            if ((unsigned)hh < (unsigned)H_ && (unsigned)g < (unsigned)W_) {
                cp16(smbase + off, Ih + ((size_t)(b*H_ + hh)*W_ + g)*64 + kc*8);
            } else {
                float4 z = make_float4(0.f,0.f,0.f,0.f);
                *(float4*)(sA + rr*AE + j*72 + kc*8) = z;
            }
        }
        CP_COMMIT();
        CP_WAIT0();
        __syncthreads();

        for (int kx = 0; kx < K; ++kx) {
            const int tap = ky*K + kx;
            if (tap + 1 < KK) {
                u32 dst = dB + (u32)((tap+1) & 1)*(BE*2);
                const __half* wh = Wh + (size_t)(tap+1)*COP*64;
                for (int c = t; c < COH*8; c += 256) {
                    int co = c >> 3, kc = c & 7;
                    cp16(dst + (u32)(co*72 + kc*8)*2,
                         wh + (size_t)(colbase + co)*64 + kc*8);
                }
                CP_COMMIT();
            }

            const u16* Bh = sB + (size_t)(tap & 1)*BE;
            const u16* A0 = sA + (mt0>>2)*AE;
            const u16* A1 = sA + (mt1>>2)*AE;
            const int a0 = ((mt0 & 3)*16 + qrow + kx*DIL)*72;
            const int a1 = ((mt1 & 3)*16 + qrow + kx*DIL)*72;

            #pragma unroll
            for (int ks = 0; ks < 4; ++ks) {
                const int kk = ks*16 + kq;
                u32 xh0 = *(const u32*)(A0 + a0 + kk);
                u32 xh1 = *(const u32*)(A0 + a0 + 8*72 + kk);
                u32 xh2 = *(const u32*)(A0 + a0 + kk + 8);
                u32 xh3 = *(const u32*)(A0 + a0 + 8*72 + kk + 8);
                u32 yh0 = *(const u32*)(A1 + a1 + kk);
                u32 yh1 = *(const u32*)(A1 + a1 + 8*72 + kk);
                u32 yh2 = *(const u32*)(A1 + a1 + kk + 8);
                u32 yh3 = *(const u32*)(A1 + a1 + 8*72 + kk + 8);
                #pragma unroll
                for (int nt = 0; nt < NTn; ++nt) {
                    const int cb = (nt*8 + qrow)*72;
                    u32 bh0 = *(const u32*)(Bh + cb + kk);
                    u32 bh1 = *(const u32*)(Bh + cb + kk + 8);
                    mma_f16(acc[0][nt], xh0,xh1,xh2,xh3, bh0,bh1);
                    mma_f16(acc[1][nt], yh0,yh1,yh2,yh3, bh0,bh1);
                }
            }
            CP_WAIT0();
            __syncthreads();
        }
    }

    // epilogue: two m-tiles per warp
    #pragma unroll
    for (int s = 0; s < 2; ++s) {
        const int mt = wid*2 + s;
        const int row = h0 + (mt >> 2);
        const int px0 = (mt & 3)*16 + qrow;   // always < 56
        const int px1 = px0 + 8;
        float* po = out + (size_t)(b*H_ + row)*W_*CO;
        #pragma unroll
        for (int nt = 0; nt < NTn; ++nt) {
            int co0 = colbase + nt*8 + kq;
            if (co0   < CO) po[px0*CO + co0]   = acc[s][nt][0];
            if (co0+1 < CO) po[px0*CO + co0+1] = acc[s][nt][1];
            if (px1 < 56) {
                if (co0   < CO) po[px1*CO + co0]   = acc[s][nt][2];
                if (co0+1 < CO) po[px1*CO + co0+1] = acc[s][nt][3];
            }
        }
    }
}

// ---------------------------------------------------------------------------
// Deformable depthwise sampling, stage 1 (emits fp32 + fp16).
// grid = (2 half-rows, H, B), 448 threads = 28 px x 16 channel-float4.
// Gather loop unrolled x4 for MLP (hide L2/DRAM latency).
// ---------------------------------------------------------------------------
template<int K, int DIL, int PAD>
__global__ void __launch_bounds__(448) deform_sample_kernel(
    const float* __restrict__ img, const float* __restrict__ off,
    const float* __restrict__ dwT, float* __restrict__ outp,
    __half* __restrict__ oh)
{
    constexpr int KK = K*K;
    constexpr int NTASK = 28*KK;
    __shared__ __align__(16) float4 s_dw4[KK*16];
    __shared__ __align__(16) short4 s_idx[NTASK];
    __shared__ __align__(16) float4 s_wt [NTASK];

    const int t = threadIdx.x;
    const int half = blockIdx.x, h = blockIdx.y, b = blockIdx.z;
    const int w0 = half * 28;

    const float4* dwT4 = (const float4*)dwT;
    for (int i = t; i < KK*16; i += 448) s_dw4[i] = dwT4[i];

    const float2* ob2 = (const float2*)(off + ((size_t)(b*H_ + h)*W_ + w0)*2*KK);
    for (int i = t; i < NTASK; i += 448) {
        int wl = i / KK, kk = i - wl*KK;
        int ky = kk / K, kx = kk - ky*K;
        float2 d = ob2[i];
        float py = (float)(h + ky*DIL - PAD) + d.x;
        float px = (float)(w0 + wl + kx*DIL - PAD) + d.y;
        float y0f = floorf(py), x0f = floorf(px);
        float wy = py - y0f,    wx = px - x0f;
        int y0 = (int)y0f, x0i = (int)x0f;
        int y1 = y0 + 1,   x1  = x0i + 1;
        float vy0 = (y0  >= 0 && y0  < H_) ? 1.f : 0.f;
        float vy1 = (y1  >= 0 && y1  < H_) ? 1.f : 0.f;
        float vx0 = (x0i >= 0 && x0i < W_) ? 1.f : 0.f;
        float vx1 = (x1  >= 0 && x1  < W_) ? 1.f : 0.f;
        int y0c = min(max(y0, 0), H_-1), y1c = min(max(y1, 0), H_-1);
        int x0c = min(max(x0i,0), W_-1), x1c = min(max(x1, 0), W_-1);
        int r0 = y0c*W_, r1 = y1c*W_;
        s_idx[i] = make_short4((short)(r0+x0c), (short)(r0+x1c),
                               (short)(r1+x0c), (short)(r1+x1c));
        s_wt[i]  = make_float4((1.f-wy)*(1.f-wx)*vy0*vx0,
                               (1.f-wy)*wx      *vy0*vx1,
                               wy      *(1.f-wx)*vy1*vx0,
                               wy      *wx      *vy1*vx1);
    }
    __syncthreads();

    const int c4 = t & 15;
    const int wl = t >> 4;
    const int w  = w0 + wl;
    const float4* imgb = (const float4*)img + (size_t)b*HW_*16;

    float4 a = make_float4(0.f, 0.f, 0.f, 0.f);
    #pragma unroll 4
    for (int kk = 0; kk < KK; ++kk) {
        short4 id = s_idx[wl*KK + kk];
        float4 wt = s_wt [wl*KK + kk];
        float4 g00 = imgb[(int)id.x*16 + c4];
        float4 g01 = imgb[(int)id.y*16 + c4];
        float4 g10 = imgb[(int)id.z*16 + c4];
        float4 g11 = imgb[(int)id.w*16 + c4];
        float4 dv  = s_dw4[kk*16 + c4];
        float sx_ = g00.x*wt.x + g01.x*wt.y + g10.x*wt.z + g11.x*wt.w;
        float sy_ = g00.y*wt.x + g01.y*wt.y + g10.y*wt.z + g11.y*wt.w;
        float sz_ = g00.z*wt.x + g01.z*wt.y + g10.z*wt.z + g11.z*wt.w;
        float sw_ = g00.w*wt.x + g01.w*wt.y + g10.w*wt.z + g11.w*wt.w;
        a.x += sx_*dv.x; a.y += sy_*dv.y; a.z += sz_*dv.z; a.w += sw_*dv.w;
    }
    const size_t p = (size_t)(b*H_ + h)*W_ + w;
    ((float4*)outp)[p*16 + c4] = a;
    __half2 hp0; hp0.x = __float2half_rn(a.x); hp0.y = __float2half_rn(a.y);
    __half2 hp1; hp1.x = __float2half_rn(a.z); hp1.y = __float2half_rn(a.w);
    __half2* ph = (__half2*)(oh + p*64 + c4*4);
    ph[0] = hp0; ph[1] = hp1;
}

// ---------------------------------------------------------------------------
// Stage-2 deform + fused 1x1 pointwise conv + x-multiply (NCHW output).
// grid = (2 half-rows, H, B), 448 threads. Dynamic smem. Gather unrolled x4.
// ---------------------------------------------------------------------------
template<int K, int DIL, int PAD>
__global__ void __launch_bounds__(448) deform_pw_kernel(
    const float* __restrict__ img,   // attn1 NHWC
    const float* __restrict__ off,   // off2 NHWC
    const float* __restrict__ dwT,   // [kk][c]
    const float* __restrict__ pw,    // [64,64] (co,ci)
    const float* __restrict__ pb,    // [64]
    const float* __restrict__ x,     // original x, NCHW
    float* __restrict__ out)         // NCHW
{
    constexpr int KK = K*K;
    constexpr int NTASK = 28*KK;
    extern __shared__ __align__(16) char sraw[];
    float4* s_dw4 = (float4*)sraw;                               // KK*16*16 B
    char*   reg   = sraw + KK*16*16;
    short4* s_idx = (short4*)reg;                                // NTASK*8
    float4* s_wt  = (float4*)(reg + NTASK*8);                    // NTASK*16
    float*  s_attn= (float*) (reg + NTASK*24);                   // 28*64*4
    // overlay (valid after gather):
    float*  s_pwT = (float*)reg;                                 // 16384
    float*  s_pb  = (float*)(reg + 16384);                       // 256
    float*  s_out = (float*)(reg + 16640);                       // 28*64*4

    const int t = threadIdx.x;
    const int half = blockIdx.x, h = blockIdx.y, b = blockIdx.z;
    const int w0 = half * 28;

    const float4* dwT4 = (const float4*)dwT;
    for (int i = t; i < KK*16; i += 448) s_dw4[i] = dwT4[i];

    const float2* ob2 = (const float2*)(off + ((size_t)(b*H_ + h)*W_ + w0)*2*KK);
    for (int i = t; i < NTASK; i += 448) {
        int wl = i / KK, kk = i - wl*KK;
        int ky = kk / K, kx = kk - ky*K;
        float2 d = ob2[i];
        float py = (float)(h + ky*DIL - PAD) + d.x;
        float px = (float)(w0 + wl + kx*DIL - PAD) + d.y;
        float y0f = floorf(py), x0f = floorf(px);
        float wy = py - y0f,    wx = px - x0f;
        int y0 = (int)y0f, x0i = (int)x0f;
        int y1 = y0 + 1,   x1  = x0i + 1;
        float vy0 = (y0  >= 0 && y0  < H_) ? 1.f : 0.f;
        float vy1 = (y1  >= 0 && y1  < H_) ? 1.f : 0.f;
        float vx0 = (x0i >= 0 && x0i < W_) ? 1.f : 0.f;
        float vx1 = (x1  >= 0 && x1  < W_) ? 1.f : 0.f;
        int y0c = min(max(y0, 0), H_-1), y1c = min(max(y1, 0), H_-1);
        int x0c = min(max(x0i,0), W_-1), x1c = min(max(x1, 0), W_-1);
        int r0 = y0c*W_, r1 = y1c*W_;
        s_idx[i] = make_short4((short)(r0+x0c), (short)(r0+x1c),
                               (short)(r1+x0c), (short)(r1+x1c));
        s_wt[i]  = make_float4((1.f-wy)*(1.f-wx)*vy0*vx0,
                               (1.f-wy)*wx      *vy0*vx1,
                               wy      *(1.f-wx)*vy1*vx0,
                               wy      *wx      *vy1*vx1);
    }
    __syncthreads();

    const int c4 = t & 15;
    const int wl = t >> 4;
    const float4* imgb = (const float4*)img + (size_t)b*HW_*16;

    float4 a = make_float4(0.f, 0.f, 0.f, 0.f);
    #pragma unroll 4
    for (int kk = 0; kk < KK; ++kk) {
        short4 id = s_idx[wl*KK + kk];
        float4 wt = s_wt [wl*KK + kk];
        float4 g00 = imgb[(int)id.x*16 + c4];
        float4 g01 = imgb[(int)id.y*16 + c4];
        float4 g10 = imgb[(int)id.z*16 + c4];
        float4 g11 = imgb[(int)id.w*16 + c4];
        float4 dv  = s_dw4[kk*16 + c4];
        float sx_ = g00.x*wt.x + g01.x*wt.y + g10.x*wt.z + g11.x*wt.w;
        float sy_ = g00.y*wt.x + g01.y*wt.y + g10.y*wt.z + g11.y*wt.w;
        float sz_ = g00.z*wt.x + g01.z*wt.y + g10.z*wt.z + g11.z*wt.w;
        float sw_ = g00.w*wt.x + g01.w*wt.y + g10.w*wt.z + g11.w*wt.w;
        a.x += sx_*dv.x; a.y += sy_*dv.y; a.z += sz_*dv.z; a.w += sw_*dv.w;
    }
    ((float4*)s_attn)[wl*16 + c4] = a;
    __syncthreads();                         // gather done; idx/wt now dead

    for (int i = t; i < 4096; i += 448) {
        int co = i >> 6, ci = i & 63;
        s_pwT[ci*64 + co] = pw[i];
    }
    if (t < 64) s_pb[t] = pb[t];
    __syncthreads();

    const int co0 = c4*4;
    float4 accp = make_float4(0.f, 0.f, 0.f, 0.f);
    const float* ar = s_attn + wl*64;
    #pragma unroll 8
    for (int ci = 0; ci < 64; ++ci) {
        float av = ar[ci];
        float4 wv = ((const float4*)(s_pwT + ci*64))[c4];
        accp.x += av*wv.x; accp.y += av*wv.y;
        accp.z += av*wv.z; accp.w += av*wv.w;
    }
    s_out[(co0  )*28 + wl] = accp.x + s_pb[co0];
    s_out[(co0+1)*28 + wl] = accp.y + s_pb[co0+1];
    s_out[(co0+2)*28 + wl] = accp.z + s_pb[co0+2];
    s_out[(co0+3)*28 + wl] = accp.w + s_pb[co0+3];
    __syncthreads();

    for (int i = t; i < 64*28; i += 448) {
        int c = i / 28, wl2 = i - c*28;
        size_t idx = ((size_t)(b*64 + c)*H_ + h)*W_ + w0 + wl2;
        out[idx] = x[idx] * s_out[c*28 + wl2];
    }
}

// ---------------------------------------------------------------------------
extern "C" void kernel_launch(void* const* d_in, const int* in_sizes, int n_in,
                              void* d_out, int out_size)
{
    const float* x   = (const float*)d_in[0];
    const float* ow1 = (const float*)d_in[1];
    const float* ob1 = (const float*)d_in[2];
    const float* dw1 = (const float*)d_in[3];
    const float* ow2 = (const float*)d_in[4];
    const float* ob2 = (const float*)d_in[5];
    const float* dw2 = (const float*)d_in[6];
    const float* pww = (const float*)d_in[7];
    const float* pwb = (const float*)d_in[8];
    float* out = (float*)d_out;

    float *xT, *off1, *attn1, *off2, *dw1T, *dw2T;
    __half *xh, *a1h, *w1h, *w2h;
    cudaGetSymbolAddress((void**)&xT,    g_xT);
    cudaGetSymbolAddress((void**)&xh,    g_xh);
    cudaGetSymbolAddress((void**)&off1,  g_off1);
    cudaGetSymbolAddress((void**)&attn1, g_attn1);
    cudaGetSymbolAddress((void**)&a1h,   g_a1h);
    cudaGetSymbolAddress((void**)&off2,  g_off2);
    cudaGetSymbolAddress((void**)&w1h,   g_w1h);
    cudaGetSymbolAddress((void**)&w2h,   g_w2h);
    cudaGetSymbolAddress((void**)&dw1T,  g_dw1T);
    cudaGetSymbolAddress((void**)&dw2T,  g_dw2T);

    // conv smem: 4 A planes + 2 B buffers (bytes)
    const int SMEM1 = 4*(68*72)*2 + 2*(32*72)*2;    // 48384
    const int SMEM2 = 4*(82*72)*2 + 2*(56*72)*2;    // 63360
    const int SMEMD = 49*16*16 + 28*49*24 + 28*64*4; // 52640
    cudaFuncSetAttribute(conv_mma_kernel<5,1,2,50,64>,
        cudaFuncAttributeMaxDynamicSharedMemorySize, SMEM1);
    cudaFuncSetAttribute(conv_mma_kernel<7,3,9,98,112>,
        cudaFuncAttributeMaxDynamicSharedMemorySize, SMEM2);
    cudaFuncSetAttribute(deform_pw_kernel<7,3,9>,
        cudaFuncAttributeMaxDynamicSharedMemorySize, SMEMD);

    // fused prelude: 224 transpose blocks + weight-prep blocks
    prelude_kernel<<<224 + PREP_BLOCKS, 256>>>(
        x, xT, xh, ow1, ow2, dw1, dw2, w1h, w2h, dw1T, dw2T);

    // stage 1: K=5, dil=1, pad=2, CO=50 (pad 64)
    conv_mma_kernel<5,1,2,50,64><<<dim3(14, B_, 2), 256, SMEM1>>>(
        xh, w1h, ob1, off1);
    deform_sample_kernel<5,1,2><<<dim3(2, H_, B_), 448>>>(
        xT, off1, dw1T, attn1, a1h);

    // stage 2: K=7, dil=3, pad=9, CO=98 (pad 112)
    conv_mma_kernel<7,3,9,98,112><<<dim3(14, B_, 2), 256, SMEM2>>>(
        a1h, w2h, ob2, off2);

    // deform2 + pointwise + x-multiply, fused
    deform_pw_kernel<7,3,9><<<dim3(2, H_, B_), 448, SMEMD>>>(
        attn1, off2, dw2T, pww, pwb, x, out);
}